// round 2
// baseline (speedup 1.0000x reference)
#include <cuda_runtime.h>
#include <math.h>

// ----------------------------------------------------------------------------
// Shapes (fixed for this problem)
// ----------------------------------------------------------------------------
#define B_   4
#define L_   1024
#define D_   1024
#define H_   16
#define HD_  64
#define FF_  4096
#define NS_  64
#define M_   (B_ * L_)          // 4096 rows

// Scratch layout (floats)
#define OFF_LN    0ull                               // 4096*1024
#define OFF_QKV   (OFF_LN   + 4194304ull)            // 4096*3072
#define OFF_ATTN  (OFF_QKV  + 12582912ull)           // 4096*1024
#define OFF_X1    (OFF_ATTN + 4194304ull)            // 4096*1024
#define OFF_X2    (OFF_X1   + 4194304ull)            // 4096*1024
#define OFF_KVN   (OFF_X2   + 4194304ull)            // 256*1024
#define OFF_CKV   (OFF_KVN  + 262144ull)             // 256*2048
#define OFF_F     (OFF_CKV  + 524288ull)             // 4096*8192
#define OFF_GG    (OFF_F    + 33554432ull)           // 4096*4096
#define SCRATCH_FLOATS (OFF_GG + 16777216ull)        // 80,478,208 floats

__device__ float g_scratch[SCRATCH_FLOATS];

// ----------------------------------------------------------------------------
// LayerNorm: one block per row, 256 threads, D=1024 (one float4 per thread)
// ----------------------------------------------------------------------------
__global__ __launch_bounds__(256)
void ln_kernel(const float* __restrict__ x, const float* __restrict__ g,
               const float* __restrict__ b, float* __restrict__ y) {
    const int row = blockIdx.x;
    const int t = threadIdx.x;
    const float4 v = ((const float4*)(x + (size_t)row * D_))[t];

    __shared__ float red[8];
    __shared__ float stat[2];

    float s = v.x + v.y + v.z + v.w;
    #pragma unroll
    for (int o = 16; o; o >>= 1) s += __shfl_xor_sync(0xffffffffu, s, o);
    if ((t & 31) == 0) red[t >> 5] = s;
    __syncthreads();
    if (t == 0) {
        float s2 = 0.f;
        #pragma unroll
        for (int i = 0; i < 8; i++) s2 += red[i];
        stat[0] = s2 * (1.0f / D_);
    }
    __syncthreads();
    const float mu = stat[0];
    const float dx = v.x - mu, dy = v.y - mu, dz = v.z - mu, dw = v.w - mu;

    float q = dx * dx + dy * dy + dz * dz + dw * dw;
    #pragma unroll
    for (int o = 16; o; o >>= 1) q += __shfl_xor_sync(0xffffffffu, q, o);
    if ((t & 31) == 0) red[t >> 5] = q;
    __syncthreads();
    if (t == 0) {
        float s2 = 0.f;
        #pragma unroll
        for (int i = 0; i < 8; i++) s2 += red[i];
        stat[1] = rsqrtf(s2 * (1.0f / D_) + 1e-5f);
    }
    __syncthreads();
    const float rs = stat[1];

    const float4 gv = ((const float4*)g)[t];
    const float4 bv = ((const float4*)b)[t];
    float4 out;
    out.x = dx * rs * gv.x + bv.x;
    out.y = dy * rs * gv.y + bv.y;
    out.z = dz * rs * gv.z + bv.z;
    out.w = dw * rs * gv.w + bv.w;
    ((float4*)(y + (size_t)row * D_))[t] = out;
}

// ----------------------------------------------------------------------------
// SGEMM: C[M,N] = A[M,K] @ W[N,K]^T + bias, with epilogue variants.
// 128x128 block tile, K-step 8, 256 threads, 8x8 microtile.
// EPI: 0 = bias only, 1 = bias + residual, 2 = sigmoid(gate)*(..)+residual
// M,N multiples of 128; K multiple of 8.
// ----------------------------------------------------------------------------
template <int EPI>
__global__ __launch_bounds__(256)
void gemm_kernel(const float* __restrict__ A, const float* __restrict__ W,
                 const float* __restrict__ bias, const float* __restrict__ res,
                 const float* __restrict__ gatep, float* __restrict__ C,
                 int M, int N, int K) {
    __shared__ float As[8][128];
    __shared__ float Bs[8][128];

    const int t = threadIdx.x;
    const int tx = t & 15;         // 0..15 -> n microtile
    const int ty = t >> 4;         // 0..15 -> m microtile
    const int mBase = blockIdx.y * 128;
    const int nBase = blockIdx.x * 128;

    const int lrow = t >> 1;       // 0..127
    const int lk = (t & 1) * 4;    // 0 or 4
    const float* Ap = A + (size_t)(mBase + lrow) * K + lk;
    const float* Wp = W + (size_t)(nBase + lrow) * K + lk;

    float acc[8][8];
    #pragma unroll
    for (int i = 0; i < 8; i++)
        #pragma unroll
        for (int j = 0; j < 8; j++) acc[i][j] = 0.f;

    for (int k0 = 0; k0 < K; k0 += 8) {
        const float4 a = *(const float4*)(Ap + k0);
        const float4 w = *(const float4*)(Wp + k0);
        As[lk + 0][lrow] = a.x; As[lk + 1][lrow] = a.y;
        As[lk + 2][lrow] = a.z; As[lk + 3][lrow] = a.w;
        Bs[lk + 0][lrow] = w.x; Bs[lk + 1][lrow] = w.y;
        Bs[lk + 2][lrow] = w.z; Bs[lk + 3][lrow] = w.w;
        __syncthreads();

        #pragma unroll
        for (int kk = 0; kk < 8; kk++) {
            const float4 a0 = *(const float4*)&As[kk][ty * 8];
            const float4 a1 = *(const float4*)&As[kk][ty * 8 + 4];
            const float4 b0 = *(const float4*)&Bs[kk][tx * 8];
            const float4 b1 = *(const float4*)&Bs[kk][tx * 8 + 4];
            const float ar[8] = {a0.x, a0.y, a0.z, a0.w, a1.x, a1.y, a1.z, a1.w};
            const float br[8] = {b0.x, b0.y, b0.z, b0.w, b1.x, b1.y, b1.z, b1.w};
            #pragma unroll
            for (int i = 0; i < 8; i++)
                #pragma unroll
                for (int j = 0; j < 8; j++) acc[i][j] += ar[i] * br[j];
        }
        __syncthreads();
    }

    float gs = 1.f;
    if (EPI == 2) gs = 1.f / (1.f + __expf(-gatep[0]));

    #pragma unroll
    for (int i = 0; i < 8; i++) {
        const int m = mBase + ty * 8 + i;
        float* Crow = C + (size_t)m * N + nBase;
        const float* Rrow = (EPI >= 1) ? (res + (size_t)m * N + nBase) : nullptr;
        #pragma unroll
        for (int j = 0; j < 8; j++) {
            const int n = tx * 8 + j;
            float c = acc[i][j] + bias[nBase + n];
            if (EPI == 1) c += Rrow[n];
            if (EPI == 2) c = gs * c + Rrow[n];
            Crow[n] = c;
        }
    }
}

// ----------------------------------------------------------------------------
// Flash attention, fp32, HD=64, 64q x 64k tiles, 256 threads.
// Q rows at Qb + (b*Lq + q)*ldq + h*64 ; K/V similar with Lkv rows.
// bias (may be null): bias[(bh*Lq + q)*Lkv + k], added AFTER the 1/8 scale.
// Output Ob + (b*Lq + q)*ldo + h*64.
// grid: (Lq/64, B*H)
// ----------------------------------------------------------------------------
__global__ __launch_bounds__(256)
void flash_kernel(const float* __restrict__ Qb, int ldq,
                  const float* __restrict__ Kb, int ldk,
                  const float* __restrict__ Vb, int ldv,
                  const float* __restrict__ bias,
                  float* __restrict__ Ob, int ldo,
                  int Lq, int Lkv) {
    __shared__ float Qt[64][64];   // transposed: Qt[d][q]
    __shared__ float KP[64][64];   // K phase: KP[d][k] ; P phase: KP[k][q]
    __shared__ float Vs[64][64];   // natural:  Vs[k][d]

    const int bh = blockIdx.y;
    const int b = bh >> 4;          // H=16
    const int h = bh & 15;
    const int q0 = blockIdx.x * 64;
    const int t = threadIdx.x;
    const int tx = t & 15;          // column group
    const int ty = t >> 4;          // row group

    const int lrow = t >> 2;        // 0..63
    const int lc0 = (t & 3) * 16;   // 0,16,32,48

    // Load Q tile transposed
    {
        const float* qrow = Qb + (size_t)(b * Lq + q0 + lrow) * ldq + h * HD_ + lc0;
        #pragma unroll
        for (int c = 0; c < 16; c += 4) {
            const float4 v = *(const float4*)(qrow + c);
            Qt[lc0 + c + 0][lrow] = v.x; Qt[lc0 + c + 1][lrow] = v.y;
            Qt[lc0 + c + 2][lrow] = v.z; Qt[lc0 + c + 3][lrow] = v.w;
        }
    }

    float o[4][4];
    float m[4], l[4];
    #pragma unroll
    for (int i = 0; i < 4; i++) {
        m[i] = -1e30f; l[i] = 0.f;
        #pragma unroll
        for (int j = 0; j < 4; j++) o[i][j] = 0.f;
    }
    const float invs = 0.125f;  // 1/sqrt(64)

    for (int k0 = 0; k0 < Lkv; k0 += 64) {
        __syncthreads();  // previous PV / Q store fence
        {
            const float* krow = Kb + (size_t)(b * Lkv + k0 + lrow) * ldk + h * HD_ + lc0;
            const float* vrow = Vb + (size_t)(b * Lkv + k0 + lrow) * ldv + h * HD_ + lc0;
            #pragma unroll
            for (int c = 0; c < 16; c += 4) {
                const float4 kv = *(const float4*)(krow + c);
                KP[lc0 + c + 0][lrow] = kv.x; KP[lc0 + c + 1][lrow] = kv.y;
                KP[lc0 + c + 2][lrow] = kv.z; KP[lc0 + c + 3][lrow] = kv.w;
                *(float4*)&Vs[lrow][lc0 + c] = *(const float4*)(vrow + c);
            }
        }
        __syncthreads();

        // S = Q K^T
        float s[4][4];
        #pragma unroll
        for (int i = 0; i < 4; i++)
            #pragma unroll
            for (int j = 0; j < 4; j++) s[i][j] = 0.f;
        #pragma unroll
        for (int kk = 0; kk < 64; kk++) {
            const float4 qa = *(const float4*)&Qt[kk][ty * 4];
            const float4 kb = *(const float4*)&KP[kk][tx * 4];
            const float qr[4] = {qa.x, qa.y, qa.z, qa.w};
            const float kr[4] = {kb.x, kb.y, kb.z, kb.w};
            #pragma unroll
            for (int i = 0; i < 4; i++)
                #pragma unroll
                for (int j = 0; j < 4; j++) s[i][j] += qr[i] * kr[j];
        }

        // scale + bias
        if (bias) {
            #pragma unroll
            for (int i = 0; i < 4; i++) {
                const float4 bb = *(const float4*)(bias +
                    ((size_t)bh * Lq + (q0 + ty * 4 + i)) * Lkv + k0 + tx * 4);
                s[i][0] = s[i][0] * invs + bb.x;
                s[i][1] = s[i][1] * invs + bb.y;
                s[i][2] = s[i][2] * invs + bb.z;
                s[i][3] = s[i][3] * invs + bb.w;
            }
        } else {
            #pragma unroll
            for (int i = 0; i < 4; i++)
                #pragma unroll
                for (int j = 0; j < 4; j++) s[i][j] *= invs;
        }

        __syncthreads();  // done reading KP as K; about to overwrite with P

        // online softmax (per 4 rows; reduce across the 16 tx lanes)
        #pragma unroll
        for (int i = 0; i < 4; i++) {
            float rm = fmaxf(fmaxf(s[i][0], s[i][1]), fmaxf(s[i][2], s[i][3]));
            #pragma unroll
            for (int off = 8; off; off >>= 1)
                rm = fmaxf(rm, __shfl_xor_sync(0xffffffffu, rm, off));
            const float mn = fmaxf(m[i], rm);
            const float sc = __expf(m[i] - mn);
            s[i][0] = __expf(s[i][0] - mn);
            s[i][1] = __expf(s[i][1] - mn);
            s[i][2] = __expf(s[i][2] - mn);
            s[i][3] = __expf(s[i][3] - mn);
            float rs = s[i][0] + s[i][1] + s[i][2] + s[i][3];
            #pragma unroll
            for (int off = 8; off; off >>= 1)
                rs += __shfl_xor_sync(0xffffffffu, rs, off);
            l[i] = l[i] * sc + rs;
            m[i] = mn;
            #pragma unroll
            for (int j = 0; j < 4; j++) o[i][j] *= sc;
        }

        // store P transposed: KP[k][q]
        #pragma unroll
        for (int j = 0; j < 4; j++) {
            const float4 pv = make_float4(s[0][j], s[1][j], s[2][j], s[3][j]);
            *(float4*)&KP[tx * 4 + j][ty * 4] = pv;
        }
        __syncthreads();

        // O += P V
        #pragma unroll
        for (int kk = 0; kk < 64; kk++) {
            const float4 pa = *(const float4*)&KP[kk][ty * 4];
            const float4 vb = *(const float4*)&Vs[kk][tx * 4];
            const float pr[4] = {pa.x, pa.y, pa.z, pa.w};
            const float vr[4] = {vb.x, vb.y, vb.z, vb.w};
            #pragma unroll
            for (int i = 0; i < 4; i++)
                #pragma unroll
                for (int j = 0; j < 4; j++) o[i][j] += pr[i] * vr[j];
        }
    }

    // normalize + store
    #pragma unroll
    for (int i = 0; i < 4; i++) {
        const float inv = 1.f / l[i];
        const float4 ov = make_float4(o[i][0] * inv, o[i][1] * inv,
                                      o[i][2] * inv, o[i][3] * inv);
        *(float4*)(Ob + (size_t)(b * Lq + q0 + ty * 4 + i) * ldo + h * HD_ + tx * 4) = ov;
    }
}

// ----------------------------------------------------------------------------
// GEGLU: gg[m][j] = f[m][j] * gelu_exact(f[m][FF+j]),  m<4096, j<4096
// Vectorized float4: one thread handles one float4 of the FF columns.
// ----------------------------------------------------------------------------
__device__ __forceinline__ float gelu_exact(float x) {
    return 0.5f * x * (1.0f + erff(x * 0.7071067811865476f));
}

__global__ __launch_bounds__(256)
void geglu_kernel(const float* __restrict__ f, float* __restrict__ gg) {
    const int idx4 = blockIdx.x * blockDim.x + threadIdx.x;  // 0 .. 4096*1024-1
    const int mrow = idx4 >> 10;
    const int j4 = (idx4 & 1023) * 4;
    const float4 val = *(const float4*)(f + (size_t)mrow * (2 * FF_) + j4);
    const float4 gt  = *(const float4*)(f + (size_t)mrow * (2 * FF_) + FF_ + j4);
    float4 out;
    out.x = val.x * gelu_exact(gt.x);
    out.y = val.y * gelu_exact(gt.y);
    out.z = val.z * gelu_exact(gt.z);
    out.w = val.w * gelu_exact(gt.w);
    *(float4*)(gg + (size_t)mrow * FF_ + j4) = out;
}

// ----------------------------------------------------------------------------
// Host orchestration
// ----------------------------------------------------------------------------
extern "C" void kernel_launch(void* const* d_in, const int* in_sizes, int n_in,
                              void* d_out, int out_size) {
    const float* x          = (const float*)d_in[0];
    const float* alibi      = (const float*)d_in[1];
    const float* species    = (const float*)d_in[2];
    const float* norm1_g    = (const float*)d_in[3];
    const float* norm1_b    = (const float*)d_in[4];
    const float* sa_wqkv    = (const float*)d_in[5];
    const float* sa_bqkv    = (const float*)d_in[6];
    const float* sa_wo      = (const float*)d_in[7];
    const float* sa_bo      = (const float*)d_in[8];
    const float* ca_nq_g    = (const float*)d_in[9];
    const float* ca_nq_b    = (const float*)d_in[10];
    const float* ca_nkv_g   = (const float*)d_in[11];
    const float* ca_nkv_b   = (const float*)d_in[12];
    const float* ca_wqkv    = (const float*)d_in[13];
    const float* ca_bqkv    = (const float*)d_in[14];
    const float* ca_wo      = (const float*)d_in[15];
    const float* ca_bo      = (const float*)d_in[16];
    const float* gate_param = (const float*)d_in[17];
    const float* ffn_g      = (const float*)d_in[18];
    const float* ffn_b      = (const float*)d_in[19];
    const float* ffn_w1     = (const float*)d_in[20];
    const float* ffn_b1     = (const float*)d_in[21];
    const float* ffn_w2     = (const float*)d_in[22];
    const float* ffn_b2     = (const float*)d_in[23];
    float* out = (float*)d_out;

    float* S = nullptr;
    cudaGetSymbolAddress((void**)&S, g_scratch);
    float* ln   = S + OFF_LN;
    float* qkv  = S + OFF_QKV;
    float* attn = S + OFF_ATTN;
    float* x1   = S + OFF_X1;
    float* x2   = S + OFF_X2;
    float* kvn  = S + OFF_KVN;
    float* ckv  = S + OFF_CKV;
    float* f    = S + OFF_F;
    float* gg   = S + OFF_GG;

    // ---- Self-attention ----
    ln_kernel<<<M_, 256>>>(x, norm1_g, norm1_b, ln);
    gemm_kernel<0><<<dim3(3 * D_ / 128, M_ / 128), 256>>>(
        ln, sa_wqkv, sa_bqkv, nullptr, nullptr, qkv, M_, 3 * D_, D_);
    flash_kernel<<<dim3(L_ / 64, B_ * H_), 256>>>(
        qkv, 3 * D_, qkv + D_, 3 * D_, qkv + 2 * D_, 3 * D_,
        alibi, attn, D_, L_, L_);
    gemm_kernel<1><<<dim3(D_ / 128, M_ / 128), 256>>>(
        attn, sa_wo, sa_bo, x, nullptr, x1, M_, D_, D_);

    // ---- Cross-attention ----
    ln_kernel<<<M_, 256>>>(x1, ca_nq_g, ca_nq_b, ln);
    ln_kernel<<<B_ * NS_, 256>>>(species, ca_nkv_g, ca_nkv_b, kvn);
    gemm_kernel<0><<<dim3(D_ / 128, M_ / 128), 256>>>(
        ln, ca_wqkv, ca_bqkv, nullptr, nullptr, attn /* cq */, M_, D_, D_);
    gemm_kernel<0><<<dim3(2 * D_ / 128, (B_ * NS_) / 128), 256>>>(
        kvn, ca_wqkv + (size_t)D_ * D_, ca_bqkv + D_, nullptr, nullptr,
        ckv, B_ * NS_, 2 * D_, D_);
    flash_kernel<<<dim3(L_ / 64, B_ * H_), 256>>>(
        attn, D_, ckv, 2 * D_, ckv + D_, 2 * D_,
        nullptr, ln /* cross out */, D_, L_, NS_);
    gemm_kernel<2><<<dim3(D_ / 128, M_ / 128), 256>>>(
        ln, ca_wo, ca_bo, x1, gate_param, x2, M_, D_, D_);

    // ---- FFN (GEGLU) ----
    ln_kernel<<<M_, 256>>>(x2, ffn_g, ffn_b, attn);
    gemm_kernel<0><<<dim3(2 * FF_ / 128, M_ / 128), 256>>>(
        attn, ffn_w1, ffn_b1, nullptr, nullptr, f, M_, 2 * FF_, D_);
    geglu_kernel<<<(M_ * FF_ / 4) / 256, 256>>>(f, gg);
    gemm_kernel<1><<<dim3(D_ / 128, M_ / 128), 256>>>(
        gg, ffn_w2, ffn_b2, x2, nullptr, out, M_, D_, FF_);
}

// round 3
// speedup vs baseline: 1.0013x; 1.0013x over previous
#include <cuda_runtime.h>
#include <math.h>

// ----------------------------------------------------------------------------
// Shapes (fixed for this problem)
// ----------------------------------------------------------------------------
#define B_   4
#define L_   1024
#define D_   1024
#define H_   16
#define HD_  64
#define FF_  4096
#define NS_  64
#define M_   (B_ * L_)          // 4096 rows

// Scratch layout (floats)
#define OFF_LN    0ull                               // 4096*1024
#define OFF_QKV   (OFF_LN   + 4194304ull)            // 4096*3072
#define OFF_ATTN  (OFF_QKV  + 12582912ull)           // 4096*1024
#define OFF_X1    (OFF_ATTN + 4194304ull)            // 4096*1024
#define OFF_X2    (OFF_X1   + 4194304ull)            // 4096*1024
#define OFF_KVN   (OFF_X2   + 4194304ull)            // 256*1024
#define OFF_CKV   (OFF_KVN  + 262144ull)             // 256*2048
#define OFF_F     (OFF_CKV  + 524288ull)             // 4096*8192
#define OFF_GG    (OFF_F    + 33554432ull)           // 4096*4096
#define SCRATCH_FLOATS (OFF_GG + 16777216ull)        // 80,478,208 floats

__device__ float g_scratch[SCRATCH_FLOATS];

// ----------------------------------------------------------------------------
// LayerNorm: one block per row, 256 threads, D=1024 (one float4 per thread)
// ----------------------------------------------------------------------------
__global__ __launch_bounds__(256)
void ln_kernel(const float* __restrict__ x, const float* __restrict__ g,
               const float* __restrict__ b, float* __restrict__ y) {
    const int row = blockIdx.x;
    const int t = threadIdx.x;
    const float4 v = ((const float4*)(x + (size_t)row * D_))[t];

    __shared__ float red[8];
    __shared__ float stat[2];

    float s = v.x + v.y + v.z + v.w;
    #pragma unroll
    for (int o = 16; o; o >>= 1) s += __shfl_xor_sync(0xffffffffu, s, o);
    if ((t & 31) == 0) red[t >> 5] = s;
    __syncthreads();
    if (t == 0) {
        float s2 = 0.f;
        #pragma unroll
        for (int i = 0; i < 8; i++) s2 += red[i];
        stat[0] = s2 * (1.0f / D_);
    }
    __syncthreads();
    const float mu = stat[0];
    const float dx = v.x - mu, dy = v.y - mu, dz = v.z - mu, dw = v.w - mu;

    float q = dx * dx + dy * dy + dz * dz + dw * dw;
    #pragma unroll
    for (int o = 16; o; o >>= 1) q += __shfl_xor_sync(0xffffffffu, q, o);
    if ((t & 31) == 0) red[t >> 5] = q;
    __syncthreads();
    if (t == 0) {
        float s2 = 0.f;
        #pragma unroll
        for (int i = 0; i < 8; i++) s2 += red[i];
        stat[1] = rsqrtf(s2 * (1.0f / D_) + 1e-5f);
    }
    __syncthreads();
    const float rs = stat[1];

    const float4 gv = ((const float4*)g)[t];
    const float4 bv = ((const float4*)b)[t];
    float4 out;
    out.x = dx * rs * gv.x + bv.x;
    out.y = dy * rs * gv.y + bv.y;
    out.z = dz * rs * gv.z + bv.z;
    out.w = dw * rs * gv.w + bv.w;
    ((float4*)(y + (size_t)row * D_))[t] = out;
}

// ----------------------------------------------------------------------------
// SGEMM: C[M,N] = A[M,K] @ W[N,K]^T + bias, with epilogue variants.
// 128x128 block tile, K-step 8, 256 threads, 8x8 microtile.
// EPI: 0 = bias only, 1 = bias + residual, 2 = sigmoid(gate)*(..)+residual
// M,N multiples of 128; K multiple of 8.
// ----------------------------------------------------------------------------
template <int EPI>
__global__ __launch_bounds__(256)
void gemm_kernel(const float* __restrict__ A, const float* __restrict__ W,
                 const float* __restrict__ bias, const float* __restrict__ res,
                 const float* __restrict__ gatep, float* __restrict__ C,
                 int M, int N, int K) {
    __shared__ float As[8][128];
    __shared__ float Bs[8][128];

    const int t = threadIdx.x;
    const int tx = t & 15;         // 0..15 -> n microtile
    const int ty = t >> 4;         // 0..15 -> m microtile
    const int mBase = blockIdx.y * 128;
    const int nBase = blockIdx.x * 128;

    const int lrow = t >> 1;       // 0..127
    const int lk = (t & 1) * 4;    // 0 or 4
    const float* Ap = A + (size_t)(mBase + lrow) * K + lk;
    const float* Wp = W + (size_t)(nBase + lrow) * K + lk;

    float acc[8][8];
    #pragma unroll
    for (int i = 0; i < 8; i++)
        #pragma unroll
        for (int j = 0; j < 8; j++) acc[i][j] = 0.f;

    for (int k0 = 0; k0 < K; k0 += 8) {
        const float4 a = *(const float4*)(Ap + k0);
        const float4 w = *(const float4*)(Wp + k0);
        As[lk + 0][lrow] = a.x; As[lk + 1][lrow] = a.y;
        As[lk + 2][lrow] = a.z; As[lk + 3][lrow] = a.w;
        Bs[lk + 0][lrow] = w.x; Bs[lk + 1][lrow] = w.y;
        Bs[lk + 2][lrow] = w.z; Bs[lk + 3][lrow] = w.w;
        __syncthreads();

        #pragma unroll
        for (int kk = 0; kk < 8; kk++) {
            const float4 a0 = *(const float4*)&As[kk][ty * 8];
            const float4 a1 = *(const float4*)&As[kk][ty * 8 + 4];
            const float4 b0 = *(const float4*)&Bs[kk][tx * 8];
            const float4 b1 = *(const float4*)&Bs[kk][tx * 8 + 4];
            const float ar[8] = {a0.x, a0.y, a0.z, a0.w, a1.x, a1.y, a1.z, a1.w};
            const float br[8] = {b0.x, b0.y, b0.z, b0.w, b1.x, b1.y, b1.z, b1.w};
            #pragma unroll
            for (int i = 0; i < 8; i++)
                #pragma unroll
                for (int j = 0; j < 8; j++) acc[i][j] += ar[i] * br[j];
        }
        __syncthreads();
    }

    float gs = 1.f;
    if (EPI == 2) gs = 1.f / (1.f + __expf(-gatep[0]));

    #pragma unroll
    for (int i = 0; i < 8; i++) {
        const int m = mBase + ty * 8 + i;
        float* Crow = C + (size_t)m * N + nBase;
        const float* Rrow = (EPI >= 1) ? (res + (size_t)m * N + nBase) : nullptr;
        #pragma unroll
        for (int j = 0; j < 8; j++) {
            const int n = tx * 8 + j;
            float c = acc[i][j] + bias[nBase + n];
            if (EPI == 1) c += Rrow[n];
            if (EPI == 2) c = gs * c + Rrow[n];
            Crow[n] = c;
        }
    }
}

// ----------------------------------------------------------------------------
// Flash attention, fp32, HD=64, 64q x 64k tiles, 256 threads.
// Q rows at Qb + (b*Lq + q)*ldq + h*64 ; K/V similar with Lkv rows.
// bias (may be null): bias[(bh*Lq + q)*Lkv + k], added AFTER the 1/8 scale.
// Output Ob + (b*Lq + q)*ldo + h*64.
// grid: (Lq/64, B*H)
// ----------------------------------------------------------------------------
__global__ __launch_bounds__(256)
void flash_kernel(const float* __restrict__ Qb, int ldq,
                  const float* __restrict__ Kb, int ldk,
                  const float* __restrict__ Vb, int ldv,
                  const float* __restrict__ bias,
                  float* __restrict__ Ob, int ldo,
                  int Lq, int Lkv) {
    __shared__ float Qt[64][64];   // transposed: Qt[d][q]
    __shared__ float KP[64][64];   // K phase: KP[d][k] ; P phase: KP[k][q]
    __shared__ float Vs[64][64];   // natural:  Vs[k][d]

    const int bh = blockIdx.y;
    const int b = bh >> 4;          // H=16
    const int h = bh & 15;
    const int q0 = blockIdx.x * 64;
    const int t = threadIdx.x;
    const int tx = t & 15;          // column group
    const int ty = t >> 4;          // row group

    const int lrow = t >> 2;        // 0..63
    const int lc0 = (t & 3) * 16;   // 0,16,32,48

    // Load Q tile transposed
    {
        const float* qrow = Qb + (size_t)(b * Lq + q0 + lrow) * ldq + h * HD_ + lc0;
        #pragma unroll
        for (int c = 0; c < 16; c += 4) {
            const float4 v = *(const float4*)(qrow + c);
            Qt[lc0 + c + 0][lrow] = v.x; Qt[lc0 + c + 1][lrow] = v.y;
            Qt[lc0 + c + 2][lrow] = v.z; Qt[lc0 + c + 3][lrow] = v.w;
        }
    }

    float o[4][4];
    float m[4], l[4];
    #pragma unroll
    for (int i = 0; i < 4; i++) {
        m[i] = -1e30f; l[i] = 0.f;
        #pragma unroll
        for (int j = 0; j < 4; j++) o[i][j] = 0.f;
    }
    const float invs = 0.125f;  // 1/sqrt(64)

    for (int k0 = 0; k0 < Lkv; k0 += 64) {
        __syncthreads();  // previous PV / Q store fence
        {
            const float* krow = Kb + (size_t)(b * Lkv + k0 + lrow) * ldk + h * HD_ + lc0;
            const float* vrow = Vb + (size_t)(b * Lkv + k0 + lrow) * ldv + h * HD_ + lc0;
            #pragma unroll
            for (int c = 0; c < 16; c += 4) {
                const float4 kv = *(const float4*)(krow + c);
                KP[lc0 + c + 0][lrow] = kv.x; KP[lc0 + c + 1][lrow] = kv.y;
                KP[lc0 + c + 2][lrow] = kv.z; KP[lc0 + c + 3][lrow] = kv.w;
                *(float4*)&Vs[lrow][lc0 + c] = *(const float4*)(vrow + c);
            }
        }
        __syncthreads();

        // S = Q K^T
        float s[4][4];
        #pragma unroll
        for (int i = 0; i < 4; i++)
            #pragma unroll
            for (int j = 0; j < 4; j++) s[i][j] = 0.f;
        #pragma unroll
        for (int kk = 0; kk < 64; kk++) {
            const float4 qa = *(const float4*)&Qt[kk][ty * 4];
            const float4 kb = *(const float4*)&KP[kk][tx * 4];
            const float qr[4] = {qa.x, qa.y, qa.z, qa.w};
            const float kr[4] = {kb.x, kb.y, kb.z, kb.w};
            #pragma unroll
            for (int i = 0; i < 4; i++)
                #pragma unroll
                for (int j = 0; j < 4; j++) s[i][j] += qr[i] * kr[j];
        }

        // scale + bias
        if (bias) {
            #pragma unroll
            for (int i = 0; i < 4; i++) {
                const float4 bb = *(const float4*)(bias +
                    ((size_t)bh * Lq + (q0 + ty * 4 + i)) * Lkv + k0 + tx * 4);
                s[i][0] = s[i][0] * invs + bb.x;
                s[i][1] = s[i][1] * invs + bb.y;
                s[i][2] = s[i][2] * invs + bb.z;
                s[i][3] = s[i][3] * invs + bb.w;
            }
        } else {
            #pragma unroll
            for (int i = 0; i < 4; i++)
                #pragma unroll
                for (int j = 0; j < 4; j++) s[i][j] *= invs;
        }

        __syncthreads();  // done reading KP as K; about to overwrite with P

        // online softmax (per 4 rows; reduce across the 16 tx lanes)
        #pragma unroll
        for (int i = 0; i < 4; i++) {
            float rm = fmaxf(fmaxf(s[i][0], s[i][1]), fmaxf(s[i][2], s[i][3]));
            #pragma unroll
            for (int off = 8; off; off >>= 1)
                rm = fmaxf(rm, __shfl_xor_sync(0xffffffffu, rm, off));
            const float mn = fmaxf(m[i], rm);
            const float sc = __expf(m[i] - mn);
            s[i][0] = __expf(s[i][0] - mn);
            s[i][1] = __expf(s[i][1] - mn);
            s[i][2] = __expf(s[i][2] - mn);
            s[i][3] = __expf(s[i][3] - mn);
            float rs = s[i][0] + s[i][1] + s[i][2] + s[i][3];
            #pragma unroll
            for (int off = 8; off; off >>= 1)
                rs += __shfl_xor_sync(0xffffffffu, rs, off);
            l[i] = l[i] * sc + rs;
            m[i] = mn;
            #pragma unroll
            for (int j = 0; j < 4; j++) o[i][j] *= sc;
        }

        // store P transposed: KP[k][q]
        #pragma unroll
        for (int j = 0; j < 4; j++) {
            const float4 pv = make_float4(s[0][j], s[1][j], s[2][j], s[3][j]);
            *(float4*)&KP[tx * 4 + j][ty * 4] = pv;
        }
        __syncthreads();

        // O += P V
        #pragma unroll
        for (int kk = 0; kk < 64; kk++) {
            const float4 pa = *(const float4*)&KP[kk][ty * 4];
            const float4 vb = *(const float4*)&Vs[kk][tx * 4];
            const float pr[4] = {pa.x, pa.y, pa.z, pa.w};
            const float vr[4] = {vb.x, vb.y, vb.z, vb.w};
            #pragma unroll
            for (int i = 0; i < 4; i++)
                #pragma unroll
                for (int j = 0; j < 4; j++) o[i][j] += pr[i] * vr[j];
        }
    }

    // normalize + store
    #pragma unroll
    for (int i = 0; i < 4; i++) {
        const float inv = 1.f / l[i];
        const float4 ov = make_float4(o[i][0] * inv, o[i][1] * inv,
                                      o[i][2] * inv, o[i][3] * inv);
        *(float4*)(Ob + (size_t)(b * Lq + q0 + ty * 4 + i) * ldo + h * HD_ + tx * 4) = ov;
    }
}

// ----------------------------------------------------------------------------
// GEGLU: gg[m][j] = f[m][j] * gelu_exact(f[m][FF+j]),  m<4096, j<4096
// Vectorized float4: one thread handles one float4 of the FF columns.
// ----------------------------------------------------------------------------
__device__ __forceinline__ float gelu_exact(float x) {
    return 0.5f * x * (1.0f + erff(x * 0.7071067811865476f));
}

__global__ __launch_bounds__(256)
void geglu_kernel(const float* __restrict__ f, float* __restrict__ gg) {
    const int idx4 = blockIdx.x * blockDim.x + threadIdx.x;  // 0 .. 4096*1024-1
    const int mrow = idx4 >> 10;
    const int j4 = (idx4 & 1023) * 4;
    const float4 val = *(const float4*)(f + (size_t)mrow * (2 * FF_) + j4);
    const float4 gt  = *(const float4*)(f + (size_t)mrow * (2 * FF_) + FF_ + j4);
    float4 out;
    out.x = val.x * gelu_exact(gt.x);
    out.y = val.y * gelu_exact(gt.y);
    out.z = val.z * gelu_exact(gt.z);
    out.w = val.w * gelu_exact(gt.w);
    *(float4*)(gg + (size_t)mrow * FF_ + j4) = out;
}

// ----------------------------------------------------------------------------
// Host orchestration
// ----------------------------------------------------------------------------
extern "C" void kernel_launch(void* const* d_in, const int* in_sizes, int n_in,
                              void* d_out, int out_size) {
    const float* x          = (const float*)d_in[0];
    const float* alibi      = (const float*)d_in[1];
    const float* species    = (const float*)d_in[2];
    const float* norm1_g    = (const float*)d_in[3];
    const float* norm1_b    = (const float*)d_in[4];
    const float* sa_wqkv    = (const float*)d_in[5];
    const float* sa_bqkv    = (const float*)d_in[6];
    const float* sa_wo      = (const float*)d_in[7];
    const float* sa_bo      = (const float*)d_in[8];
    const float* ca_nq_g    = (const float*)d_in[9];
    const float* ca_nq_b    = (const float*)d_in[10];
    const float* ca_nkv_g   = (const float*)d_in[11];
    const float* ca_nkv_b   = (const float*)d_in[12];
    const float* ca_wqkv    = (const float*)d_in[13];
    const float* ca_bqkv    = (const float*)d_in[14];
    const float* ca_wo      = (const float*)d_in[15];
    const float* ca_bo      = (const float*)d_in[16];
    const float* gate_param = (const float*)d_in[17];
    const float* ffn_g      = (const float*)d_in[18];
    const float* ffn_b      = (const float*)d_in[19];
    const float* ffn_w1     = (const float*)d_in[20];
    const float* ffn_b1     = (const float*)d_in[21];
    const float* ffn_w2     = (const float*)d_in[22];
    const float* ffn_b2     = (const float*)d_in[23];
    float* out = (float*)d_out;

    float* S = nullptr;
    cudaGetSymbolAddress((void**)&S, g_scratch);
    float* ln   = S + OFF_LN;
    float* qkv  = S + OFF_QKV;
    float* attn = S + OFF_ATTN;
    float* x1   = S + OFF_X1;
    float* x2   = S + OFF_X2;
    float* kvn  = S + OFF_KVN;
    float* ckv  = S + OFF_CKV;
    float* f    = S + OFF_F;
    float* gg   = S + OFF_GG;

    // ---- Self-attention ----
    ln_kernel<<<M_, 256>>>(x, norm1_g, norm1_b, ln);
    gemm_kernel<0><<<dim3(3 * D_ / 128, M_ / 128), 256>>>(
        ln, sa_wqkv, sa_bqkv, nullptr, nullptr, qkv, M_, 3 * D_, D_);
    flash_kernel<<<dim3(L_ / 64, B_ * H_), 256>>>(
        qkv, 3 * D_, qkv + D_, 3 * D_, qkv + 2 * D_, 3 * D_,
        alibi, attn, D_, L_, L_);
    gemm_kernel<1><<<dim3(D_ / 128, M_ / 128), 256>>>(
        attn, sa_wo, sa_bo, x, nullptr, x1, M_, D_, D_);

    // ---- Cross-attention ----
    ln_kernel<<<M_, 256>>>(x1, ca_nq_g, ca_nq_b, ln);
    ln_kernel<<<B_ * NS_, 256>>>(species, ca_nkv_g, ca_nkv_b, kvn);
    gemm_kernel<0><<<dim3(D_ / 128, M_ / 128), 256>>>(
        ln, ca_wqkv, ca_bqkv, nullptr, nullptr, attn /* cq */, M_, D_, D_);
    gemm_kernel<0><<<dim3(2 * D_ / 128, (B_ * NS_) / 128), 256>>>(
        kvn, ca_wqkv + (size_t)D_ * D_, ca_bqkv + D_, nullptr, nullptr,
        ckv, B_ * NS_, 2 * D_, D_);
    flash_kernel<<<dim3(L_ / 64, B_ * H_), 256>>>(
        attn, D_, ckv, 2 * D_, ckv + D_, 2 * D_,
        nullptr, ln /* cross out */, D_, L_, NS_);
    gemm_kernel<2><<<dim3(D_ / 128, M_ / 128), 256>>>(
        ln, ca_wo, ca_bo, x1, gate_param, x2, M_, D_, D_);

    // ---- FFN (GEGLU) ----
    ln_kernel<<<M_, 256>>>(x2, ffn_g, ffn_b, attn);
    gemm_kernel<0><<<dim3(2 * FF_ / 128, M_ / 128), 256>>>(
        attn, ffn_w1, ffn_b1, nullptr, nullptr, f, M_, 2 * FF_, D_);
    geglu_kernel<<<(M_ * FF_ / 4) / 256, 256>>>(f, gg);
    gemm_kernel<1><<<dim3(D_ / 128, M_ / 128), 256>>>(
        gg, ffn_w2, ffn_b2, x2, nullptr, out, M_, D_, FF_);
}

// round 4
// speedup vs baseline: 1.0015x; 1.0003x over previous
#include <cuda_runtime.h>
#include <math.h>

// ----------------------------------------------------------------------------
// Shapes (fixed for this problem)
// ----------------------------------------------------------------------------
#define B_   4
#define L_   1024
#define D_   1024
#define H_   16
#define HD_  64
#define FF_  4096
#define NS_  64
#define M_   (B_ * L_)          // 4096 rows

// Scratch layout (floats)
#define OFF_LN    0ull                               // 4096*1024
#define OFF_QKV   (OFF_LN   + 4194304ull)            // 4096*3072
#define OFF_ATTN  (OFF_QKV  + 12582912ull)           // 4096*1024
#define OFF_X1    (OFF_ATTN + 4194304ull)            // 4096*1024
#define OFF_X2    (OFF_X1   + 4194304ull)            // 4096*1024
#define OFF_KVN   (OFF_X2   + 4194304ull)            // 256*1024
#define OFF_CKV   (OFF_KVN  + 262144ull)             // 256*2048
#define OFF_F     (OFF_CKV  + 524288ull)             // 4096*8192
#define OFF_GG    (OFF_F    + 33554432ull)           // 4096*4096
#define SCRATCH_FLOATS (OFF_GG + 16777216ull)        // 80,478,208 floats

__device__ float g_scratch[SCRATCH_FLOATS];

// ----------------------------------------------------------------------------
// LayerNorm: one block per row, 256 threads, D=1024 (one float4 per thread)
// ----------------------------------------------------------------------------
__global__ __launch_bounds__(256)
void ln_kernel(const float* __restrict__ x, const float* __restrict__ g,
               const float* __restrict__ b, float* __restrict__ y) {
    const int row = blockIdx.x;
    const int t = threadIdx.x;
    const float4 v = ((const float4*)(x + (size_t)row * D_))[t];

    __shared__ float red[8];
    __shared__ float stat[2];

    float s = v.x + v.y + v.z + v.w;
    #pragma unroll
    for (int o = 16; o; o >>= 1) s += __shfl_xor_sync(0xffffffffu, s, o);
    if ((t & 31) == 0) red[t >> 5] = s;
    __syncthreads();
    if (t == 0) {
        float s2 = 0.f;
        #pragma unroll
        for (int i = 0; i < 8; i++) s2 += red[i];
        stat[0] = s2 * (1.0f / D_);
    }
    __syncthreads();
    const float mu = stat[0];
    const float dx = v.x - mu, dy = v.y - mu, dz = v.z - mu, dw = v.w - mu;

    float q = dx * dx + dy * dy + dz * dz + dw * dw;
    #pragma unroll
    for (int o = 16; o; o >>= 1) q += __shfl_xor_sync(0xffffffffu, q, o);
    if ((t & 31) == 0) red[t >> 5] = q;
    __syncthreads();
    if (t == 0) {
        float s2 = 0.f;
        #pragma unroll
        for (int i = 0; i < 8; i++) s2 += red[i];
        stat[1] = rsqrtf(s2 * (1.0f / D_) + 1e-5f);
    }
    __syncthreads();
    const float rs = stat[1];

    const float4 gv = ((const float4*)g)[t];
    const float4 bv = ((const float4*)b)[t];
    float4 out;
    out.x = dx * rs * gv.x + bv.x;
    out.y = dy * rs * gv.y + bv.y;
    out.z = dz * rs * gv.z + bv.z;
    out.w = dw * rs * gv.w + bv.w;
    ((float4*)(y + (size_t)row * D_))[t] = out;
}

// ----------------------------------------------------------------------------
// SGEMM: C[M,N] = A[M,K] @ W[N,K]^T + bias, with epilogue variants.
// 128x128 block tile, K-step 8, 256 threads, 8x8 microtile.
// EPI: 0 = bias only, 1 = bias + residual, 2 = sigmoid(gate)*(..)+residual
// M,N multiples of 128; K multiple of 8.
// ----------------------------------------------------------------------------
template <int EPI>
__global__ __launch_bounds__(256)
void gemm_kernel(const float* __restrict__ A, const float* __restrict__ W,
                 const float* __restrict__ bias, const float* __restrict__ res,
                 const float* __restrict__ gatep, float* __restrict__ C,
                 int M, int N, int K) {
    __shared__ float As[8][128];
    __shared__ float Bs[8][128];

    const int t = threadIdx.x;
    const int tx = t & 15;         // 0..15 -> n microtile
    const int ty = t >> 4;         // 0..15 -> m microtile
    const int mBase = blockIdx.y * 128;
    const int nBase = blockIdx.x * 128;

    const int lrow = t >> 1;       // 0..127
    const int lk = (t & 1) * 4;    // 0 or 4
    const float* Ap = A + (size_t)(mBase + lrow) * K + lk;
    const float* Wp = W + (size_t)(nBase + lrow) * K + lk;

    float acc[8][8];
    #pragma unroll
    for (int i = 0; i < 8; i++)
        #pragma unroll
        for (int j = 0; j < 8; j++) acc[i][j] = 0.f;

    for (int k0 = 0; k0 < K; k0 += 8) {
        const float4 a = *(const float4*)(Ap + k0);
        const float4 w = *(const float4*)(Wp + k0);
        As[lk + 0][lrow] = a.x; As[lk + 1][lrow] = a.y;
        As[lk + 2][lrow] = a.z; As[lk + 3][lrow] = a.w;
        Bs[lk + 0][lrow] = w.x; Bs[lk + 1][lrow] = w.y;
        Bs[lk + 2][lrow] = w.z; Bs[lk + 3][lrow] = w.w;
        __syncthreads();

        #pragma unroll
        for (int kk = 0; kk < 8; kk++) {
            const float4 a0 = *(const float4*)&As[kk][ty * 8];
            const float4 a1 = *(const float4*)&As[kk][ty * 8 + 4];
            const float4 b0 = *(const float4*)&Bs[kk][tx * 8];
            const float4 b1 = *(const float4*)&Bs[kk][tx * 8 + 4];
            const float ar[8] = {a0.x, a0.y, a0.z, a0.w, a1.x, a1.y, a1.z, a1.w};
            const float br[8] = {b0.x, b0.y, b0.z, b0.w, b1.x, b1.y, b1.z, b1.w};
            #pragma unroll
            for (int i = 0; i < 8; i++)
                #pragma unroll
                for (int j = 0; j < 8; j++) acc[i][j] += ar[i] * br[j];
        }
        __syncthreads();
    }

    float gs = 1.f;
    if (EPI == 2) gs = 1.f / (1.f + __expf(-gatep[0]));

    #pragma unroll
    for (int i = 0; i < 8; i++) {
        const int m = mBase + ty * 8 + i;
        float* Crow = C + (size_t)m * N + nBase;
        const float* Rrow = (EPI >= 1) ? (res + (size_t)m * N + nBase) : nullptr;
        #pragma unroll
        for (int j = 0; j < 8; j++) {
            const int n = tx * 8 + j;
            float c = acc[i][j] + bias[nBase + n];
            if (EPI == 1) c += Rrow[n];
            if (EPI == 2) c = gs * c + Rrow[n];
            Crow[n] = c;
        }
    }
}

// ----------------------------------------------------------------------------
// Flash attention, fp32, HD=64, 64q x 64k tiles, 256 threads.
// Q rows at Qb + (b*Lq + q)*ldq + h*64 ; K/V similar with Lkv rows.
// bias (may be null): bias[(bh*Lq + q)*Lkv + k], added AFTER the 1/8 scale.
// Output Ob + (b*Lq + q)*ldo + h*64.
// grid: (Lq/64, B*H)
// ----------------------------------------------------------------------------
__global__ __launch_bounds__(256)
void flash_kernel(const float* __restrict__ Qb, int ldq,
                  const float* __restrict__ Kb, int ldk,
                  const float* __restrict__ Vb, int ldv,
                  const float* __restrict__ bias,
                  float* __restrict__ Ob, int ldo,
                  int Lq, int Lkv) {
    __shared__ float Qt[64][64];   // transposed: Qt[d][q]
    __shared__ float KP[64][64];   // K phase: KP[d][k] ; P phase: KP[k][q]
    __shared__ float Vs[64][64];   // natural:  Vs[k][d]

    const int bh = blockIdx.y;
    const int b = bh >> 4;          // H=16
    const int h = bh & 15;
    const int q0 = blockIdx.x * 64;
    const int t = threadIdx.x;
    const int tx = t & 15;          // column group
    const int ty = t >> 4;          // row group

    const int lrow = t >> 2;        // 0..63
    const int lc0 = (t & 3) * 16;   // 0,16,32,48

    // Load Q tile transposed
    {
        const float* qrow = Qb + (size_t)(b * Lq + q0 + lrow) * ldq + h * HD_ + lc0;
        #pragma unroll
        for (int c = 0; c < 16; c += 4) {
            const float4 v = *(const float4*)(qrow + c);
            Qt[lc0 + c + 0][lrow] = v.x; Qt[lc0 + c + 1][lrow] = v.y;
            Qt[lc0 + c + 2][lrow] = v.z; Qt[lc0 + c + 3][lrow] = v.w;
        }
    }

    float o[4][4];
    float m[4], l[4];
    #pragma unroll
    for (int i = 0; i < 4; i++) {
        m[i] = -1e30f; l[i] = 0.f;
        #pragma unroll
        for (int j = 0; j < 4; j++) o[i][j] = 0.f;
    }
    const float invs = 0.125f;  // 1/sqrt(64)

    for (int k0 = 0; k0 < Lkv; k0 += 64) {
        __syncthreads();  // previous PV / Q store fence
        {
            const float* krow = Kb + (size_t)(b * Lkv + k0 + lrow) * ldk + h * HD_ + lc0;
            const float* vrow = Vb + (size_t)(b * Lkv + k0 + lrow) * ldv + h * HD_ + lc0;
            #pragma unroll
            for (int c = 0; c < 16; c += 4) {
                const float4 kv = *(const float4*)(krow + c);
                KP[lc0 + c + 0][lrow] = kv.x; KP[lc0 + c + 1][lrow] = kv.y;
                KP[lc0 + c + 2][lrow] = kv.z; KP[lc0 + c + 3][lrow] = kv.w;
                *(float4*)&Vs[lrow][lc0 + c] = *(const float4*)(vrow + c);
            }
        }
        __syncthreads();

        // S = Q K^T
        float s[4][4];
        #pragma unroll
        for (int i = 0; i < 4; i++)
            #pragma unroll
            for (int j = 0; j < 4; j++) s[i][j] = 0.f;
        #pragma unroll
        for (int kk = 0; kk < 64; kk++) {
            const float4 qa = *(const float4*)&Qt[kk][ty * 4];
            const float4 kb = *(const float4*)&KP[kk][tx * 4];
            const float qr[4] = {qa.x, qa.y, qa.z, qa.w};
            const float kr[4] = {kb.x, kb.y, kb.z, kb.w};
            #pragma unroll
            for (int i = 0; i < 4; i++)
                #pragma unroll
                for (int j = 0; j < 4; j++) s[i][j] += qr[i] * kr[j];
        }

        // scale + bias
        if (bias) {
            #pragma unroll
            for (int i = 0; i < 4; i++) {
                const float4 bb = *(const float4*)(bias +
                    ((size_t)bh * Lq + (q0 + ty * 4 + i)) * Lkv + k0 + tx * 4);
                s[i][0] = s[i][0] * invs + bb.x;
                s[i][1] = s[i][1] * invs + bb.y;
                s[i][2] = s[i][2] * invs + bb.z;
                s[i][3] = s[i][3] * invs + bb.w;
            }
        } else {
            #pragma unroll
            for (int i = 0; i < 4; i++)
                #pragma unroll
                for (int j = 0; j < 4; j++) s[i][j] *= invs;
        }

        __syncthreads();  // done reading KP as K; about to overwrite with P

        // online softmax (per 4 rows; reduce across the 16 tx lanes)
        #pragma unroll
        for (int i = 0; i < 4; i++) {
            float rm = fmaxf(fmaxf(s[i][0], s[i][1]), fmaxf(s[i][2], s[i][3]));
            #pragma unroll
            for (int off = 8; off; off >>= 1)
                rm = fmaxf(rm, __shfl_xor_sync(0xffffffffu, rm, off));
            const float mn = fmaxf(m[i], rm);
            const float sc = __expf(m[i] - mn);
            s[i][0] = __expf(s[i][0] - mn);
            s[i][1] = __expf(s[i][1] - mn);
            s[i][2] = __expf(s[i][2] - mn);
            s[i][3] = __expf(s[i][3] - mn);
            float rs = s[i][0] + s[i][1] + s[i][2] + s[i][3];
            #pragma unroll
            for (int off = 8; off; off >>= 1)
                rs += __shfl_xor_sync(0xffffffffu, rs, off);
            l[i] = l[i] * sc + rs;
            m[i] = mn;
            #pragma unroll
            for (int j = 0; j < 4; j++) o[i][j] *= sc;
        }

        // store P transposed: KP[k][q]
        #pragma unroll
        for (int j = 0; j < 4; j++) {
            const float4 pv = make_float4(s[0][j], s[1][j], s[2][j], s[3][j]);
            *(float4*)&KP[tx * 4 + j][ty * 4] = pv;
        }
        __syncthreads();

        // O += P V
        #pragma unroll
        for (int kk = 0; kk < 64; kk++) {
            const float4 pa = *(const float4*)&KP[kk][ty * 4];
            const float4 vb = *(const float4*)&Vs[kk][tx * 4];
            const float pr[4] = {pa.x, pa.y, pa.z, pa.w};
            const float vr[4] = {vb.x, vb.y, vb.z, vb.w};
            #pragma unroll
            for (int i = 0; i < 4; i++)
                #pragma unroll
                for (int j = 0; j < 4; j++) o[i][j] += pr[i] * vr[j];
        }
    }

    // normalize + store
    #pragma unroll
    for (int i = 0; i < 4; i++) {
        const float inv = 1.f / l[i];
        const float4 ov = make_float4(o[i][0] * inv, o[i][1] * inv,
                                      o[i][2] * inv, o[i][3] * inv);
        *(float4*)(Ob + (size_t)(b * Lq + q0 + ty * 4 + i) * ldo + h * HD_ + tx * 4) = ov;
    }
}

// ----------------------------------------------------------------------------
// GEGLU: gg[m][j] = f[m][j] * gelu_exact(f[m][FF+j]),  m<4096, j<4096
// Vectorized float4: one thread handles one float4 of the FF columns.
// ----------------------------------------------------------------------------
__device__ __forceinline__ float gelu_exact(float x) {
    return 0.5f * x * (1.0f + erff(x * 0.7071067811865476f));
}

__global__ __launch_bounds__(256)
void geglu_kernel(const float* __restrict__ f, float* __restrict__ gg) {
    const int idx4 = blockIdx.x * blockDim.x + threadIdx.x;  // 0 .. 4096*1024-1
    const int mrow = idx4 >> 10;
    const int j4 = (idx4 & 1023) * 4;
    const float4 val = *(const float4*)(f + (size_t)mrow * (2 * FF_) + j4);
    const float4 gt  = *(const float4*)(f + (size_t)mrow * (2 * FF_) + FF_ + j4);
    float4 out;
    out.x = val.x * gelu_exact(gt.x);
    out.y = val.y * gelu_exact(gt.y);
    out.z = val.z * gelu_exact(gt.z);
    out.w = val.w * gelu_exact(gt.w);
    *(float4*)(gg + (size_t)mrow * FF_ + j4) = out;
}

// ----------------------------------------------------------------------------
// Host orchestration
// ----------------------------------------------------------------------------
extern "C" void kernel_launch(void* const* d_in, const int* in_sizes, int n_in,
                              void* d_out, int out_size) {
    const float* x          = (const float*)d_in[0];
    const float* alibi      = (const float*)d_in[1];
    const float* species    = (const float*)d_in[2];
    const float* norm1_g    = (const float*)d_in[3];
    const float* norm1_b    = (const float*)d_in[4];
    const float* sa_wqkv    = (const float*)d_in[5];
    const float* sa_bqkv    = (const float*)d_in[6];
    const float* sa_wo      = (const float*)d_in[7];
    const float* sa_bo      = (const float*)d_in[8];
    const float* ca_nq_g    = (const float*)d_in[9];
    const float* ca_nq_b    = (const float*)d_in[10];
    const float* ca_nkv_g   = (const float*)d_in[11];
    const float* ca_nkv_b   = (const float*)d_in[12];
    const float* ca_wqkv    = (const float*)d_in[13];
    const float* ca_bqkv    = (const float*)d_in[14];
    const float* ca_wo      = (const float*)d_in[15];
    const float* ca_bo      = (const float*)d_in[16];
    const float* gate_param = (const float*)d_in[17];
    const float* ffn_g      = (const float*)d_in[18];
    const float* ffn_b      = (const float*)d_in[19];
    const float* ffn_w1     = (const float*)d_in[20];
    const float* ffn_b1     = (const float*)d_in[21];
    const float* ffn_w2     = (const float*)d_in[22];
    const float* ffn_b2     = (const float*)d_in[23];
    float* out = (float*)d_out;

    float* S = nullptr;
    cudaGetSymbolAddress((void**)&S, g_scratch);
    float* ln   = S + OFF_LN;
    float* qkv  = S + OFF_QKV;
    float* attn = S + OFF_ATTN;
    float* x1   = S + OFF_X1;
    float* x2   = S + OFF_X2;
    float* kvn  = S + OFF_KVN;
    float* ckv  = S + OFF_CKV;
    float* f    = S + OFF_F;
    float* gg   = S + OFF_GG;

    // ---- Self-attention ----
    ln_kernel<<<M_, 256>>>(x, norm1_g, norm1_b, ln);
    gemm_kernel<0><<<dim3(3 * D_ / 128, M_ / 128), 256>>>(
        ln, sa_wqkv, sa_bqkv, nullptr, nullptr, qkv, M_, 3 * D_, D_);
    flash_kernel<<<dim3(L_ / 64, B_ * H_), 256>>>(
        qkv, 3 * D_, qkv + D_, 3 * D_, qkv + 2 * D_, 3 * D_,
        alibi, attn, D_, L_, L_);
    gemm_kernel<1><<<dim3(D_ / 128, M_ / 128), 256>>>(
        attn, sa_wo, sa_bo, x, nullptr, x1, M_, D_, D_);

    // ---- Cross-attention ----
    ln_kernel<<<M_, 256>>>(x1, ca_nq_g, ca_nq_b, ln);
    ln_kernel<<<B_ * NS_, 256>>>(species, ca_nkv_g, ca_nkv_b, kvn);
    gemm_kernel<0><<<dim3(D_ / 128, M_ / 128), 256>>>(
        ln, ca_wqkv, ca_bqkv, nullptr, nullptr, attn /* cq */, M_, D_, D_);
    gemm_kernel<0><<<dim3(2 * D_ / 128, (B_ * NS_) / 128), 256>>>(
        kvn, ca_wqkv + (size_t)D_ * D_, ca_bqkv + D_, nullptr, nullptr,
        ckv, B_ * NS_, 2 * D_, D_);
    flash_kernel<<<dim3(L_ / 64, B_ * H_), 256>>>(
        attn, D_, ckv, 2 * D_, ckv + D_, 2 * D_,
        nullptr, ln /* cross out */, D_, L_, NS_);
    gemm_kernel<2><<<dim3(D_ / 128, M_ / 128), 256>>>(
        ln, ca_wo, ca_bo, x1, gate_param, x2, M_, D_, D_);

    // ---- FFN (GEGLU) ----
    ln_kernel<<<M_, 256>>>(x2, ffn_g, ffn_b, attn);
    gemm_kernel<0><<<dim3(2 * FF_ / 128, M_ / 128), 256>>>(
        attn, ffn_w1, ffn_b1, nullptr, nullptr, f, M_, 2 * FF_, D_);
    geglu_kernel<<<(M_ * FF_ / 4) / 256, 256>>>(f, gg);
    gemm_kernel<1><<<dim3(D_ / 128, M_ / 128), 256>>>(
        gg, ffn_w2, ffn_b2, x2, nullptr, out, M_, D_, FF_);
}

// round 6
// speedup vs baseline: 2.3395x; 2.3359x over previous
#include <cuda_runtime.h>
#include <cuda_bf16.h>
#include <math.h>
#include <stdint.h>

// ----------------------------------------------------------------------------
// Shapes (fixed)
// ----------------------------------------------------------------------------
#define B_   4
#define L_   1024
#define D_   1024
#define H_   16
#define HD_  64
#define FF_  4096
#define NS_  64
#define M_   (B_ * L_)          // 4096 rows

// ----------------------------------------------------------------------------
// Scratch (bytes), all offsets 1024-aligned
// ----------------------------------------------------------------------------
#define SZ_WQKV   (3072u*1024u*2u)
#define SZ_WO     (1024u*1024u*2u)
#define SZ_WF1    (8192u*1024u*2u)
#define SZ_WF2    (1024u*4096u*2u)
#define SZ_ACT    (4096u*1024u*2u)
#define SZ_KVN    (256u*1024u*2u)
#define SZ_GG     (4096u*4096u*2u)
#define SZ_QKV32  (4096ull*3072u*4u)
#define SZ_D32    (4096ull*1024u*4u)
#define SZ_CKV32  (256u*2048u*4u)
#define SZ_F32    (4096ull*8192u*4u)

#define O_WQKVS_H   0ull
#define O_WQKVS_L   (O_WQKVS_H + SZ_WQKV)
#define O_WSAO_H    (O_WQKVS_L + SZ_WQKV)
#define O_WSAO_L    (O_WSAO_H + SZ_WO)
#define O_WQKVC_H   (O_WSAO_L + SZ_WO)
#define O_WQKVC_L   (O_WQKVC_H + SZ_WQKV)
#define O_WCAO_H    (O_WQKVC_L + SZ_WQKV)
#define O_WCAO_L    (O_WCAO_H + SZ_WO)
#define O_WF1_H     (O_WCAO_L + SZ_WO)
#define O_WF1_L     (O_WF1_H + SZ_WF1)
#define O_WF2_H     (O_WF1_L + SZ_WF1)
#define O_WF2_L     (O_WF2_H + SZ_WF2)
#define O_LN_H      (O_WF2_L + SZ_WF2)
#define O_LN_L      (O_LN_H + SZ_ACT)
#define O_AT_H      (O_LN_L + SZ_ACT)
#define O_AT_L      (O_AT_H + SZ_ACT)
#define O_KVN_H     (O_AT_L + SZ_ACT)
#define O_KVN_L     (O_KVN_H + SZ_KVN)
#define O_GG_H      (O_KVN_L + SZ_KVN)
#define O_GG_L      (O_GG_H + SZ_GG)
#define O_QKV       (O_GG_L + SZ_GG)
#define O_CQ        (O_QKV + SZ_QKV32)
#define O_CKV       (O_CQ + SZ_D32)
#define O_X1        (O_CKV + SZ_CKV32)
#define O_X2        (O_X1 + SZ_D32)
#define O_F         (O_X2 + SZ_D32)
#define SCRATCH_BYTES (O_F + SZ_F32)

__device__ __align__(1024) char g_scratch[SCRATCH_BYTES];

// ----------------------------------------------------------------------------
// PTX helpers (family-agnostic: ldmatrix / mma.sync / cp.async only)
// ----------------------------------------------------------------------------
__device__ __forceinline__ uint32_t smem_u32(const void* p) {
    uint32_t a;
    asm("{ .reg .u64 t; cvta.to.shared.u64 t, %1; cvt.u32.u64 %0, t; }"
        : "=r"(a) : "l"(p));
    return a;
}
__device__ __forceinline__ void cpa16(uint32_t s, const void* g) {
    asm volatile("cp.async.cg.shared.global [%0], [%1], 16;" :: "r"(s), "l"(g));
}
#define CP_COMMIT() asm volatile("cp.async.commit_group;" ::: "memory")
#define CP_WAIT0() asm volatile("cp.async.wait_group 0;" ::: "memory")
#define CP_WAIT1() asm volatile("cp.async.wait_group 1;" ::: "memory")

__device__ __forceinline__ void ldm_x4(uint32_t* r, uint32_t addr) {
    asm volatile("ldmatrix.sync.aligned.m8n8.x4.shared.b16 {%0,%1,%2,%3}, [%4];"
        : "=r"(r[0]), "=r"(r[1]), "=r"(r[2]), "=r"(r[3]) : "r"(addr));
}
__device__ __forceinline__ void mma_bf16(float* d, const uint32_t* a, const uint32_t* b) {
    asm volatile(
        "mma.sync.aligned.m16n8k16.row.col.f32.bf16.bf16.f32 "
        "{%0,%1,%2,%3}, {%4,%5,%6,%7}, {%8,%9}, {%0,%1,%2,%3};"
        : "+f"(d[0]), "+f"(d[1]), "+f"(d[2]), "+f"(d[3])
        : "r"(a[0]), "r"(a[1]), "r"(a[2]), "r"(a[3]), "r"(b[0]), "r"(b[1]));
}

__device__ __forceinline__ __nv_bfloat162 pack_hi(float a, float b) {
    return __halves2bfloat162(__float2bfloat16(a), __float2bfloat16(b));
}
__device__ __forceinline__ __nv_bfloat162 pack_lo(float a, float b) {
    __nv_bfloat16 ha = __float2bfloat16(a), hb = __float2bfloat16(b);
    return __halves2bfloat162(__float2bfloat16(a - __bfloat162float(ha)),
                              __float2bfloat16(b - __bfloat162float(hb)));
}

// ----------------------------------------------------------------------------
// Weight split: fp32 -> bf16 hi/lo planes
// ----------------------------------------------------------------------------
__global__ __launch_bounds__(256)
void cvt_split_kernel(const float4* __restrict__ w, __nv_bfloat162* __restrict__ hi,
                      __nv_bfloat162* __restrict__ lo, int n4) {
    int i = blockIdx.x * 256 + threadIdx.x;
    if (i >= n4) return;
    const float4 v = w[i];
    hi[i * 2]     = pack_hi(v.x, v.y);
    hi[i * 2 + 1] = pack_hi(v.z, v.w);
    lo[i * 2]     = pack_lo(v.x, v.y);
    lo[i * 2 + 1] = pack_lo(v.z, v.w);
}

// ----------------------------------------------------------------------------
// LayerNorm: one block per row, 256 threads, D=1024; outputs bf16 hi/lo planes
// ----------------------------------------------------------------------------
__global__ __launch_bounds__(256)
void ln_kernel(const float* __restrict__ x, const float* __restrict__ g,
               const float* __restrict__ b, __nv_bfloat16* __restrict__ yh,
               __nv_bfloat16* __restrict__ yl) {
    const int row = blockIdx.x;
    const int t = threadIdx.x;
    const float4 v = ((const float4*)(x + (size_t)row * D_))[t];

    __shared__ float red[8];
    __shared__ float stat[2];

    float s = v.x + v.y + v.z + v.w;
    #pragma unroll
    for (int o = 16; o; o >>= 1) s += __shfl_xor_sync(0xffffffffu, s, o);
    if ((t & 31) == 0) red[t >> 5] = s;
    __syncthreads();
    if (t == 0) {
        float s2 = 0.f;
        #pragma unroll
        for (int i = 0; i < 8; i++) s2 += red[i];
        stat[0] = s2 * (1.0f / D_);
    }
    __syncthreads();
    const float mu = stat[0];
    const float dx = v.x - mu, dy = v.y - mu, dz = v.z - mu, dw = v.w - mu;

    float q = dx * dx + dy * dy + dz * dz + dw * dw;
    #pragma unroll
    for (int o = 16; o; o >>= 1) q += __shfl_xor_sync(0xffffffffu, q, o);
    if ((t & 31) == 0) red[t >> 5] = q;
    __syncthreads();
    if (t == 0) {
        float s2 = 0.f;
        #pragma unroll
        for (int i = 0; i < 8; i++) s2 += red[i];
        stat[1] = rsqrtf(s2 * (1.0f / D_) + 1e-5f);
    }
    __syncthreads();
    const float rs = stat[1];

    const float4 gv = ((const float4*)g)[t];
    const float4 bv = ((const float4*)b)[t];
    float o0 = dx * rs * gv.x + bv.x;
    float o1 = dy * rs * gv.y + bv.y;
    float o2 = dz * rs * gv.z + bv.z;
    float o3 = dw * rs * gv.w + bv.w;
    const size_t base = (size_t)row * D_ + t * 4;
    *(__nv_bfloat162*)(yh + base)     = pack_hi(o0, o1);
    *(__nv_bfloat162*)(yh + base + 2) = pack_hi(o2, o3);
    *(__nv_bfloat162*)(yl + base)     = pack_lo(o0, o1);
    *(__nv_bfloat162*)(yl + base + 2) = pack_lo(o2, o3);
}

// ----------------------------------------------------------------------------
// mma.sync split-bf16 GEMM: C[M,N] = A[M,K] @ W[N,K]^T (+epilogue)
// CTA tile 128x128, warp tile 64x32 (2x4 warps), K-chunk 64, double-buffered
// cp.async. SMEM rows padded to 72 elems (144 B) -> conflict-free ldmatrix.
// EPI: 0 bias; 1 bias+res; 2 sigmoid(gate)*(..)+res
// ----------------------------------------------------------------------------
#define TM 128
#define TN 128
#define KCH 64
#define RS 72                       // padded row stride (bf16 elems)
#define RSB (RS * 2)                // 144 bytes
#define PLANE_B (128 * RSB)         // 18432
#define SA_H 0
#define SA_L PLANE_B
#define SW_H (2 * PLANE_B)
#define SW_L (3 * PLANE_B)
#define STAGE_B (4 * PLANE_B)       // 73728
#define GEMM_SMEM (2 * STAGE_B)     // 147456

template <int EPI>
__global__ __launch_bounds__(256, 1)
void mma_gemm(const __nv_bfloat16* __restrict__ Ah, const __nv_bfloat16* __restrict__ Al,
              const __nv_bfloat16* __restrict__ Wh, const __nv_bfloat16* __restrict__ Wl,
              const float* __restrict__ bias, const float* __restrict__ res,
              const float* __restrict__ gatep, float* __restrict__ C,
              int N, int K, int wRowOff) {
    extern __shared__ char smem[];
    const uint32_t sb = smem_u32(smem);
    const int t = threadIdx.x;
    const int lane = t & 31;
    const int wid = t >> 5;
    const int wm = wid & 1;         // 0..1 (m tile of 64)
    const int wn = wid >> 1;        // 0..3 (n tile of 32)

    const int mBase = blockIdx.y * TM;
    const int nBase = blockIdx.x * TN;

    // ---- load geometry: 4 chunks of 16B per plane per thread ----
    uint32_t sOff[4];
    size_t gOffA[4], gOffW[4];
    #pragma unroll
    for (int j = 0; j < 4; j++) {
        const int id = t + 256 * j;       // 0..1023
        const int r = id >> 3;            // row 0..127
        const int ch = id & 7;            // 16B chunk 0..7
        sOff[j] = (uint32_t)r * RSB + ch * 16;
        gOffA[j] = ((size_t)(mBase + r) * K + ch * 8) * 2;
        gOffW[j] = ((size_t)(nBase + wRowOff + r) * K + ch * 8) * 2;
    }
    const char* pAh = (const char*)Ah;
    const char* pAl = (const char*)Al;
    const char* pWh = (const char*)Wh;
    const char* pWl = (const char*)Wl;

    auto load_stage = [&](int c, int s) {
        const uint32_t sd = sb + s * STAGE_B;
        const size_t kb = (size_t)c * 128;   // 64 bf16 per chunk = 128 B
        #pragma unroll
        for (int j = 0; j < 4; j++) {
            cpa16(sd + SA_H + sOff[j], pAh + gOffA[j] + kb);
            cpa16(sd + SA_L + sOff[j], pAl + gOffA[j] + kb);
            cpa16(sd + SW_H + sOff[j], pWh + gOffW[j] + kb);
            cpa16(sd + SW_L + sOff[j], pWl + gOffW[j] + kb);
        }
    };

    float acc[4][4][4];
    #pragma unroll
    for (int i = 0; i < 4; i++)
        #pragma unroll
        for (int j = 0; j < 4; j++)
            #pragma unroll
            for (int k = 0; k < 4; k++) acc[i][j][k] = 0.f;

    const int nch = K / KCH;
    load_stage(0, 0);
    CP_COMMIT();

    // ldmatrix address templates (within a stage)
    const uint32_t aRowOff = (uint32_t)(wm * 64 + (lane & 15)) * RSB
                           + ((lane >> 4) * 8) * 2;
    const uint32_t bRowOff = (uint32_t)(wn * 32 + (lane & 7) + ((lane >> 4) & 1) * 8) * RSB
                           + (((lane >> 3) & 1) * 8) * 2;

    for (int c = 0; c < nch; c++) {
        if (c + 1 < nch) { load_stage(c + 1, (c + 1) & 1); CP_COMMIT(); }
        if (c + 1 < nch) { CP_WAIT1(); } else { CP_WAIT0(); }
        __syncthreads();

        const uint32_t sd = sb + (c & 1) * STAGE_B;
        #pragma unroll
        for (int kk = 0; kk < KCH; kk += 16) {
            uint32_t ah[4][4], al[4][4];
            #pragma unroll
            for (int mf = 0; mf < 4; mf++) {
                const uint32_t ad = sd + aRowOff + (uint32_t)(mf * 16) * RSB + kk * 2;
                ldm_x4(ah[mf], ad + SA_H);
                ldm_x4(al[mf], ad + SA_L);
            }
            uint32_t bh[4][2], bl[4][2];
            #pragma unroll
            for (int nf2 = 0; nf2 < 2; nf2++) {
                const uint32_t bd = sd + bRowOff + (uint32_t)(nf2 * 16) * RSB + kk * 2;
                uint32_t r[4];
                ldm_x4(r, bd + SW_H);
                bh[nf2 * 2][0] = r[0]; bh[nf2 * 2][1] = r[1];
                bh[nf2 * 2 + 1][0] = r[2]; bh[nf2 * 2 + 1][1] = r[3];
                ldm_x4(r, bd + SW_L);
                bl[nf2 * 2][0] = r[0]; bl[nf2 * 2][1] = r[1];
                bl[nf2 * 2 + 1][0] = r[2]; bl[nf2 * 2 + 1][1] = r[3];
            }
            #pragma unroll
            for (int mf = 0; mf < 4; mf++)
                #pragma unroll
                for (int nf = 0; nf < 4; nf++) {
                    mma_bf16(acc[mf][nf], ah[mf], bh[nf]);
                    mma_bf16(acc[mf][nf], al[mf], bh[nf]);
                    mma_bf16(acc[mf][nf], ah[mf], bl[nf]);
                }
        }
        __syncthreads();
    }

    // ---- epilogue ----
    float gs = 1.f;
    if (EPI == 2) gs = 1.f / (1.f + __expf(-gatep[0]));

    const int mWarp = mBase + wm * 64;
    const int nWarp = nBase + wn * 32;
    #pragma unroll
    for (int mf = 0; mf < 4; mf++) {
        const int r0 = mWarp + mf * 16 + (lane >> 2);
        #pragma unroll
        for (int nf = 0; nf < 4; nf++) {
            const int c0 = nWarp + nf * 8 + 2 * (lane & 3);
            const float b0 = bias[c0], b1 = bias[c0 + 1];
            float v0 = acc[mf][nf][0] + b0;
            float v1 = acc[mf][nf][1] + b1;
            float v2 = acc[mf][nf][2] + b0;
            float v3 = acc[mf][nf][3] + b1;
            if (EPI == 1) {
                v0 += res[(size_t)r0 * N + c0];
                v1 += res[(size_t)r0 * N + c0 + 1];
                v2 += res[(size_t)(r0 + 8) * N + c0];
                v3 += res[(size_t)(r0 + 8) * N + c0 + 1];
            } else if (EPI == 2) {
                v0 = gs * v0 + res[(size_t)r0 * N + c0];
                v1 = gs * v1 + res[(size_t)r0 * N + c0 + 1];
                v2 = gs * v2 + res[(size_t)(r0 + 8) * N + c0];
                v3 = gs * v3 + res[(size_t)(r0 + 8) * N + c0 + 1];
            }
            *(float2*)(C + (size_t)r0 * N + c0) = make_float2(v0, v1);
            *(float2*)(C + (size_t)(r0 + 8) * N + c0) = make_float2(v2, v3);
        }
    }
}

// ----------------------------------------------------------------------------
// Flash attention, fp32 compute, HD=64, 64q x 64k tiles, 256 threads.
// Outputs bf16 hi/lo planes with row stride D_.
// ----------------------------------------------------------------------------
__global__ __launch_bounds__(256)
void flash_kernel(const float* __restrict__ Qb, int ldq,
                  const float* __restrict__ Kb, int ldk,
                  const float* __restrict__ Vb, int ldv,
                  const float* __restrict__ bias,
                  __nv_bfloat16* __restrict__ Oh, __nv_bfloat16* __restrict__ Ol,
                  int Lq, int Lkv) {
    __shared__ float Qt[64][64];
    __shared__ float KP[64][64];
    __shared__ float Vs[64][64];

    const int bh = blockIdx.y;
    const int b = bh >> 4;
    const int h = bh & 15;
    const int q0 = blockIdx.x * 64;
    const int t = threadIdx.x;
    const int tx = t & 15;
    const int ty = t >> 4;

    const int lrow = t >> 2;
    const int lc0 = (t & 3) * 16;

    {
        const float* qrow = Qb + (size_t)(b * Lq + q0 + lrow) * ldq + h * HD_ + lc0;
        #pragma unroll
        for (int c = 0; c < 16; c += 4) {
            const float4 v = *(const float4*)(qrow + c);
            Qt[lc0 + c + 0][lrow] = v.x; Qt[lc0 + c + 1][lrow] = v.y;
            Qt[lc0 + c + 2][lrow] = v.z; Qt[lc0 + c + 3][lrow] = v.w;
        }
    }

    float o[4][4];
    float m[4], l[4];
    #pragma unroll
    for (int i = 0; i < 4; i++) {
        m[i] = -1e30f; l[i] = 0.f;
        #pragma unroll
        for (int j = 0; j < 4; j++) o[i][j] = 0.f;
    }
    const float invs = 0.125f;

    for (int k0 = 0; k0 < Lkv; k0 += 64) {
        __syncthreads();
        {
            const float* krow = Kb + (size_t)(b * Lkv + k0 + lrow) * ldk + h * HD_ + lc0;
            const float* vrow = Vb + (size_t)(b * Lkv + k0 + lrow) * ldv + h * HD_ + lc0;
            #pragma unroll
            for (int c = 0; c < 16; c += 4) {
                const float4 kv = *(const float4*)(krow + c);
                KP[lc0 + c + 0][lrow] = kv.x; KP[lc0 + c + 1][lrow] = kv.y;
                KP[lc0 + c + 2][lrow] = kv.z; KP[lc0 + c + 3][lrow] = kv.w;
                *(float4*)&Vs[lrow][lc0 + c] = *(const float4*)(vrow + c);
            }
        }
        __syncthreads();

        float s[4][4];
        #pragma unroll
        for (int i = 0; i < 4; i++)
            #pragma unroll
            for (int j = 0; j < 4; j++) s[i][j] = 0.f;
        #pragma unroll
        for (int kk = 0; kk < 64; kk++) {
            const float4 qa = *(const float4*)&Qt[kk][ty * 4];
            const float4 kb = *(const float4*)&KP[kk][tx * 4];
            const float qr[4] = {qa.x, qa.y, qa.z, qa.w};
            const float kr[4] = {kb.x, kb.y, kb.z, kb.w};
            #pragma unroll
            for (int i = 0; i < 4; i++)
                #pragma unroll
                for (int j = 0; j < 4; j++) s[i][j] += qr[i] * kr[j];
        }

        if (bias) {
            #pragma unroll
            for (int i = 0; i < 4; i++) {
                const float4 bb = *(const float4*)(bias +
                    ((size_t)bh * Lq + (q0 + ty * 4 + i)) * Lkv + k0 + tx * 4);
                s[i][0] = s[i][0] * invs + bb.x;
                s[i][1] = s[i][1] * invs + bb.y;
                s[i][2] = s[i][2] * invs + bb.z;
                s[i][3] = s[i][3] * invs + bb.w;
            }
        } else {
            #pragma unroll
            for (int i = 0; i < 4; i++)
                #pragma unroll
                for (int j = 0; j < 4; j++) s[i][j] *= invs;
        }

        __syncthreads();

        #pragma unroll
        for (int i = 0; i < 4; i++) {
            float rm = fmaxf(fmaxf(s[i][0], s[i][1]), fmaxf(s[i][2], s[i][3]));
            #pragma unroll
            for (int off = 8; off; off >>= 1)
                rm = fmaxf(rm, __shfl_xor_sync(0xffffffffu, rm, off));
            const float mn = fmaxf(m[i], rm);
            const float sc = __expf(m[i] - mn);
            s[i][0] = __expf(s[i][0] - mn);
            s[i][1] = __expf(s[i][1] - mn);
            s[i][2] = __expf(s[i][2] - mn);
            s[i][3] = __expf(s[i][3] - mn);
            float rs = s[i][0] + s[i][1] + s[i][2] + s[i][3];
            #pragma unroll
            for (int off = 8; off; off >>= 1)
                rs += __shfl_xor_sync(0xffffffffu, rs, off);
            l[i] = l[i] * sc + rs;
            m[i] = mn;
            #pragma unroll
            for (int j = 0; j < 4; j++) o[i][j] *= sc;
        }

        #pragma unroll
        for (int j = 0; j < 4; j++) {
            const float4 pv = make_float4(s[0][j], s[1][j], s[2][j], s[3][j]);
            *(float4*)&KP[tx * 4 + j][ty * 4] = pv;
        }
        __syncthreads();

        #pragma unroll
        for (int kk = 0; kk < 64; kk++) {
            const float4 pa = *(const float4*)&KP[kk][ty * 4];
            const float4 vb = *(const float4*)&Vs[kk][tx * 4];
            const float pr[4] = {pa.x, pa.y, pa.z, pa.w};
            const float vr[4] = {vb.x, vb.y, vb.z, vb.w};
            #pragma unroll
            for (int i = 0; i < 4; i++)
                #pragma unroll
                for (int j = 0; j < 4; j++) o[i][j] += pr[i] * vr[j];
        }
    }

    #pragma unroll
    for (int i = 0; i < 4; i++) {
        const float inv = 1.f / l[i];
        const float o0 = o[i][0] * inv, o1 = o[i][1] * inv;
        const float o2 = o[i][2] * inv, o3 = o[i][3] * inv;
        const size_t base = (size_t)(b * Lq + q0 + ty * 4 + i) * D_ + h * HD_ + tx * 4;
        *(__nv_bfloat162*)(Oh + base)     = pack_hi(o0, o1);
        *(__nv_bfloat162*)(Oh + base + 2) = pack_hi(o2, o3);
        *(__nv_bfloat162*)(Ol + base)     = pack_lo(o0, o1);
        *(__nv_bfloat162*)(Ol + base + 2) = pack_lo(o2, o3);
    }
}

// ----------------------------------------------------------------------------
// GEGLU -> bf16 hi/lo planes
// ----------------------------------------------------------------------------
__device__ __forceinline__ float gelu_exact(float x) {
    return 0.5f * x * (1.0f + erff(x * 0.7071067811865476f));
}

__global__ __launch_bounds__(256)
void geglu_kernel(const float* __restrict__ f, __nv_bfloat16* __restrict__ gh,
                  __nv_bfloat16* __restrict__ gl) {
    const int idx4 = blockIdx.x * blockDim.x + threadIdx.x;
    const int mrow = idx4 >> 10;
    const int j4 = (idx4 & 1023) * 4;
    const float4 val = *(const float4*)(f + (size_t)mrow * (2 * FF_) + j4);
    const float4 gt  = *(const float4*)(f + (size_t)mrow * (2 * FF_) + FF_ + j4);
    const float o0 = val.x * gelu_exact(gt.x);
    const float o1 = val.y * gelu_exact(gt.y);
    const float o2 = val.z * gelu_exact(gt.z);
    const float o3 = val.w * gelu_exact(gt.w);
    const size_t base = (size_t)mrow * FF_ + j4;
    *(__nv_bfloat162*)(gh + base)     = pack_hi(o0, o1);
    *(__nv_bfloat162*)(gh + base + 2) = pack_hi(o2, o3);
    *(__nv_bfloat162*)(gl + base)     = pack_lo(o0, o1);
    *(__nv_bfloat162*)(gl + base + 2) = pack_lo(o2, o3);
}

// ----------------------------------------------------------------------------
// Host orchestration
// ----------------------------------------------------------------------------
extern "C" void kernel_launch(void* const* d_in, const int* in_sizes, int n_in,
                              void* d_out, int out_size) {
    const float* x          = (const float*)d_in[0];
    const float* alibi      = (const float*)d_in[1];
    const float* species    = (const float*)d_in[2];
    const float* norm1_g    = (const float*)d_in[3];
    const float* norm1_b    = (const float*)d_in[4];
    const float* sa_wqkv    = (const float*)d_in[5];
    const float* sa_bqkv    = (const float*)d_in[6];
    const float* sa_wo      = (const float*)d_in[7];
    const float* sa_bo      = (const float*)d_in[8];
    const float* ca_nq_g    = (const float*)d_in[9];
    const float* ca_nq_b    = (const float*)d_in[10];
    const float* ca_nkv_g   = (const float*)d_in[11];
    const float* ca_nkv_b   = (const float*)d_in[12];
    const float* ca_wqkv    = (const float*)d_in[13];
    const float* ca_bqkv    = (const float*)d_in[14];
    const float* ca_wo      = (const float*)d_in[15];
    const float* ca_bo      = (const float*)d_in[16];
    const float* gate_param = (const float*)d_in[17];
    const float* ffn_g      = (const float*)d_in[18];
    const float* ffn_b      = (const float*)d_in[19];
    const float* ffn_w1     = (const float*)d_in[20];
    const float* ffn_b1     = (const float*)d_in[21];
    const float* ffn_w2     = (const float*)d_in[22];
    const float* ffn_b2     = (const float*)d_in[23];
    float* out = (float*)d_out;

    char* S = nullptr;
    cudaGetSymbolAddress((void**)&S, g_scratch);
    #define BF(off) ((__nv_bfloat16*)(S + (off)))
    #define F32(off) ((float*)(S + (off)))
    __nv_bfloat16 *wqkvs_h = BF(O_WQKVS_H), *wqkvs_l = BF(O_WQKVS_L);
    __nv_bfloat16 *wsao_h = BF(O_WSAO_H), *wsao_l = BF(O_WSAO_L);
    __nv_bfloat16 *wqkvc_h = BF(O_WQKVC_H), *wqkvc_l = BF(O_WQKVC_L);
    __nv_bfloat16 *wcao_h = BF(O_WCAO_H), *wcao_l = BF(O_WCAO_L);
    __nv_bfloat16 *wf1_h = BF(O_WF1_H), *wf1_l = BF(O_WF1_L);
    __nv_bfloat16 *wf2_h = BF(O_WF2_H), *wf2_l = BF(O_WF2_L);
    __nv_bfloat16 *ln_h = BF(O_LN_H), *ln_l = BF(O_LN_L);
    __nv_bfloat16 *at_h = BF(O_AT_H), *at_l = BF(O_AT_L);
    __nv_bfloat16 *kvn_h = BF(O_KVN_H), *kvn_l = BF(O_KVN_L);
    __nv_bfloat16 *gg_h = BF(O_GG_H), *gg_l = BF(O_GG_L);
    float *qkv = F32(O_QKV), *cq = F32(O_CQ), *ckv = F32(O_CKV);
    float *x1 = F32(O_X1), *x2 = F32(O_X2), *f = F32(O_F);

    cudaFuncSetAttribute(mma_gemm<0>, cudaFuncAttributeMaxDynamicSharedMemorySize, GEMM_SMEM);
    cudaFuncSetAttribute(mma_gemm<1>, cudaFuncAttributeMaxDynamicSharedMemorySize, GEMM_SMEM);
    cudaFuncSetAttribute(mma_gemm<2>, cudaFuncAttributeMaxDynamicSharedMemorySize, GEMM_SMEM);

    // ---- weight split ----
    auto cvt = [&](const float* w, __nv_bfloat16* h, __nv_bfloat16* l, int n) {
        cvt_split_kernel<<<(n / 4 + 255) / 256, 256>>>(
            (const float4*)w, (__nv_bfloat162*)h, (__nv_bfloat162*)l, n / 4);
    };
    cvt(sa_wqkv, wqkvs_h, wqkvs_l, 3 * D_ * D_);
    cvt(sa_wo,   wsao_h,  wsao_l,  D_ * D_);
    cvt(ca_wqkv, wqkvc_h, wqkvc_l, 3 * D_ * D_);
    cvt(ca_wo,   wcao_h,  wcao_l,  D_ * D_);
    cvt(ffn_w1,  wf1_h,   wf1_l,   2 * FF_ * D_);
    cvt(ffn_w2,  wf2_h,   wf2_l,   D_ * FF_);

    // ---- Self-attention ----
    ln_kernel<<<M_, 256>>>(x, norm1_g, norm1_b, ln_h, ln_l);
    mma_gemm<0><<<dim3(3 * D_ / TN, M_ / TM), 256, GEMM_SMEM>>>(
        ln_h, ln_l, wqkvs_h, wqkvs_l, sa_bqkv, nullptr, nullptr, qkv, 3 * D_, D_, 0);
    flash_kernel<<<dim3(L_ / 64, B_ * H_), 256>>>(
        qkv, 3 * D_, qkv + D_, 3 * D_, qkv + 2 * D_, 3 * D_, alibi, at_h, at_l, L_, L_);
    mma_gemm<1><<<dim3(D_ / TN, M_ / TM), 256, GEMM_SMEM>>>(
        at_h, at_l, wsao_h, wsao_l, sa_bo, x, nullptr, x1, D_, D_, 0);

    // ---- Cross-attention ----
    ln_kernel<<<M_, 256>>>(x1, ca_nq_g, ca_nq_b, ln_h, ln_l);
    ln_kernel<<<B_ * NS_, 256>>>(species, ca_nkv_g, ca_nkv_b, kvn_h, kvn_l);
    mma_gemm<0><<<dim3(D_ / TN, M_ / TM), 256, GEMM_SMEM>>>(
        ln_h, ln_l, wqkvc_h, wqkvc_l, ca_bqkv, nullptr, nullptr, cq, D_, D_, 0);
    mma_gemm<0><<<dim3(2 * D_ / TN, (B_ * NS_) / TM), 256, GEMM_SMEM>>>(
        kvn_h, kvn_l, wqkvc_h, wqkvc_l, ca_bqkv + D_, nullptr, nullptr,
        ckv, 2 * D_, D_, D_);
    flash_kernel<<<dim3(L_ / 64, B_ * H_), 256>>>(
        cq, D_, ckv, 2 * D_, ckv + D_, 2 * D_, nullptr, at_h, at_l, L_, NS_);
    mma_gemm<2><<<dim3(D_ / TN, M_ / TM), 256, GEMM_SMEM>>>(
        at_h, at_l, wcao_h, wcao_l, ca_bo, x1, gate_param, x2, D_, D_, 0);

    // ---- FFN (GEGLU) ----
    ln_kernel<<<M_, 256>>>(x2, ffn_g, ffn_b, ln_h, ln_l);
    mma_gemm<0><<<dim3(2 * FF_ / TN, M_ / TM), 256, GEMM_SMEM>>>(
        ln_h, ln_l, wf1_h, wf1_l, ffn_b1, nullptr, nullptr, f, 2 * FF_, D_, 0);
    geglu_kernel<<<(M_ * FF_ / 4) / 256, 256>>>(f, gg_h, gg_l);
    mma_gemm<1><<<dim3(D_ / TN, M_ / TM), 256, GEMM_SMEM>>>(
        gg_h, gg_l, wf2_h, wf2_l, ffn_b2, x2, nullptr, out, D_, FF_, 0);
}

// round 7
// speedup vs baseline: 2.3407x; 1.0005x over previous
#include <cuda_runtime.h>
#include <cuda_bf16.h>
#include <math.h>
#include <stdint.h>

// ----------------------------------------------------------------------------
// Shapes (fixed)
// ----------------------------------------------------------------------------
#define B_   4
#define L_   1024
#define D_   1024
#define H_   16
#define HD_  64
#define FF_  4096
#define NS_  64
#define M_   (B_ * L_)          // 4096 rows

// ----------------------------------------------------------------------------
// Scratch (bytes), all offsets 1024-aligned
// ----------------------------------------------------------------------------
#define SZ_WQKV   (3072u*1024u*2u)
#define SZ_WO     (1024u*1024u*2u)
#define SZ_WF1    (8192u*1024u*2u)
#define SZ_WF2    (1024u*4096u*2u)
#define SZ_ACT    (4096u*1024u*2u)
#define SZ_KVN    (256u*1024u*2u)
#define SZ_GG     (4096u*4096u*2u)
#define SZ_QKV32  (4096ull*3072u*4u)
#define SZ_D32    (4096ull*1024u*4u)
#define SZ_CKV32  (256u*2048u*4u)
#define SZ_F32    (4096ull*8192u*4u)

#define O_WQKVS_H   0ull
#define O_WQKVS_L   (O_WQKVS_H + SZ_WQKV)
#define O_WSAO_H    (O_WQKVS_L + SZ_WQKV)
#define O_WSAO_L    (O_WSAO_H + SZ_WO)
#define O_WQKVC_H   (O_WSAO_L + SZ_WO)
#define O_WQKVC_L   (O_WQKVC_H + SZ_WQKV)
#define O_WCAO_H    (O_WQKVC_L + SZ_WQKV)
#define O_WCAO_L    (O_WCAO_H + SZ_WO)
#define O_WF1_H     (O_WCAO_L + SZ_WO)
#define O_WF1_L     (O_WF1_H + SZ_WF1)
#define O_WF2_H     (O_WF1_L + SZ_WF1)
#define O_WF2_L     (O_WF2_H + SZ_WF2)
#define O_LN_H      (O_WF2_L + SZ_WF2)
#define O_LN_L      (O_LN_H + SZ_ACT)
#define O_AT_H      (O_LN_L + SZ_ACT)
#define O_AT_L      (O_AT_H + SZ_ACT)
#define O_KVN_H     (O_AT_L + SZ_ACT)
#define O_KVN_L     (O_KVN_H + SZ_KVN)
#define O_GG_H      (O_KVN_L + SZ_KVN)
#define O_GG_L      (O_GG_H + SZ_GG)
#define O_QKV       (O_GG_L + SZ_GG)
#define O_CQ        (O_QKV + SZ_QKV32)
#define O_CKV       (O_CQ + SZ_D32)
#define O_X1        (O_CKV + SZ_CKV32)
#define O_X2        (O_X1 + SZ_D32)
#define O_F         (O_X2 + SZ_D32)
#define SCRATCH_BYTES (O_F + SZ_F32)

__device__ __align__(1024) char g_scratch[SCRATCH_BYTES];

// ----------------------------------------------------------------------------
// PTX helpers (family-agnostic: ldmatrix / mma.sync / cp.async only)
// ----------------------------------------------------------------------------
__device__ __forceinline__ uint32_t smem_u32(const void* p) {
    uint32_t a;
    asm("{ .reg .u64 t; cvta.to.shared.u64 t, %1; cvt.u32.u64 %0, t; }"
        : "=r"(a) : "l"(p));
    return a;
}
__device__ __forceinline__ void cpa16(uint32_t s, const void* g) {
    asm volatile("cp.async.cg.shared.global [%0], [%1], 16;" :: "r"(s), "l"(g));
}
#define CP_COMMIT() asm volatile("cp.async.commit_group;" ::: "memory")
#define CP_WAIT0() asm volatile("cp.async.wait_group 0;" ::: "memory")
#define CP_WAIT1() asm volatile("cp.async.wait_group 1;" ::: "memory")

__device__ __forceinline__ void ldm_x4(uint32_t* r, uint32_t addr) {
    asm volatile("ldmatrix.sync.aligned.m8n8.x4.shared.b16 {%0,%1,%2,%3}, [%4];"
        : "=r"(r[0]), "=r"(r[1]), "=r"(r[2]), "=r"(r[3]) : "r"(addr));
}
__device__ __forceinline__ void mma_bf16(float* d, const uint32_t* a, const uint32_t* b) {
    asm volatile(
        "mma.sync.aligned.m16n8k16.row.col.f32.bf16.bf16.f32 "
        "{%0,%1,%2,%3}, {%4,%5,%6,%7}, {%8,%9}, {%0,%1,%2,%3};"
        : "+f"(d[0]), "+f"(d[1]), "+f"(d[2]), "+f"(d[3])
        : "r"(a[0]), "r"(a[1]), "r"(a[2]), "r"(a[3]), "r"(b[0]), "r"(b[1]));
}

__device__ __forceinline__ __nv_bfloat162 pack_hi(float a, float b) {
    return __halves2bfloat162(__float2bfloat16(a), __float2bfloat16(b));
}
__device__ __forceinline__ __nv_bfloat162 pack_lo(float a, float b) {
    __nv_bfloat16 ha = __float2bfloat16(a), hb = __float2bfloat16(b);
    return __halves2bfloat162(__float2bfloat16(a - __bfloat162float(ha)),
                              __float2bfloat16(b - __bfloat162float(hb)));
}

// ----------------------------------------------------------------------------
// Weight split: fp32 -> bf16 hi/lo planes
// ----------------------------------------------------------------------------
__global__ __launch_bounds__(256)
void cvt_split_kernel(const float4* __restrict__ w, __nv_bfloat162* __restrict__ hi,
                      __nv_bfloat162* __restrict__ lo, int n4) {
    int i = blockIdx.x * 256 + threadIdx.x;
    if (i >= n4) return;
    const float4 v = w[i];
    hi[i * 2]     = pack_hi(v.x, v.y);
    hi[i * 2 + 1] = pack_hi(v.z, v.w);
    lo[i * 2]     = pack_lo(v.x, v.y);
    lo[i * 2 + 1] = pack_lo(v.z, v.w);
}

// ----------------------------------------------------------------------------
// LayerNorm: one block per row, 256 threads, D=1024; outputs bf16 hi/lo planes
// ----------------------------------------------------------------------------
__global__ __launch_bounds__(256)
void ln_kernel(const float* __restrict__ x, const float* __restrict__ g,
               const float* __restrict__ b, __nv_bfloat16* __restrict__ yh,
               __nv_bfloat16* __restrict__ yl) {
    const int row = blockIdx.x;
    const int t = threadIdx.x;
    const float4 v = ((const float4*)(x + (size_t)row * D_))[t];

    __shared__ float red[8];
    __shared__ float stat[2];

    float s = v.x + v.y + v.z + v.w;
    #pragma unroll
    for (int o = 16; o; o >>= 1) s += __shfl_xor_sync(0xffffffffu, s, o);
    if ((t & 31) == 0) red[t >> 5] = s;
    __syncthreads();
    if (t == 0) {
        float s2 = 0.f;
        #pragma unroll
        for (int i = 0; i < 8; i++) s2 += red[i];
        stat[0] = s2 * (1.0f / D_);
    }
    __syncthreads();
    const float mu = stat[0];
    const float dx = v.x - mu, dy = v.y - mu, dz = v.z - mu, dw = v.w - mu;

    float q = dx * dx + dy * dy + dz * dz + dw * dw;
    #pragma unroll
    for (int o = 16; o; o >>= 1) q += __shfl_xor_sync(0xffffffffu, q, o);
    if ((t & 31) == 0) red[t >> 5] = q;
    __syncthreads();
    if (t == 0) {
        float s2 = 0.f;
        #pragma unroll
        for (int i = 0; i < 8; i++) s2 += red[i];
        stat[1] = rsqrtf(s2 * (1.0f / D_) + 1e-5f);
    }
    __syncthreads();
    const float rs = stat[1];

    const float4 gv = ((const float4*)g)[t];
    const float4 bv = ((const float4*)b)[t];
    float o0 = dx * rs * gv.x + bv.x;
    float o1 = dy * rs * gv.y + bv.y;
    float o2 = dz * rs * gv.z + bv.z;
    float o3 = dw * rs * gv.w + bv.w;
    const size_t base = (size_t)row * D_ + t * 4;
    *(__nv_bfloat162*)(yh + base)     = pack_hi(o0, o1);
    *(__nv_bfloat162*)(yh + base + 2) = pack_hi(o2, o3);
    *(__nv_bfloat162*)(yl + base)     = pack_lo(o0, o1);
    *(__nv_bfloat162*)(yl + base + 2) = pack_lo(o2, o3);
}

// ----------------------------------------------------------------------------
// mma.sync split-bf16 GEMM: C[M,N] = A[M,K] @ W[N,K]^T (+epilogue)
// CTA tile 128x128, warp tile 64x32 (2x4 warps), K-chunk 64, double-buffered
// cp.async. SMEM rows padded to 72 elems (144 B) -> conflict-free ldmatrix.
// EPI: 0 bias; 1 bias+res; 2 sigmoid(gate)*(..)+res
// ----------------------------------------------------------------------------
#define TM 128
#define TN 128
#define KCH 64
#define RS 72                       // padded row stride (bf16 elems)
#define RSB (RS * 2)                // 144 bytes
#define PLANE_B (128 * RSB)         // 18432
#define SA_H 0
#define SA_L PLANE_B
#define SW_H (2 * PLANE_B)
#define SW_L (3 * PLANE_B)
#define STAGE_B (4 * PLANE_B)       // 73728
#define GEMM_SMEM (2 * STAGE_B)     // 147456

template <int EPI>
__global__ __launch_bounds__(256, 1)
void mma_gemm(const __nv_bfloat16* __restrict__ Ah, const __nv_bfloat16* __restrict__ Al,
              const __nv_bfloat16* __restrict__ Wh, const __nv_bfloat16* __restrict__ Wl,
              const float* __restrict__ bias, const float* __restrict__ res,
              const float* __restrict__ gatep, float* __restrict__ C,
              int N, int K, int wRowOff) {
    extern __shared__ char smem[];
    const uint32_t sb = smem_u32(smem);
    const int t = threadIdx.x;
    const int lane = t & 31;
    const int wid = t >> 5;
    const int wm = wid & 1;         // 0..1 (m tile of 64)
    const int wn = wid >> 1;        // 0..3 (n tile of 32)

    const int mBase = blockIdx.y * TM;
    const int nBase = blockIdx.x * TN;

    // ---- load geometry: 4 chunks of 16B per plane per thread ----
    uint32_t sOff[4];
    size_t gOffA[4], gOffW[4];
    #pragma unroll
    for (int j = 0; j < 4; j++) {
        const int id = t + 256 * j;       // 0..1023
        const int r = id >> 3;            // row 0..127
        const int ch = id & 7;            // 16B chunk 0..7
        sOff[j] = (uint32_t)r * RSB + ch * 16;
        gOffA[j] = ((size_t)(mBase + r) * K + ch * 8) * 2;
        gOffW[j] = ((size_t)(nBase + wRowOff + r) * K + ch * 8) * 2;
    }
    const char* pAh = (const char*)Ah;
    const char* pAl = (const char*)Al;
    const char* pWh = (const char*)Wh;
    const char* pWl = (const char*)Wl;

    auto load_stage = [&](int c, int s) {
        const uint32_t sd = sb + s * STAGE_B;
        const size_t kb = (size_t)c * 128;   // 64 bf16 per chunk = 128 B
        #pragma unroll
        for (int j = 0; j < 4; j++) {
            cpa16(sd + SA_H + sOff[j], pAh + gOffA[j] + kb);
            cpa16(sd + SA_L + sOff[j], pAl + gOffA[j] + kb);
            cpa16(sd + SW_H + sOff[j], pWh + gOffW[j] + kb);
            cpa16(sd + SW_L + sOff[j], pWl + gOffW[j] + kb);
        }
    };

    float acc[4][4][4];
    #pragma unroll
    for (int i = 0; i < 4; i++)
        #pragma unroll
        for (int j = 0; j < 4; j++)
            #pragma unroll
            for (int k = 0; k < 4; k++) acc[i][j][k] = 0.f;

    const int nch = K / KCH;
    load_stage(0, 0);
    CP_COMMIT();

    // ldmatrix address templates (within a stage)
    const uint32_t aRowOff = (uint32_t)(wm * 64 + (lane & 15)) * RSB
                           + ((lane >> 4) * 8) * 2;
    const uint32_t bRowOff = (uint32_t)(wn * 32 + (lane & 7) + ((lane >> 4) & 1) * 8) * RSB
                           + (((lane >> 3) & 1) * 8) * 2;

    for (int c = 0; c < nch; c++) {
        if (c + 1 < nch) { load_stage(c + 1, (c + 1) & 1); CP_COMMIT(); }
        if (c + 1 < nch) { CP_WAIT1(); } else { CP_WAIT0(); }
        __syncthreads();

        const uint32_t sd = sb + (c & 1) * STAGE_B;
        #pragma unroll
        for (int kk = 0; kk < KCH; kk += 16) {
            uint32_t ah[4][4], al[4][4];
            #pragma unroll
            for (int mf = 0; mf < 4; mf++) {
                const uint32_t ad = sd + aRowOff + (uint32_t)(mf * 16) * RSB + kk * 2;
                ldm_x4(ah[mf], ad + SA_H);
                ldm_x4(al[mf], ad + SA_L);
            }
            uint32_t bh[4][2], bl[4][2];
            #pragma unroll
            for (int nf2 = 0; nf2 < 2; nf2++) {
                const uint32_t bd = sd + bRowOff + (uint32_t)(nf2 * 16) * RSB + kk * 2;
                uint32_t r[4];
                ldm_x4(r, bd + SW_H);
                bh[nf2 * 2][0] = r[0]; bh[nf2 * 2][1] = r[1];
                bh[nf2 * 2 + 1][0] = r[2]; bh[nf2 * 2 + 1][1] = r[3];
                ldm_x4(r, bd + SW_L);
                bl[nf2 * 2][0] = r[0]; bl[nf2 * 2][1] = r[1];
                bl[nf2 * 2 + 1][0] = r[2]; bl[nf2 * 2 + 1][1] = r[3];
            }
            #pragma unroll
            for (int mf = 0; mf < 4; mf++)
                #pragma unroll
                for (int nf = 0; nf < 4; nf++) {
                    mma_bf16(acc[mf][nf], ah[mf], bh[nf]);
                    mma_bf16(acc[mf][nf], al[mf], bh[nf]);
                    mma_bf16(acc[mf][nf], ah[mf], bl[nf]);
                }
        }
        __syncthreads();
    }

    // ---- epilogue ----
    float gs = 1.f;
    if (EPI == 2) gs = 1.f / (1.f + __expf(-gatep[0]));

    const int mWarp = mBase + wm * 64;
    const int nWarp = nBase + wn * 32;
    #pragma unroll
    for (int mf = 0; mf < 4; mf++) {
        const int r0 = mWarp + mf * 16 + (lane >> 2);
        #pragma unroll
        for (int nf = 0; nf < 4; nf++) {
            const int c0 = nWarp + nf * 8 + 2 * (lane & 3);
            const float b0 = bias[c0], b1 = bias[c0 + 1];
            float v0 = acc[mf][nf][0] + b0;
            float v1 = acc[mf][nf][1] + b1;
            float v2 = acc[mf][nf][2] + b0;
            float v3 = acc[mf][nf][3] + b1;
            if (EPI == 1) {
                v0 += res[(size_t)r0 * N + c0];
                v1 += res[(size_t)r0 * N + c0 + 1];
                v2 += res[(size_t)(r0 + 8) * N + c0];
                v3 += res[(size_t)(r0 + 8) * N + c0 + 1];
            } else if (EPI == 2) {
                v0 = gs * v0 + res[(size_t)r0 * N + c0];
                v1 = gs * v1 + res[(size_t)r0 * N + c0 + 1];
                v2 = gs * v2 + res[(size_t)(r0 + 8) * N + c0];
                v3 = gs * v3 + res[(size_t)(r0 + 8) * N + c0 + 1];
            }
            *(float2*)(C + (size_t)r0 * N + c0) = make_float2(v0, v1);
            *(float2*)(C + (size_t)(r0 + 8) * N + c0) = make_float2(v2, v3);
        }
    }
}

// ----------------------------------------------------------------------------
// Flash attention, fp32 compute, HD=64, 64q x 64k tiles, 256 threads.
// Outputs bf16 hi/lo planes with row stride D_.
// ----------------------------------------------------------------------------
__global__ __launch_bounds__(256)
void flash_kernel(const float* __restrict__ Qb, int ldq,
                  const float* __restrict__ Kb, int ldk,
                  const float* __restrict__ Vb, int ldv,
                  const float* __restrict__ bias,
                  __nv_bfloat16* __restrict__ Oh, __nv_bfloat16* __restrict__ Ol,
                  int Lq, int Lkv) {
    __shared__ float Qt[64][64];
    __shared__ float KP[64][64];
    __shared__ float Vs[64][64];

    const int bh = blockIdx.y;
    const int b = bh >> 4;
    const int h = bh & 15;
    const int q0 = blockIdx.x * 64;
    const int t = threadIdx.x;
    const int tx = t & 15;
    const int ty = t >> 4;

    const int lrow = t >> 2;
    const int lc0 = (t & 3) * 16;

    {
        const float* qrow = Qb + (size_t)(b * Lq + q0 + lrow) * ldq + h * HD_ + lc0;
        #pragma unroll
        for (int c = 0; c < 16; c += 4) {
            const float4 v = *(const float4*)(qrow + c);
            Qt[lc0 + c + 0][lrow] = v.x; Qt[lc0 + c + 1][lrow] = v.y;
            Qt[lc0 + c + 2][lrow] = v.z; Qt[lc0 + c + 3][lrow] = v.w;
        }
    }

    float o[4][4];
    float m[4], l[4];
    #pragma unroll
    for (int i = 0; i < 4; i++) {
        m[i] = -1e30f; l[i] = 0.f;
        #pragma unroll
        for (int j = 0; j < 4; j++) o[i][j] = 0.f;
    }
    const float invs = 0.125f;

    for (int k0 = 0; k0 < Lkv; k0 += 64) {
        __syncthreads();
        {
            const float* krow = Kb + (size_t)(b * Lkv + k0 + lrow) * ldk + h * HD_ + lc0;
            const float* vrow = Vb + (size_t)(b * Lkv + k0 + lrow) * ldv + h * HD_ + lc0;
            #pragma unroll
            for (int c = 0; c < 16; c += 4) {
                const float4 kv = *(const float4*)(krow + c);
                KP[lc0 + c + 0][lrow] = kv.x; KP[lc0 + c + 1][lrow] = kv.y;
                KP[lc0 + c + 2][lrow] = kv.z; KP[lc0 + c + 3][lrow] = kv.w;
                *(float4*)&Vs[lrow][lc0 + c] = *(const float4*)(vrow + c);
            }
        }
        __syncthreads();

        float s[4][4];
        #pragma unroll
        for (int i = 0; i < 4; i++)
            #pragma unroll
            for (int j = 0; j < 4; j++) s[i][j] = 0.f;
        #pragma unroll
        for (int kk = 0; kk < 64; kk++) {
            const float4 qa = *(const float4*)&Qt[kk][ty * 4];
            const float4 kb = *(const float4*)&KP[kk][tx * 4];
            const float qr[4] = {qa.x, qa.y, qa.z, qa.w};
            const float kr[4] = {kb.x, kb.y, kb.z, kb.w};
            #pragma unroll
            for (int i = 0; i < 4; i++)
                #pragma unroll
                for (int j = 0; j < 4; j++) s[i][j] += qr[i] * kr[j];
        }

        if (bias) {
            #pragma unroll
            for (int i = 0; i < 4; i++) {
                const float4 bb = *(const float4*)(bias +
                    ((size_t)bh * Lq + (q0 + ty * 4 + i)) * Lkv + k0 + tx * 4);
                s[i][0] = s[i][0] * invs + bb.x;
                s[i][1] = s[i][1] * invs + bb.y;
                s[i][2] = s[i][2] * invs + bb.z;
                s[i][3] = s[i][3] * invs + bb.w;
            }
        } else {
            #pragma unroll
            for (int i = 0; i < 4; i++)
                #pragma unroll
                for (int j = 0; j < 4; j++) s[i][j] *= invs;
        }

        __syncthreads();

        #pragma unroll
        for (int i = 0; i < 4; i++) {
            float rm = fmaxf(fmaxf(s[i][0], s[i][1]), fmaxf(s[i][2], s[i][3]));
            #pragma unroll
            for (int off = 8; off; off >>= 1)
                rm = fmaxf(rm, __shfl_xor_sync(0xffffffffu, rm, off));
            const float mn = fmaxf(m[i], rm);
            const float sc = __expf(m[i] - mn);
            s[i][0] = __expf(s[i][0] - mn);
            s[i][1] = __expf(s[i][1] - mn);
            s[i][2] = __expf(s[i][2] - mn);
            s[i][3] = __expf(s[i][3] - mn);
            float rs = s[i][0] + s[i][1] + s[i][2] + s[i][3];
            #pragma unroll
            for (int off = 8; off; off >>= 1)
                rs += __shfl_xor_sync(0xffffffffu, rs, off);
            l[i] = l[i] * sc + rs;
            m[i] = mn;
            #pragma unroll
            for (int j = 0; j < 4; j++) o[i][j] *= sc;
        }

        #pragma unroll
        for (int j = 0; j < 4; j++) {
            const float4 pv = make_float4(s[0][j], s[1][j], s[2][j], s[3][j]);
            *(float4*)&KP[tx * 4 + j][ty * 4] = pv;
        }
        __syncthreads();

        #pragma unroll
        for (int kk = 0; kk < 64; kk++) {
            const float4 pa = *(const float4*)&KP[kk][ty * 4];
            const float4 vb = *(const float4*)&Vs[kk][tx * 4];
            const float pr[4] = {pa.x, pa.y, pa.z, pa.w};
            const float vr[4] = {vb.x, vb.y, vb.z, vb.w};
            #pragma unroll
            for (int i = 0; i < 4; i++)
                #pragma unroll
                for (int j = 0; j < 4; j++) o[i][j] += pr[i] * vr[j];
        }
    }

    #pragma unroll
    for (int i = 0; i < 4; i++) {
        const float inv = 1.f / l[i];
        const float o0 = o[i][0] * inv, o1 = o[i][1] * inv;
        const float o2 = o[i][2] * inv, o3 = o[i][3] * inv;
        const size_t base = (size_t)(b * Lq + q0 + ty * 4 + i) * D_ + h * HD_ + tx * 4;
        *(__nv_bfloat162*)(Oh + base)     = pack_hi(o0, o1);
        *(__nv_bfloat162*)(Oh + base + 2) = pack_hi(o2, o3);
        *(__nv_bfloat162*)(Ol + base)     = pack_lo(o0, o1);
        *(__nv_bfloat162*)(Ol + base + 2) = pack_lo(o2, o3);
    }
}

// ----------------------------------------------------------------------------
// GEGLU -> bf16 hi/lo planes
// ----------------------------------------------------------------------------
__device__ __forceinline__ float gelu_exact(float x) {
    return 0.5f * x * (1.0f + erff(x * 0.7071067811865476f));
}

__global__ __launch_bounds__(256)
void geglu_kernel(const float* __restrict__ f, __nv_bfloat16* __restrict__ gh,
                  __nv_bfloat16* __restrict__ gl) {
    const int idx4 = blockIdx.x * blockDim.x + threadIdx.x;
    const int mrow = idx4 >> 10;
    const int j4 = (idx4 & 1023) * 4;
    const float4 val = *(const float4*)(f + (size_t)mrow * (2 * FF_) + j4);
    const float4 gt  = *(const float4*)(f + (size_t)mrow * (2 * FF_) + FF_ + j4);
    const float o0 = val.x * gelu_exact(gt.x);
    const float o1 = val.y * gelu_exact(gt.y);
    const float o2 = val.z * gelu_exact(gt.z);
    const float o3 = val.w * gelu_exact(gt.w);
    const size_t base = (size_t)mrow * FF_ + j4;
    *(__nv_bfloat162*)(gh + base)     = pack_hi(o0, o1);
    *(__nv_bfloat162*)(gh + base + 2) = pack_hi(o2, o3);
    *(__nv_bfloat162*)(gl + base)     = pack_lo(o0, o1);
    *(__nv_bfloat162*)(gl + base + 2) = pack_lo(o2, o3);
}

// ----------------------------------------------------------------------------
// Host orchestration
// ----------------------------------------------------------------------------
extern "C" void kernel_launch(void* const* d_in, const int* in_sizes, int n_in,
                              void* d_out, int out_size) {
    const float* x          = (const float*)d_in[0];
    const float* alibi      = (const float*)d_in[1];
    const float* species    = (const float*)d_in[2];
    const float* norm1_g    = (const float*)d_in[3];
    const float* norm1_b    = (const float*)d_in[4];
    const float* sa_wqkv    = (const float*)d_in[5];
    const float* sa_bqkv    = (const float*)d_in[6];
    const float* sa_wo      = (const float*)d_in[7];
    const float* sa_bo      = (const float*)d_in[8];
    const float* ca_nq_g    = (const float*)d_in[9];
    const float* ca_nq_b    = (const float*)d_in[10];
    const float* ca_nkv_g   = (const float*)d_in[11];
    const float* ca_nkv_b   = (const float*)d_in[12];
    const float* ca_wqkv    = (const float*)d_in[13];
    const float* ca_bqkv    = (const float*)d_in[14];
    const float* ca_wo      = (const float*)d_in[15];
    const float* ca_bo      = (const float*)d_in[16];
    const float* gate_param = (const float*)d_in[17];
    const float* ffn_g      = (const float*)d_in[18];
    const float* ffn_b      = (const float*)d_in[19];
    const float* ffn_w1     = (const float*)d_in[20];
    const float* ffn_b1     = (const float*)d_in[21];
    const float* ffn_w2     = (const float*)d_in[22];
    const float* ffn_b2     = (const float*)d_in[23];
    float* out = (float*)d_out;

    char* S = nullptr;
    cudaGetSymbolAddress((void**)&S, g_scratch);
    #define BF(off) ((__nv_bfloat16*)(S + (off)))
    #define F32(off) ((float*)(S + (off)))
    __nv_bfloat16 *wqkvs_h = BF(O_WQKVS_H), *wqkvs_l = BF(O_WQKVS_L);
    __nv_bfloat16 *wsao_h = BF(O_WSAO_H), *wsao_l = BF(O_WSAO_L);
    __nv_bfloat16 *wqkvc_h = BF(O_WQKVC_H), *wqkvc_l = BF(O_WQKVC_L);
    __nv_bfloat16 *wcao_h = BF(O_WCAO_H), *wcao_l = BF(O_WCAO_L);
    __nv_bfloat16 *wf1_h = BF(O_WF1_H), *wf1_l = BF(O_WF1_L);
    __nv_bfloat16 *wf2_h = BF(O_WF2_H), *wf2_l = BF(O_WF2_L);
    __nv_bfloat16 *ln_h = BF(O_LN_H), *ln_l = BF(O_LN_L);
    __nv_bfloat16 *at_h = BF(O_AT_H), *at_l = BF(O_AT_L);
    __nv_bfloat16 *kvn_h = BF(O_KVN_H), *kvn_l = BF(O_KVN_L);
    __nv_bfloat16 *gg_h = BF(O_GG_H), *gg_l = BF(O_GG_L);
    float *qkv = F32(O_QKV), *cq = F32(O_CQ), *ckv = F32(O_CKV);
    float *x1 = F32(O_X1), *x2 = F32(O_X2), *f = F32(O_F);

    cudaFuncSetAttribute(mma_gemm<0>, cudaFuncAttributeMaxDynamicSharedMemorySize, GEMM_SMEM);
    cudaFuncSetAttribute(mma_gemm<1>, cudaFuncAttributeMaxDynamicSharedMemorySize, GEMM_SMEM);
    cudaFuncSetAttribute(mma_gemm<2>, cudaFuncAttributeMaxDynamicSharedMemorySize, GEMM_SMEM);

    // ---- weight split ----
    auto cvt = [&](const float* w, __nv_bfloat16* h, __nv_bfloat16* l, int n) {
        cvt_split_kernel<<<(n / 4 + 255) / 256, 256>>>(
            (const float4*)w, (__nv_bfloat162*)h, (__nv_bfloat162*)l, n / 4);
    };
    cvt(sa_wqkv, wqkvs_h, wqkvs_l, 3 * D_ * D_);
    cvt(sa_wo,   wsao_h,  wsao_l,  D_ * D_);
    cvt(ca_wqkv, wqkvc_h, wqkvc_l, 3 * D_ * D_);
    cvt(ca_wo,   wcao_h,  wcao_l,  D_ * D_);
    cvt(ffn_w1,  wf1_h,   wf1_l,   2 * FF_ * D_);
    cvt(ffn_w2,  wf2_h,   wf2_l,   D_ * FF_);

    // ---- Self-attention ----
    ln_kernel<<<M_, 256>>>(x, norm1_g, norm1_b, ln_h, ln_l);
    mma_gemm<0><<<dim3(3 * D_ / TN, M_ / TM), 256, GEMM_SMEM>>>(
        ln_h, ln_l, wqkvs_h, wqkvs_l, sa_bqkv, nullptr, nullptr, qkv, 3 * D_, D_, 0);
    flash_kernel<<<dim3(L_ / 64, B_ * H_), 256>>>(
        qkv, 3 * D_, qkv + D_, 3 * D_, qkv + 2 * D_, 3 * D_, alibi, at_h, at_l, L_, L_);
    mma_gemm<1><<<dim3(D_ / TN, M_ / TM), 256, GEMM_SMEM>>>(
        at_h, at_l, wsao_h, wsao_l, sa_bo, x, nullptr, x1, D_, D_, 0);

    // ---- Cross-attention ----
    ln_kernel<<<M_, 256>>>(x1, ca_nq_g, ca_nq_b, ln_h, ln_l);
    ln_kernel<<<B_ * NS_, 256>>>(species, ca_nkv_g, ca_nkv_b, kvn_h, kvn_l);
    mma_gemm<0><<<dim3(D_ / TN, M_ / TM), 256, GEMM_SMEM>>>(
        ln_h, ln_l, wqkvc_h, wqkvc_l, ca_bqkv, nullptr, nullptr, cq, D_, D_, 0);
    mma_gemm<0><<<dim3(2 * D_ / TN, (B_ * NS_) / TM), 256, GEMM_SMEM>>>(
        kvn_h, kvn_l, wqkvc_h, wqkvc_l, ca_bqkv + D_, nullptr, nullptr,
        ckv, 2 * D_, D_, D_);
    flash_kernel<<<dim3(L_ / 64, B_ * H_), 256>>>(
        cq, D_, ckv, 2 * D_, ckv + D_, 2 * D_, nullptr, at_h, at_l, L_, NS_);
    mma_gemm<2><<<dim3(D_ / TN, M_ / TM), 256, GEMM_SMEM>>>(
        at_h, at_l, wcao_h, wcao_l, ca_bo, x1, gate_param, x2, D_, D_, 0);

    // ---- FFN (GEGLU) ----
    ln_kernel<<<M_, 256>>>(x2, ffn_g, ffn_b, ln_h, ln_l);
    mma_gemm<0><<<dim3(2 * FF_ / TN, M_ / TM), 256, GEMM_SMEM>>>(
        ln_h, ln_l, wf1_h, wf1_l, ffn_b1, nullptr, nullptr, f, 2 * FF_, D_, 0);
    geglu_kernel<<<(M_ * FF_ / 4) / 256, 256>>>(f, gg_h, gg_l);
    mma_gemm<1><<<dim3(D_ / TN, M_ / TM), 256, GEMM_SMEM>>>(
        gg_h, gg_l, wf2_h, wf2_l, ffn_b2, x2, nullptr, out, D_, FF_, 0);
}

// round 8
// speedup vs baseline: 2.8197x; 1.2047x over previous
#include <cuda_runtime.h>
#include <cuda_bf16.h>
#include <math.h>
#include <stdint.h>

// ----------------------------------------------------------------------------
// Shapes (fixed)
// ----------------------------------------------------------------------------
#define B_   4
#define L_   1024
#define D_   1024
#define H_   16
#define HD_  64
#define FF_  4096
#define NS_  64
#define M_   (B_ * L_)          // 4096 rows

// ----------------------------------------------------------------------------
// Scratch (bytes), all offsets 1024-aligned
// ----------------------------------------------------------------------------
#define SZ_WQKV   (3072ull*1024u*2u)
#define SZ_WO     (1024ull*1024u*2u)
#define SZ_WF1    (8192ull*1024u*2u)
#define SZ_WF2    (1024ull*4096u*2u)
#define SZ_ACT    (4096ull*1024u*2u)
#define SZ_KVN    (256ull*1024u*2u)
#define SZ_GG     (4096ull*4096u*2u)
#define SZ_QKVP   (4096ull*3072u*2u)
#define SZ_CQ     (4096ull*1024u*2u)
#define SZ_CKVP   (256ull*2048u*2u)
#define SZ_D32    (4096ull*1024u*4u)

#define O_WQKVS_H   0ull
#define O_WQKVS_L   (O_WQKVS_H + SZ_WQKV)
#define O_WSAO_H    (O_WQKVS_L + SZ_WQKV)
#define O_WSAO_L    (O_WSAO_H + SZ_WO)
#define O_WQKVC_H   (O_WSAO_L + SZ_WO)
#define O_WQKVC_L   (O_WQKVC_H + SZ_WQKV)
#define O_WCAO_H    (O_WQKVC_L + SZ_WQKV)
#define O_WCAO_L    (O_WCAO_H + SZ_WO)
#define O_WF1_H     (O_WCAO_L + SZ_WO)
#define O_WF1_L     (O_WF1_H + SZ_WF1)
#define O_WF2_H     (O_WF1_L + SZ_WF1)
#define O_WF2_L     (O_WF2_H + SZ_WF2)
#define O_LN_H      (O_WF2_L + SZ_WF2)
#define O_LN_L      (O_LN_H + SZ_ACT)
#define O_AT_H      (O_LN_L + SZ_ACT)
#define O_AT_L      (O_AT_H + SZ_ACT)
#define O_KVN_H     (O_AT_L + SZ_ACT)
#define O_KVN_L     (O_KVN_H + SZ_KVN)
#define O_GG_H      (O_KVN_L + SZ_KVN)
#define O_GG_L      (O_GG_H + SZ_GG)
#define O_QKV_H     (O_GG_L + SZ_GG)
#define O_QKV_L     (O_QKV_H + SZ_QKVP)
#define O_CQ_H      (O_QKV_L + SZ_QKVP)
#define O_CQ_L      (O_CQ_H + SZ_CQ)
#define O_CKV_H     (O_CQ_L + SZ_CQ)
#define O_CKV_L     (O_CKV_H + SZ_CKVP)
#define O_X1        (O_CKV_L + SZ_CKVP)
#define O_X2        (O_X1 + SZ_D32)
#define SCRATCH_BYTES (O_X2 + SZ_D32)

__device__ __align__(1024) char g_scratch[SCRATCH_BYTES];

// ----------------------------------------------------------------------------
// PTX helpers (family-agnostic: ldmatrix / mma.sync / cp.async only)
// ----------------------------------------------------------------------------
__device__ __forceinline__ uint32_t smem_u32(const void* p) {
    uint32_t a;
    asm("{ .reg .u64 t; cvta.to.shared.u64 t, %1; cvt.u32.u64 %0, t; }"
        : "=r"(a) : "l"(p));
    return a;
}
__device__ __forceinline__ void cpa16(uint32_t s, const void* g) {
    asm volatile("cp.async.cg.shared.global [%0], [%1], 16;" :: "r"(s), "l"(g));
}
#define CP_COMMIT() asm volatile("cp.async.commit_group;" ::: "memory")
#define CP_WAIT0() asm volatile("cp.async.wait_group 0;" ::: "memory")
#define CP_WAIT1() asm volatile("cp.async.wait_group 1;" ::: "memory")

__device__ __forceinline__ void ldm_x4(uint32_t* r, uint32_t addr) {
    asm volatile("ldmatrix.sync.aligned.m8n8.x4.shared.b16 {%0,%1,%2,%3}, [%4];"
        : "=r"(r[0]), "=r"(r[1]), "=r"(r[2]), "=r"(r[3]) : "r"(addr));
}
__device__ __forceinline__ void ldm_x4_t(uint32_t* r, uint32_t addr) {
    asm volatile("ldmatrix.sync.aligned.m8n8.x4.trans.shared.b16 {%0,%1,%2,%3}, [%4];"
        : "=r"(r[0]), "=r"(r[1]), "=r"(r[2]), "=r"(r[3]) : "r"(addr));
}
__device__ __forceinline__ void mma_bf16(float* d, const uint32_t* a, const uint32_t* b) {
    asm volatile(
        "mma.sync.aligned.m16n8k16.row.col.f32.bf16.bf16.f32 "
        "{%0,%1,%2,%3}, {%4,%5,%6,%7}, {%8,%9}, {%0,%1,%2,%3};"
        : "+f"(d[0]), "+f"(d[1]), "+f"(d[2]), "+f"(d[3])
        : "r"(a[0]), "r"(a[1]), "r"(a[2]), "r"(a[3]), "r"(b[0]), "r"(b[1]));
}

__device__ __forceinline__ __nv_bfloat162 pack_hi(float a, float b) {
    return __halves2bfloat162(__float2bfloat16(a), __float2bfloat16(b));
}
__device__ __forceinline__ __nv_bfloat162 pack_lo(float a, float b) {
    __nv_bfloat16 ha = __float2bfloat16(a), hb = __float2bfloat16(b);
    return __halves2bfloat162(__float2bfloat16(a - __bfloat162float(ha)),
                              __float2bfloat16(b - __bfloat162float(hb)));
}
__device__ __forceinline__ uint32_t packu_hi(float a, float b) {
    __nv_bfloat162 v = pack_hi(a, b);
    return *(uint32_t*)&v;
}
__device__ __forceinline__ uint32_t packu_lo(float a, float b) {
    __nv_bfloat162 v = pack_lo(a, b);
    return *(uint32_t*)&v;
}

// Fast exp on FFMA pipe: exp2 range reduction + degree-5 Taylor (rel err ~2e-6).
// Valid for x <= 0 (softmax path).
__device__ __forceinline__ float fexp(float x) {
    float z = x * 1.4426950408889634f;
    z = fmaxf(z, -120.0f);
    float zi = z + 12582912.0f;                     // round-to-nearest int
    int i = __float_as_int(zi) - 0x4B400000;
    float f = z - (zi - 12582912.0f);               // f in [-0.5, 0.5]
    float p = 1.3333558e-3f;
    p = fmaf(p, f, 9.6181291e-3f);
    p = fmaf(p, f, 5.5504109e-2f);
    p = fmaf(p, f, 2.4022651e-1f);
    p = fmaf(p, f, 6.9314718e-1f);
    p = fmaf(p, f, 1.0f);
    return p * __int_as_float((i + 127) << 23);
}

// ----------------------------------------------------------------------------
// Weight split: fp32 -> bf16 hi/lo planes
// ----------------------------------------------------------------------------
__global__ __launch_bounds__(256)
void cvt_split_kernel(const float4* __restrict__ w, __nv_bfloat162* __restrict__ hi,
                      __nv_bfloat162* __restrict__ lo, int n4) {
    int i = blockIdx.x * 256 + threadIdx.x;
    if (i >= n4) return;
    const float4 v = w[i];
    hi[i * 2]     = pack_hi(v.x, v.y);
    hi[i * 2 + 1] = pack_hi(v.z, v.w);
    lo[i * 2]     = pack_lo(v.x, v.y);
    lo[i * 2 + 1] = pack_lo(v.z, v.w);
}

// ffn_w1 interleave: out row 2j = w1[j] (val), row 2j+1 = w1[FF+j] (gate)
__global__ __launch_bounds__(256)
void cvt_split_ileave_kernel(const float* __restrict__ w, __nv_bfloat162* __restrict__ hi,
                             __nv_bfloat162* __restrict__ lo, int n4) {
    int i = blockIdx.x * 256 + threadIdx.x;   // over dst float4 units, K=1024
    if (i >= n4) return;
    const int row = i >> 8;                   // dst row (0..8191)
    const int col4 = (i & 255) * 4;
    const int srow = (row & 1) ? (FF_ + (row >> 1)) : (row >> 1);
    const float4 v = *(const float4*)(w + (size_t)srow * 1024 + col4);
    hi[i * 2]     = pack_hi(v.x, v.y);
    hi[i * 2 + 1] = pack_hi(v.z, v.w);
    lo[i * 2]     = pack_lo(v.x, v.y);
    lo[i * 2 + 1] = pack_lo(v.z, v.w);
}

// ----------------------------------------------------------------------------
// LayerNorm: one block per row, 256 threads, D=1024; outputs bf16 hi/lo planes
// ----------------------------------------------------------------------------
__global__ __launch_bounds__(256)
void ln_kernel(const float* __restrict__ x, const float* __restrict__ g,
               const float* __restrict__ b, __nv_bfloat16* __restrict__ yh,
               __nv_bfloat16* __restrict__ yl) {
    const int row = blockIdx.x;
    const int t = threadIdx.x;
    const float4 v = ((const float4*)(x + (size_t)row * D_))[t];

    __shared__ float red[8];
    __shared__ float stat[2];

    float s = v.x + v.y + v.z + v.w;
    #pragma unroll
    for (int o = 16; o; o >>= 1) s += __shfl_xor_sync(0xffffffffu, s, o);
    if ((t & 31) == 0) red[t >> 5] = s;
    __syncthreads();
    if (t == 0) {
        float s2 = 0.f;
        #pragma unroll
        for (int i = 0; i < 8; i++) s2 += red[i];
        stat[0] = s2 * (1.0f / D_);
    }
    __syncthreads();
    const float mu = stat[0];
    const float dx = v.x - mu, dy = v.y - mu, dz = v.z - mu, dw = v.w - mu;

    float q = dx * dx + dy * dy + dz * dz + dw * dw;
    #pragma unroll
    for (int o = 16; o; o >>= 1) q += __shfl_xor_sync(0xffffffffu, q, o);
    if ((t & 31) == 0) red[t >> 5] = q;
    __syncthreads();
    if (t == 0) {
        float s2 = 0.f;
        #pragma unroll
        for (int i = 0; i < 8; i++) s2 += red[i];
        stat[1] = rsqrtf(s2 * (1.0f / D_) + 1e-5f);
    }
    __syncthreads();
    const float rs = stat[1];

    const float4 gv = ((const float4*)g)[t];
    const float4 bv = ((const float4*)b)[t];
    float o0 = dx * rs * gv.x + bv.x;
    float o1 = dy * rs * gv.y + bv.y;
    float o2 = dz * rs * gv.z + bv.z;
    float o3 = dw * rs * gv.w + bv.w;
    const size_t base = (size_t)row * D_ + t * 4;
    *(__nv_bfloat162*)(yh + base)     = pack_hi(o0, o1);
    *(__nv_bfloat162*)(yh + base + 2) = pack_hi(o2, o3);
    *(__nv_bfloat162*)(yl + base)     = pack_lo(o0, o1);
    *(__nv_bfloat162*)(yl + base + 2) = pack_lo(o2, o3);
}

__device__ __forceinline__ float gelu_exact(float x) {
    return 0.5f * x * (1.0f + erff(x * 0.7071067811865476f));
}

// ----------------------------------------------------------------------------
// mma.sync split-bf16 GEMM: C[M,N] = A[M,K] @ W[N,K]^T (+epilogue)
// CTA tile 128x128, warp tile 64x32 (2x4 warps), K-chunk 64, double-buffered.
// EPI: 1 bias+res (fp32 out); 2 sigmoid(gate)*(..)+res (fp32 out);
//      3 bias only -> bf16 hi/lo planes; 4 GEGLU (interleaved W) -> bf16 planes
// ----------------------------------------------------------------------------
#define TM 128
#define TN 128
#define KCH 64
#define RS 72
#define RSB (RS * 2)
#define PLANE_B (128 * RSB)
#define SA_H 0
#define SA_L PLANE_B
#define SW_H (2 * PLANE_B)
#define SW_L (3 * PLANE_B)
#define STAGE_B (4 * PLANE_B)
#define GEMM_SMEM (2 * STAGE_B)

template <int EPI>
__global__ __launch_bounds__(256, 1)
void mma_gemm(const __nv_bfloat16* __restrict__ Ah, const __nv_bfloat16* __restrict__ Al,
              const __nv_bfloat16* __restrict__ Wh, const __nv_bfloat16* __restrict__ Wl,
              const float* __restrict__ bias, const float* __restrict__ res,
              const float* __restrict__ gatep, float* __restrict__ C,
              __nv_bfloat16* __restrict__ Ch, __nv_bfloat16* __restrict__ Cl,
              int N, int K, int wRowOff) {
    extern __shared__ char smem[];
    const uint32_t sb = smem_u32(smem);
    const int t = threadIdx.x;
    const int lane = t & 31;
    const int wid = t >> 5;
    const int wm = wid & 1;
    const int wn = wid >> 1;

    const int mBase = blockIdx.y * TM;
    const int nBase = blockIdx.x * TN;

    uint32_t sOff[4];
    size_t gOffA[4], gOffW[4];
    #pragma unroll
    for (int j = 0; j < 4; j++) {
        const int id = t + 256 * j;
        const int r = id >> 3;
        const int ch = id & 7;
        sOff[j] = (uint32_t)r * RSB + ch * 16;
        gOffA[j] = ((size_t)(mBase + r) * K + ch * 8) * 2;
        gOffW[j] = ((size_t)(nBase + wRowOff + r) * K + ch * 8) * 2;
    }
    const char* pAh = (const char*)Ah;
    const char* pAl = (const char*)Al;
    const char* pWh = (const char*)Wh;
    const char* pWl = (const char*)Wl;

    auto load_stage = [&](int c, int s) {
        const uint32_t sd = sb + s * STAGE_B;
        const size_t kb = (size_t)c * 128;
        #pragma unroll
        for (int j = 0; j < 4; j++) {
            cpa16(sd + SA_H + sOff[j], pAh + gOffA[j] + kb);
            cpa16(sd + SA_L + sOff[j], pAl + gOffA[j] + kb);
            cpa16(sd + SW_H + sOff[j], pWh + gOffW[j] + kb);
            cpa16(sd + SW_L + sOff[j], pWl + gOffW[j] + kb);
        }
    };

    float acc[4][4][4];
    #pragma unroll
    for (int i = 0; i < 4; i++)
        #pragma unroll
        for (int j = 0; j < 4; j++)
            #pragma unroll
            for (int k = 0; k < 4; k++) acc[i][j][k] = 0.f;

    const int nch = K / KCH;
    load_stage(0, 0);
    CP_COMMIT();

    const uint32_t aRowOff = (uint32_t)(wm * 64 + (lane & 15)) * RSB
                           + ((lane >> 4) * 8) * 2;
    const uint32_t bRowOff = (uint32_t)(wn * 32 + (lane & 7) + ((lane >> 4) & 1) * 8) * RSB
                           + (((lane >> 3) & 1) * 8) * 2;

    for (int c = 0; c < nch; c++) {
        if (c + 1 < nch) { load_stage(c + 1, (c + 1) & 1); CP_COMMIT(); }
        if (c + 1 < nch) { CP_WAIT1(); } else { CP_WAIT0(); }
        __syncthreads();

        const uint32_t sd = sb + (c & 1) * STAGE_B;
        #pragma unroll
        for (int kk = 0; kk < KCH; kk += 16) {
            uint32_t ah[4][4], al[4][4];
            #pragma unroll
            for (int mf = 0; mf < 4; mf++) {
                const uint32_t ad = sd + aRowOff + (uint32_t)(mf * 16) * RSB + kk * 2;
                ldm_x4(ah[mf], ad + SA_H);
                ldm_x4(al[mf], ad + SA_L);
            }
            uint32_t bh[4][2], bl[4][2];
            #pragma unroll
            for (int nf2 = 0; nf2 < 2; nf2++) {
                const uint32_t bd = sd + bRowOff + (uint32_t)(nf2 * 16) * RSB + kk * 2;
                uint32_t r[4];
                ldm_x4(r, bd + SW_H);
                bh[nf2 * 2][0] = r[0]; bh[nf2 * 2][1] = r[1];
                bh[nf2 * 2 + 1][0] = r[2]; bh[nf2 * 2 + 1][1] = r[3];
                ldm_x4(r, bd + SW_L);
                bl[nf2 * 2][0] = r[0]; bl[nf2 * 2][1] = r[1];
                bl[nf2 * 2 + 1][0] = r[2]; bl[nf2 * 2 + 1][1] = r[3];
            }
            #pragma unroll
            for (int mf = 0; mf < 4; mf++)
                #pragma unroll
                for (int nf = 0; nf < 4; nf++) {
                    mma_bf16(acc[mf][nf], ah[mf], bh[nf]);
                    mma_bf16(acc[mf][nf], al[mf], bh[nf]);
                    mma_bf16(acc[mf][nf], ah[mf], bl[nf]);
                }
        }
        __syncthreads();
    }

    // ---- epilogue ----
    float gs = 1.f;
    if (EPI == 2) gs = 1.f / (1.f + __expf(-gatep[0]));

    const int mWarp = mBase + wm * 64;
    const int nWarp = nBase + wn * 32;
    #pragma unroll
    for (int mf = 0; mf < 4; mf++) {
        const int r0 = mWarp + mf * 16 + (lane >> 2);
        #pragma unroll
        for (int nf = 0; nf < 4; nf++) {
            const int c0 = nWarp + nf * 8 + 2 * (lane & 3);
            if (EPI == 1 || EPI == 2) {
                const float b0 = bias[c0], b1 = bias[c0 + 1];
                float v0 = acc[mf][nf][0] + b0;
                float v1 = acc[mf][nf][1] + b1;
                float v2 = acc[mf][nf][2] + b0;
                float v3 = acc[mf][nf][3] + b1;
                if (EPI == 1) {
                    v0 += res[(size_t)r0 * N + c0];
                    v1 += res[(size_t)r0 * N + c0 + 1];
                    v2 += res[(size_t)(r0 + 8) * N + c0];
                    v3 += res[(size_t)(r0 + 8) * N + c0 + 1];
                } else {
                    v0 = gs * v0 + res[(size_t)r0 * N + c0];
                    v1 = gs * v1 + res[(size_t)r0 * N + c0 + 1];
                    v2 = gs * v2 + res[(size_t)(r0 + 8) * N + c0];
                    v3 = gs * v3 + res[(size_t)(r0 + 8) * N + c0 + 1];
                }
                *(float2*)(C + (size_t)r0 * N + c0) = make_float2(v0, v1);
                *(float2*)(C + (size_t)(r0 + 8) * N + c0) = make_float2(v2, v3);
            } else if (EPI == 3) {
                const float b0 = bias[c0], b1 = bias[c0 + 1];
                const float v0 = acc[mf][nf][0] + b0;
                const float v1 = acc[mf][nf][1] + b1;
                const float v2 = acc[mf][nf][2] + b0;
                const float v3 = acc[mf][nf][3] + b1;
                *(__nv_bfloat162*)(Ch + (size_t)r0 * N + c0) = pack_hi(v0, v1);
                *(__nv_bfloat162*)(Cl + (size_t)r0 * N + c0) = pack_lo(v0, v1);
                *(__nv_bfloat162*)(Ch + (size_t)(r0 + 8) * N + c0) = pack_hi(v2, v3);
                *(__nv_bfloat162*)(Cl + (size_t)(r0 + 8) * N + c0) = pack_lo(v2, v3);
            } else {  // EPI == 4: GEGLU with interleaved W (even=val, odd=gate)
                const int jj = c0 >> 1;
                const int Nout = N >> 1;
                const float bv = bias[jj], bg = bias[FF_ + jj];
                const float va = acc[mf][nf][0] + bv;
                const float ga = acc[mf][nf][1] + bg;
                const float vb = acc[mf][nf][2] + bv;
                const float gb = acc[mf][nf][3] + bg;
                const float oa = va * gelu_exact(ga);
                const float ob = vb * gelu_exact(gb);
                const __nv_bfloat16 ha = __float2bfloat16(oa);
                const __nv_bfloat16 hb = __float2bfloat16(ob);
                Ch[(size_t)r0 * Nout + jj] = ha;
                Cl[(size_t)r0 * Nout + jj] = __float2bfloat16(oa - __bfloat162float(ha));
                Ch[(size_t)(r0 + 8) * Nout + jj] = hb;
                Cl[(size_t)(r0 + 8) * Nout + jj] = __float2bfloat16(ob - __bfloat162float(hb));
            }
        }
    }
}

// ----------------------------------------------------------------------------
// Tensor-core flash attention (split bf16), HD=64, 64q x 64kv tiles.
// 128 threads (4 warps); warp w owns q rows [16w,16w+16).
// Q/K/V given as bf16 hi/lo planes. Output bf16 hi/lo planes, row stride D_.
// ----------------------------------------------------------------------------
#define FRSB 144
#define FPLANE (64 * FRSB)            // 9216
#define FSTAGE (4 * FPLANE)           // 36864 (KH, KL, VH, VL)
#define FQOFF  (2 * FSTAGE)           // 73728 (QH, QL)
#define FLASH_SMEM (FQOFF + 2 * FPLANE)  // 92160

__global__ __launch_bounds__(128)
void flash_mma(const __nv_bfloat16* __restrict__ Qh, const __nv_bfloat16* __restrict__ Ql,
               int ldq,
               const __nv_bfloat16* __restrict__ Kh, const __nv_bfloat16* __restrict__ Kl,
               int ldk,
               const __nv_bfloat16* __restrict__ Vh, const __nv_bfloat16* __restrict__ Vl,
               const float* __restrict__ bias,
               __nv_bfloat16* __restrict__ Oh, __nv_bfloat16* __restrict__ Ol,
               int Lq, int Lkv) {
    extern __shared__ char smem[];
    const uint32_t sb = smem_u32(smem);
    const int t = threadIdx.x, lane = t & 31, w = t >> 5;
    const int bh = blockIdx.y, b = bh >> 4, h = bh & 15;
    const int q0 = blockIdx.x * 64;

    // Q tile -> smem (its own commit group)
    #pragma unroll
    for (int j = 0; j < 4; j++) {
        const int id = t + 128 * j, r = id >> 3, ch = id & 7;
        const size_t g = ((size_t)(b * Lq + q0 + r)) * ldq + h * 64 + ch * 8;
        const uint32_t so = sb + FQOFF + (uint32_t)r * FRSB + ch * 16;
        cpa16(so, (const char*)Qh + g * 2);
        cpa16(so + FPLANE, (const char*)Ql + g * 2);
    }
    CP_COMMIT();

    auto load_kv = [&](int it, int s) {
        const uint32_t sd = sb + s * FSTAGE;
        const int k0 = it * 64;
        #pragma unroll
        for (int j = 0; j < 4; j++) {
            const int id = t + 128 * j, r = id >> 3, ch = id & 7;
            const size_t g = ((size_t)(b * Lkv + k0 + r)) * ldk + h * 64 + ch * 8;
            const uint32_t so = sd + (uint32_t)r * FRSB + ch * 16;
            cpa16(so,              (const char*)Kh + g * 2);
            cpa16(so + FPLANE,     (const char*)Kl + g * 2);
            cpa16(so + 2 * FPLANE, (const char*)Vh + g * 2);
            cpa16(so + 3 * FPLANE, (const char*)Vl + g * 2);
        }
    };
    load_kv(0, 0); CP_COMMIT();

    uint32_t qfh[4][4], qfl[4][4];
    float o_[8][4];
    #pragma unroll
    for (int i = 0; i < 8; i++)
        #pragma unroll
        for (int j = 0; j < 4; j++) o_[i][j] = 0.f;
    float m0 = -1e30f, m1 = -1e30f, l0 = 0.f, l1 = 0.f;
    const float invs = 0.125f;

    const int nt = Lkv / 64;
    for (int it = 0; it < nt; it++) {
        if (it + 1 < nt) { load_kv(it + 1, (it + 1) & 1); CP_COMMIT(); CP_WAIT1(); }
        else { CP_WAIT0(); }
        __syncthreads();
        const uint32_t sd = sb + (it & 1) * FSTAGE;

        if (it == 0) {
            #pragma unroll
            for (int kf = 0; kf < 4; kf++) {
                const uint32_t qa = sb + FQOFF
                    + (uint32_t)(w * 16 + (lane & 15)) * FRSB
                    + ((lane >> 4) * 8 + kf * 16) * 2;
                ldm_x4(qfh[kf], qa);
                ldm_x4(qfl[kf], qa + FPLANE);
            }
        }

        // ---- S = Q K^T (split) ----
        float s_[8][4];
        #pragma unroll
        for (int i = 0; i < 8; i++)
            #pragma unroll
            for (int j = 0; j < 4; j++) s_[i][j] = 0.f;
        #pragma unroll
        for (int kf = 0; kf < 4; kf++) {
            #pragma unroll
            for (int g = 0; g < 4; g++) {
                const uint32_t ka = sd
                    + (uint32_t)(g * 16 + (lane & 7) + ((lane >> 4) & 1) * 8) * FRSB
                    + (((lane >> 3) & 1) * 8 + kf * 16) * 2;
                uint32_t rh[4], rl[4];
                ldm_x4(rh, ka);
                ldm_x4(rl, ka + FPLANE);
                mma_bf16(s_[2 * g],     qfh[kf], rh);
                mma_bf16(s_[2 * g],     qfl[kf], rh);
                mma_bf16(s_[2 * g],     qfh[kf], rl);
                mma_bf16(s_[2 * g + 1], qfh[kf], rh + 2);
                mma_bf16(s_[2 * g + 1], qfl[kf], rh + 2);
                mma_bf16(s_[2 * g + 1], qfh[kf], rl + 2);
            }
        }

        // ---- scale + bias ----
        if (bias) {
            const int k0 = it * 64;
            const float* bp = bias
                + ((size_t)bh * Lq + (q0 + w * 16 + (lane >> 2))) * Lkv
                + k0 + (lane & 3) * 2;
            #pragma unroll
            for (int nf = 0; nf < 8; nf++) {
                const float2 b0 = *(const float2*)(bp + nf * 8);
                const float2 b1 = *(const float2*)(bp + (size_t)8 * Lkv + nf * 8);
                s_[nf][0] = fmaf(s_[nf][0], invs, b0.x);
                s_[nf][1] = fmaf(s_[nf][1], invs, b0.y);
                s_[nf][2] = fmaf(s_[nf][2], invs, b1.x);
                s_[nf][3] = fmaf(s_[nf][3], invs, b1.y);
            }
        } else {
            #pragma unroll
            for (int nf = 0; nf < 8; nf++)
                #pragma unroll
                for (int i = 0; i < 4; i++) s_[nf][i] *= invs;
        }

        // ---- online softmax (rows gr=lane>>2 and gr+8) ----
        float mx0 = s_[0][0], mx1 = s_[0][2];
        #pragma unroll
        for (int nf = 0; nf < 8; nf++) {
            mx0 = fmaxf(mx0, fmaxf(s_[nf][0], s_[nf][1]));
            mx1 = fmaxf(mx1, fmaxf(s_[nf][2], s_[nf][3]));
        }
        mx0 = fmaxf(mx0, __shfl_xor_sync(0xffffffffu, mx0, 1));
        mx0 = fmaxf(mx0, __shfl_xor_sync(0xffffffffu, mx0, 2));
        mx1 = fmaxf(mx1, __shfl_xor_sync(0xffffffffu, mx1, 1));
        mx1 = fmaxf(mx1, __shfl_xor_sync(0xffffffffu, mx1, 2));
        const float mn0 = fmaxf(m0, mx0), mn1 = fmaxf(m1, mx1);
        const float sc0 = fexp(m0 - mn0), sc1 = fexp(m1 - mn1);
        m0 = mn0; m1 = mn1;
        float sum0 = 0.f, sum1 = 0.f;
        #pragma unroll
        for (int nf = 0; nf < 8; nf++) {
            s_[nf][0] = fexp(s_[nf][0] - mn0);
            s_[nf][1] = fexp(s_[nf][1] - mn0);
            s_[nf][2] = fexp(s_[nf][2] - mn1);
            s_[nf][3] = fexp(s_[nf][3] - mn1);
            sum0 += s_[nf][0] + s_[nf][1];
            sum1 += s_[nf][2] + s_[nf][3];
        }
        sum0 += __shfl_xor_sync(0xffffffffu, sum0, 1);
        sum0 += __shfl_xor_sync(0xffffffffu, sum0, 2);
        sum1 += __shfl_xor_sync(0xffffffffu, sum1, 1);
        sum1 += __shfl_xor_sync(0xffffffffu, sum1, 2);
        l0 = l0 * sc0 + sum0;
        l1 = l1 * sc1 + sum1;
        #pragma unroll
        for (int nf = 0; nf < 8; nf++) {
            o_[nf][0] *= sc0; o_[nf][1] *= sc0;
            o_[nf][2] *= sc1; o_[nf][3] *= sc1;
        }

        // ---- O += P V (split; P frags from S regs, V via ldmatrix.trans) ----
        #pragma unroll
        for (int kf = 0; kf < 4; kf++) {
            uint32_t pah[4], pal[4];
            pah[0] = packu_hi(s_[2 * kf][0], s_[2 * kf][1]);
            pah[1] = packu_hi(s_[2 * kf][2], s_[2 * kf][3]);
            pah[2] = packu_hi(s_[2 * kf + 1][0], s_[2 * kf + 1][1]);
            pah[3] = packu_hi(s_[2 * kf + 1][2], s_[2 * kf + 1][3]);
            pal[0] = packu_lo(s_[2 * kf][0], s_[2 * kf][1]);
            pal[1] = packu_lo(s_[2 * kf][2], s_[2 * kf][3]);
            pal[2] = packu_lo(s_[2 * kf + 1][0], s_[2 * kf + 1][1]);
            pal[3] = packu_lo(s_[2 * kf + 1][2], s_[2 * kf + 1][3]);
            #pragma unroll
            for (int g = 0; g < 4; g++) {
                const uint32_t va = sd + 2 * FPLANE
                    + (uint32_t)(kf * 16 + (lane & 15)) * FRSB
                    + ((lane >> 4) * 8 + g * 16) * 2;
                uint32_t rh[4], rl[4];
                ldm_x4_t(rh, va);
                ldm_x4_t(rl, va + FPLANE);
                mma_bf16(o_[2 * g],     pah, rh);
                mma_bf16(o_[2 * g],     pal, rh);
                mma_bf16(o_[2 * g],     pah, rl);
                mma_bf16(o_[2 * g + 1], pah, rh + 2);
                mma_bf16(o_[2 * g + 1], pal, rh + 2);
                mma_bf16(o_[2 * g + 1], pah, rl + 2);
            }
        }
        __syncthreads();
    }

    // ---- normalize + store bf16 hi/lo ----
    const float inv0 = 1.f / l0, inv1 = 1.f / l1;
    const int row0 = b * Lq + q0 + w * 16 + (lane >> 2);
    #pragma unroll
    for (int nf = 0; nf < 8; nf++) {
        const int col = h * 64 + nf * 8 + (lane & 3) * 2;
        const float a0 = o_[nf][0] * inv0, a1 = o_[nf][1] * inv0;
        const float a2 = o_[nf][2] * inv1, a3 = o_[nf][3] * inv1;
        *(__nv_bfloat162*)(Oh + (size_t)row0 * D_ + col) = pack_hi(a0, a1);
        *(__nv_bfloat162*)(Ol + (size_t)row0 * D_ + col) = pack_lo(a0, a1);
        *(__nv_bfloat162*)(Oh + (size_t)(row0 + 8) * D_ + col) = pack_hi(a2, a3);
        *(__nv_bfloat162*)(Ol + (size_t)(row0 + 8) * D_ + col) = pack_lo(a2, a3);
    }
}

// ----------------------------------------------------------------------------
// Host orchestration
// ----------------------------------------------------------------------------
extern "C" void kernel_launch(void* const* d_in, const int* in_sizes, int n_in,
                              void* d_out, int out_size) {
    const float* x          = (const float*)d_in[0];
    const float* alibi      = (const float*)d_in[1];
    const float* species    = (const float*)d_in[2];
    const float* norm1_g    = (const float*)d_in[3];
    const float* norm1_b    = (const float*)d_in[4];
    const float* sa_wqkv    = (const float*)d_in[5];
    const float* sa_bqkv    = (const float*)d_in[6];
    const float* sa_wo      = (const float*)d_in[7];
    const float* sa_bo      = (const float*)d_in[8];
    const float* ca_nq_g    = (const float*)d_in[9];
    const float* ca_nq_b    = (const float*)d_in[10];
    const float* ca_nkv_g   = (const float*)d_in[11];
    const float* ca_nkv_b   = (const float*)d_in[12];
    const float* ca_wqkv    = (const float*)d_in[13];
    const float* ca_bqkv    = (const float*)d_in[14];
    const float* ca_wo      = (const float*)d_in[15];
    const float* ca_bo      = (const float*)d_in[16];
    const float* gate_param = (const float*)d_in[17];
    const float* ffn_g      = (const float*)d_in[18];
    const float* ffn_b      = (const float*)d_in[19];
    const float* ffn_w1     = (const float*)d_in[20];
    const float* ffn_b1     = (const float*)d_in[21];
    const float* ffn_w2     = (const float*)d_in[22];
    const float* ffn_b2     = (const float*)d_in[23];
    float* out = (float*)d_out;

    char* S = nullptr;
    cudaGetSymbolAddress((void**)&S, g_scratch);
    #define BF(off) ((__nv_bfloat16*)(S + (off)))
    #define F32(off) ((float*)(S + (off)))
    __nv_bfloat16 *wqkvs_h = BF(O_WQKVS_H), *wqkvs_l = BF(O_WQKVS_L);
    __nv_bfloat16 *wsao_h = BF(O_WSAO_H), *wsao_l = BF(O_WSAO_L);
    __nv_bfloat16 *wqkvc_h = BF(O_WQKVC_H), *wqkvc_l = BF(O_WQKVC_L);
    __nv_bfloat16 *wcao_h = BF(O_WCAO_H), *wcao_l = BF(O_WCAO_L);
    __nv_bfloat16 *wf1_h = BF(O_WF1_H), *wf1_l = BF(O_WF1_L);
    __nv_bfloat16 *wf2_h = BF(O_WF2_H), *wf2_l = BF(O_WF2_L);
    __nv_bfloat16 *ln_h = BF(O_LN_H), *ln_l = BF(O_LN_L);
    __nv_bfloat16 *at_h = BF(O_AT_H), *at_l = BF(O_AT_L);
    __nv_bfloat16 *kvn_h = BF(O_KVN_H), *kvn_l = BF(O_KVN_L);
    __nv_bfloat16 *gg_h = BF(O_GG_H), *gg_l = BF(O_GG_L);
    __nv_bfloat16 *qkv_h = BF(O_QKV_H), *qkv_l = BF(O_QKV_L);
    __nv_bfloat16 *cq_h = BF(O_CQ_H), *cq_l = BF(O_CQ_L);
    __nv_bfloat16 *ckv_h = BF(O_CKV_H), *ckv_l = BF(O_CKV_L);
    float *x1 = F32(O_X1), *x2 = F32(O_X2);

    cudaFuncSetAttribute(mma_gemm<1>, cudaFuncAttributeMaxDynamicSharedMemorySize, GEMM_SMEM);
    cudaFuncSetAttribute(mma_gemm<2>, cudaFuncAttributeMaxDynamicSharedMemorySize, GEMM_SMEM);
    cudaFuncSetAttribute(mma_gemm<3>, cudaFuncAttributeMaxDynamicSharedMemorySize, GEMM_SMEM);
    cudaFuncSetAttribute(mma_gemm<4>, cudaFuncAttributeMaxDynamicSharedMemorySize, GEMM_SMEM);
    cudaFuncSetAttribute(flash_mma, cudaFuncAttributeMaxDynamicSharedMemorySize, FLASH_SMEM);

    // ---- weight split ----
    auto cvt = [&](const float* w, __nv_bfloat16* h, __nv_bfloat16* l, int n) {
        cvt_split_kernel<<<(n / 4 + 255) / 256, 256>>>(
            (const float4*)w, (__nv_bfloat162*)h, (__nv_bfloat162*)l, n / 4);
    };
    cvt(sa_wqkv, wqkvs_h, wqkvs_l, 3 * D_ * D_);
    cvt(sa_wo,   wsao_h,  wsao_l,  D_ * D_);
    cvt(ca_wqkv, wqkvc_h, wqkvc_l, 3 * D_ * D_);
    cvt(ca_wo,   wcao_h,  wcao_l,  D_ * D_);
    cvt(ffn_w2,  wf2_h,   wf2_l,   D_ * FF_);
    cvt_split_ileave_kernel<<<(2 * FF_ * D_ / 4 + 255) / 256, 256>>>(
        ffn_w1, (__nv_bfloat162*)wf1_h, (__nv_bfloat162*)wf1_l, 2 * FF_ * D_ / 4);

    // ---- Self-attention ----
    ln_kernel<<<M_, 256>>>(x, norm1_g, norm1_b, ln_h, ln_l);
    mma_gemm<3><<<dim3(3 * D_ / TN, M_ / TM), 256, GEMM_SMEM>>>(
        ln_h, ln_l, wqkvs_h, wqkvs_l, sa_bqkv, nullptr, nullptr,
        nullptr, qkv_h, qkv_l, 3 * D_, D_, 0);
    flash_mma<<<dim3(L_ / 64, B_ * H_), 128, FLASH_SMEM>>>(
        qkv_h, qkv_l, 3 * D_,
        qkv_h + D_, qkv_l + D_, 3 * D_,
        qkv_h + 2 * D_, qkv_l + 2 * D_,
        alibi, at_h, at_l, L_, L_);
    mma_gemm<1><<<dim3(D_ / TN, M_ / TM), 256, GEMM_SMEM>>>(
        at_h, at_l, wsao_h, wsao_l, sa_bo, x, nullptr, x1, nullptr, nullptr, D_, D_, 0);

    // ---- Cross-attention ----
    ln_kernel<<<M_, 256>>>(x1, ca_nq_g, ca_nq_b, ln_h, ln_l);
    ln_kernel<<<B_ * NS_, 256>>>(species, ca_nkv_g, ca_nkv_b, kvn_h, kvn_l);
    mma_gemm<3><<<dim3(D_ / TN, M_ / TM), 256, GEMM_SMEM>>>(
        ln_h, ln_l, wqkvc_h, wqkvc_l, ca_bqkv, nullptr, nullptr,
        nullptr, cq_h, cq_l, D_, D_, 0);
    mma_gemm<3><<<dim3(2 * D_ / TN, (B_ * NS_) / TM), 256, GEMM_SMEM>>>(
        kvn_h, kvn_l, wqkvc_h, wqkvc_l, ca_bqkv + D_, nullptr, nullptr,
        nullptr, ckv_h, ckv_l, 2 * D_, D_, D_);
    flash_mma<<<dim3(L_ / 64, B_ * H_), 128, FLASH_SMEM>>>(
        cq_h, cq_l, D_,
        ckv_h, ckv_l, 2 * D_,
        ckv_h + D_, ckv_l + D_,
        nullptr, at_h, at_l, L_, NS_);
    mma_gemm<2><<<dim3(D_ / TN, M_ / TM), 256, GEMM_SMEM>>>(
        at_h, at_l, wcao_h, wcao_l, ca_bo, x1, gate_param, x2, nullptr, nullptr, D_, D_, 0);

    // ---- FFN (GEGLU fused into FFN1 epilogue) ----
    ln_kernel<<<M_, 256>>>(x2, ffn_g, ffn_b, ln_h, ln_l);
    mma_gemm<4><<<dim3(2 * FF_ / TN, M_ / TM), 256, GEMM_SMEM>>>(
        ln_h, ln_l, wf1_h, wf1_l, ffn_b1, nullptr, nullptr,
        nullptr, gg_h, gg_l, 2 * FF_, D_, 0);
    mma_gemm<1><<<dim3(D_ / TN, M_ / TM), 256, GEMM_SMEM>>>(
        gg_h, gg_l, wf2_h, wf2_l, ffn_b2, x2, nullptr, out, nullptr, nullptr, D_, FF_, 0);
}

// round 9
// speedup vs baseline: 3.7094x; 1.3155x over previous
#include <cuda_runtime.h>
#include <cuda_fp16.h>
#include <math.h>
#include <stdint.h>

// ----------------------------------------------------------------------------
// Shapes (fixed)
// ----------------------------------------------------------------------------
#define B_   4
#define L_   1024
#define D_   1024
#define H_   16
#define HD_  64
#define FF_  4096
#define NS_  64
#define M_   (B_ * L_)          // 4096 rows

// ----------------------------------------------------------------------------
// Scratch (bytes)
// ----------------------------------------------------------------------------
#define SZ_WQKV   (3072ull*1024u*2u)
#define SZ_WO     (1024ull*1024u*2u)
#define SZ_WF1    (8192ull*1024u*2u)
#define SZ_WF2    (1024ull*4096u*2u)
#define SZ_ACT    (4096ull*1024u*2u)
#define SZ_KVN    (256ull*1024u*2u)
#define SZ_GG     (4096ull*4096u*2u)
#define SZ_QKVP   (4096ull*3072u*2u)
#define SZ_CQ     (4096ull*1024u*2u)
#define SZ_CKVP   (256ull*2048u*2u)
#define SZ_D32    (4096ull*1024u*4u)

#define O_WQKVS     0ull
#define O_WSAO      (O_WQKVS + SZ_WQKV)
#define O_WQKVC     (O_WSAO + SZ_WO)
#define O_WCAO      (O_WQKVC + SZ_WQKV)
#define O_WF1       (O_WCAO + SZ_WO)
#define O_WF2       (O_WF1 + SZ_WF1)
#define O_LN_H      (O_WF2 + SZ_WF2)
#define O_LN_L      (O_LN_H + SZ_ACT)
#define O_AT_H      (O_LN_L + SZ_ACT)
#define O_AT_L      (O_AT_H + SZ_ACT)
#define O_KVN_H     (O_AT_L + SZ_ACT)
#define O_KVN_L     (O_KVN_H + SZ_KVN)
#define O_GG_H      (O_KVN_L + SZ_KVN)
#define O_GG_L      (O_GG_H + SZ_GG)
#define O_QKV_H     (O_GG_L + SZ_GG)
#define O_QKV_L     (O_QKV_H + SZ_QKVP)
#define O_CQ_H      (O_QKV_L + SZ_QKVP)
#define O_CQ_L      (O_CQ_H + SZ_CQ)
#define O_CKV_H     (O_CQ_L + SZ_CQ)
#define O_CKV_L     (O_CKV_H + SZ_CKVP)
#define O_X1        (O_CKV_L + SZ_CKVP)
#define O_X2        (O_X1 + SZ_D32)
#define SCRATCH_BYTES (O_X2 + SZ_D32)

__device__ __align__(1024) char g_scratch[SCRATCH_BYTES];

// ----------------------------------------------------------------------------
// PTX helpers (family-agnostic)
// ----------------------------------------------------------------------------
__device__ __forceinline__ uint32_t smem_u32(const void* p) {
    uint32_t a;
    asm("{ .reg .u64 t; cvta.to.shared.u64 t, %1; cvt.u32.u64 %0, t; }"
        : "=r"(a) : "l"(p));
    return a;
}
__device__ __forceinline__ void cpa16(uint32_t s, const void* g) {
    asm volatile("cp.async.cg.shared.global [%0], [%1], 16;" :: "r"(s), "l"(g));
}
#define CP_COMMIT() asm volatile("cp.async.commit_group;" ::: "memory")
#define CP_WAIT0() asm volatile("cp.async.wait_group 0;" ::: "memory")
#define CP_WAIT1() asm volatile("cp.async.wait_group 1;" ::: "memory")

__device__ __forceinline__ void ldm_x4(uint32_t* r, uint32_t addr) {
    asm volatile("ldmatrix.sync.aligned.m8n8.x4.shared.b16 {%0,%1,%2,%3}, [%4];"
        : "=r"(r[0]), "=r"(r[1]), "=r"(r[2]), "=r"(r[3]) : "r"(addr));
}
__device__ __forceinline__ void ldm_x4_t(uint32_t* r, uint32_t addr) {
    asm volatile("ldmatrix.sync.aligned.m8n8.x4.trans.shared.b16 {%0,%1,%2,%3}, [%4];"
        : "=r"(r[0]), "=r"(r[1]), "=r"(r[2]), "=r"(r[3]) : "r"(addr));
}
__device__ __forceinline__ void mma_f16(float* d, const uint32_t* a, const uint32_t* b) {
    asm volatile(
        "mma.sync.aligned.m16n8k16.row.col.f32.f16.f16.f32 "
        "{%0,%1,%2,%3}, {%4,%5,%6,%7}, {%8,%9}, {%0,%1,%2,%3};"
        : "+f"(d[0]), "+f"(d[1]), "+f"(d[2]), "+f"(d[3])
        : "r"(a[0]), "r"(a[1]), "r"(a[2]), "r"(a[3]), "r"(b[0]), "r"(b[1]));
}

__device__ __forceinline__ __half2 packh_hi(float a, float b) {
    return __floats2half2_rn(a, b);
}
__device__ __forceinline__ __half2 packh_lo(float a, float b) {
    const __half ha = __float2half_rn(a), hb = __float2half_rn(b);
    return __halves2half2(__float2half_rn(a - __half2float(ha)),
                          __float2half_rn(b - __half2float(hb)));
}
__device__ __forceinline__ uint32_t packu_hi(float a, float b) {
    __half2 v = packh_hi(a, b);
    return *(uint32_t*)&v;
}
__device__ __forceinline__ uint32_t packu_lo(float a, float b) {
    __half2 v = packh_lo(a, b);
    return *(uint32_t*)&v;
}

// Fast exp on FFMA pipe (x <= 0 path), rel err ~2e-6
__device__ __forceinline__ float fexp(float x) {
    float z = x * 1.4426950408889634f;
    z = fmaxf(z, -120.0f);
    float zi = z + 12582912.0f;
    int i = __float_as_int(zi) - 0x4B400000;
    float f = z - (zi - 12582912.0f);
    float p = 1.3333558e-3f;
    p = fmaf(p, f, 9.6181291e-3f);
    p = fmaf(p, f, 5.5504109e-2f);
    p = fmaf(p, f, 2.4022651e-1f);
    p = fmaf(p, f, 6.9314718e-1f);
    p = fmaf(p, f, 1.0f);
    return p * __int_as_float((i + 127) << 23);
}

// ----------------------------------------------------------------------------
// Weight convert: fp32 -> single fp16 plane
// ----------------------------------------------------------------------------
__global__ __launch_bounds__(256)
void cvt_h_kernel(const float4* __restrict__ w, __half2* __restrict__ hi, int n4) {
    int i = blockIdx.x * 256 + threadIdx.x;
    if (i >= n4) return;
    const float4 v = w[i];
    hi[i * 2]     = packh_hi(v.x, v.y);
    hi[i * 2 + 1] = packh_hi(v.z, v.w);
}

// ffn_w1 interleave: dst row 2j = w1[j] (val), 2j+1 = w1[FF+j] (gate)
__global__ __launch_bounds__(256)
void cvt_h_ileave_kernel(const float* __restrict__ w, __half2* __restrict__ hi, int n4) {
    int i = blockIdx.x * 256 + threadIdx.x;
    if (i >= n4) return;
    const int row = i >> 8;
    const int col4 = (i & 255) * 4;
    const int srow = (row & 1) ? (FF_ + (row >> 1)) : (row >> 1);
    const float4 v = *(const float4*)(w + (size_t)srow * 1024 + col4);
    hi[i * 2]     = packh_hi(v.x, v.y);
    hi[i * 2 + 1] = packh_hi(v.z, v.w);
}

// ----------------------------------------------------------------------------
// LayerNorm -> fp16 hi/lo planes
// ----------------------------------------------------------------------------
__global__ __launch_bounds__(256)
void ln_kernel(const float* __restrict__ x, const float* __restrict__ g,
               const float* __restrict__ b, __half* __restrict__ yh,
               __half* __restrict__ yl) {
    const int row = blockIdx.x;
    const int t = threadIdx.x;
    const float4 v = ((const float4*)(x + (size_t)row * D_))[t];

    __shared__ float red[8];
    __shared__ float stat[2];

    float s = v.x + v.y + v.z + v.w;
    #pragma unroll
    for (int o = 16; o; o >>= 1) s += __shfl_xor_sync(0xffffffffu, s, o);
    if ((t & 31) == 0) red[t >> 5] = s;
    __syncthreads();
    if (t == 0) {
        float s2 = 0.f;
        #pragma unroll
        for (int i = 0; i < 8; i++) s2 += red[i];
        stat[0] = s2 * (1.0f / D_);
    }
    __syncthreads();
    const float mu = stat[0];
    const float dx = v.x - mu, dy = v.y - mu, dz = v.z - mu, dw = v.w - mu;

    float q = dx * dx + dy * dy + dz * dz + dw * dw;
    #pragma unroll
    for (int o = 16; o; o >>= 1) q += __shfl_xor_sync(0xffffffffu, q, o);
    if ((t & 31) == 0) red[t >> 5] = q;
    __syncthreads();
    if (t == 0) {
        float s2 = 0.f;
        #pragma unroll
        for (int i = 0; i < 8; i++) s2 += red[i];
        stat[1] = rsqrtf(s2 * (1.0f / D_) + 1e-5f);
    }
    __syncthreads();
    const float rs = stat[1];

    const float4 gv = ((const float4*)g)[t];
    const float4 bv = ((const float4*)b)[t];
    float o0 = dx * rs * gv.x + bv.x;
    float o1 = dy * rs * gv.y + bv.y;
    float o2 = dz * rs * gv.z + bv.z;
    float o3 = dw * rs * gv.w + bv.w;
    const size_t base = (size_t)row * D_ + t * 4;
    *(__half2*)(yh + base)     = packh_hi(o0, o1);
    *(__half2*)(yh + base + 2) = packh_hi(o2, o3);
    *(__half2*)(yl + base)     = packh_lo(o0, o1);
    *(__half2*)(yl + base + 2) = packh_lo(o2, o3);
}

__device__ __forceinline__ float gelu_exact(float x) {
    return 0.5f * x * (1.0f + erff(x * 0.7071067811865476f));
}

// ----------------------------------------------------------------------------
// mma.sync 2-term fp16 GEMM: C[M,N] = A[M,K] @ W[N,K]^T (+epilogue)
// A as fp16 hi/lo planes, W single fp16 plane.
// CTA tile 128x128, warp tile 64x32 (2x4 warps), K-chunk 64, double-buffered.
// EPI: 1 bias+res (fp32 out); 2 sigmoid(gate)*(..)+res (fp32 out);
//      3 bias only -> fp16 hi/lo planes; 4 GEGLU (interleaved W) -> fp16 planes
// ----------------------------------------------------------------------------
#define TM 128
#define TN 128
#define KCH 64
#define RS 72
#define RSB (RS * 2)
#define PLANE_B (128 * RSB)         // 18432
#define SA_H 0
#define SA_L PLANE_B
#define SW_W (2 * PLANE_B)
#define STAGE_B (3 * PLANE_B)       // 55296
#define GEMM_SMEM (2 * STAGE_B)     // 110592

template <int EPI>
__global__ __launch_bounds__(256, 1)
void mma_gemm(const __half* __restrict__ Ah, const __half* __restrict__ Al,
              const __half* __restrict__ W,
              const float* __restrict__ bias, const float* __restrict__ res,
              const float* __restrict__ gatep, float* __restrict__ C,
              __half* __restrict__ Ch, __half* __restrict__ Cl,
              int N, int K, int wRowOff) {
    extern __shared__ char smem[];
    const uint32_t sb = smem_u32(smem);
    const int t = threadIdx.x;
    const int lane = t & 31;
    const int wid = t >> 5;
    const int wm = wid & 1;
    const int wn = wid >> 1;

    const int mBase = blockIdx.y * TM;
    const int nBase = blockIdx.x * TN;

    uint32_t sOff[4];
    size_t gOffA[4], gOffW[4];
    #pragma unroll
    for (int j = 0; j < 4; j++) {
        const int id = t + 256 * j;
        const int r = id >> 3;
        const int ch = id & 7;
        sOff[j] = (uint32_t)r * RSB + ch * 16;
        gOffA[j] = ((size_t)(mBase + r) * K + ch * 8) * 2;
        gOffW[j] = ((size_t)(nBase + wRowOff + r) * K + ch * 8) * 2;
    }
    const char* pAh = (const char*)Ah;
    const char* pAl = (const char*)Al;
    const char* pW  = (const char*)W;

    auto load_stage = [&](int c, int s) {
        const uint32_t sd = sb + s * STAGE_B;
        const size_t kb = (size_t)c * 128;
        #pragma unroll
        for (int j = 0; j < 4; j++) {
            cpa16(sd + SA_H + sOff[j], pAh + gOffA[j] + kb);
            cpa16(sd + SA_L + sOff[j], pAl + gOffA[j] + kb);
            cpa16(sd + SW_W + sOff[j], pW  + gOffW[j] + kb);
        }
    };

    float acc[4][4][4];
    #pragma unroll
    for (int i = 0; i < 4; i++)
        #pragma unroll
        for (int j = 0; j < 4; j++)
            #pragma unroll
            for (int k = 0; k < 4; k++) acc[i][j][k] = 0.f;

    const int nch = K / KCH;
    load_stage(0, 0);
    CP_COMMIT();

    const uint32_t aRowOff = (uint32_t)(wm * 64 + (lane & 15)) * RSB
                           + ((lane >> 4) * 8) * 2;
    const uint32_t bRowOff = (uint32_t)(wn * 32 + (lane & 7) + ((lane >> 4) & 1) * 8) * RSB
                           + (((lane >> 3) & 1) * 8) * 2;

    for (int c = 0; c < nch; c++) {
        if (c + 1 < nch) { load_stage(c + 1, (c + 1) & 1); CP_COMMIT(); }
        if (c + 1 < nch) { CP_WAIT1(); } else { CP_WAIT0(); }
        __syncthreads();

        const uint32_t sd = sb + (c & 1) * STAGE_B;
        #pragma unroll
        for (int kk = 0; kk < KCH; kk += 16) {
            uint32_t ah[4][4], al[4][4];
            #pragma unroll
            for (int mf = 0; mf < 4; mf++) {
                const uint32_t ad = sd + aRowOff + (uint32_t)(mf * 16) * RSB + kk * 2;
                ldm_x4(ah[mf], ad + SA_H);
                ldm_x4(al[mf], ad + SA_L);
            }
            uint32_t bw[4][2];
            #pragma unroll
            for (int nf2 = 0; nf2 < 2; nf2++) {
                const uint32_t bd = sd + SW_W + bRowOff + (uint32_t)(nf2 * 16) * RSB + kk * 2;
                uint32_t r[4];
                ldm_x4(r, bd);
                bw[nf2 * 2][0] = r[0]; bw[nf2 * 2][1] = r[1];
                bw[nf2 * 2 + 1][0] = r[2]; bw[nf2 * 2 + 1][1] = r[3];
            }
            #pragma unroll
            for (int mf = 0; mf < 4; mf++)
                #pragma unroll
                for (int nf = 0; nf < 4; nf++) {
                    mma_f16(acc[mf][nf], ah[mf], bw[nf]);
                    mma_f16(acc[mf][nf], al[mf], bw[nf]);
                }
        }
        __syncthreads();
    }

    // ---- epilogue ----
    float gs = 1.f;
    if (EPI == 2) gs = 1.f / (1.f + __expf(-gatep[0]));

    const int mWarp = mBase + wm * 64;
    const int nWarp = nBase + wn * 32;
    #pragma unroll
    for (int mf = 0; mf < 4; mf++) {
        const int r0 = mWarp + mf * 16 + (lane >> 2);
        #pragma unroll
        for (int nf = 0; nf < 4; nf++) {
            const int c0 = nWarp + nf * 8 + 2 * (lane & 3);
            if (EPI == 1 || EPI == 2) {
                const float b0 = bias[c0], b1 = bias[c0 + 1];
                float v0 = acc[mf][nf][0] + b0;
                float v1 = acc[mf][nf][1] + b1;
                float v2 = acc[mf][nf][2] + b0;
                float v3 = acc[mf][nf][3] + b1;
                if (EPI == 1) {
                    v0 += res[(size_t)r0 * N + c0];
                    v1 += res[(size_t)r0 * N + c0 + 1];
                    v2 += res[(size_t)(r0 + 8) * N + c0];
                    v3 += res[(size_t)(r0 + 8) * N + c0 + 1];
                } else {
                    v0 = gs * v0 + res[(size_t)r0 * N + c0];
                    v1 = gs * v1 + res[(size_t)r0 * N + c0 + 1];
                    v2 = gs * v2 + res[(size_t)(r0 + 8) * N + c0];
                    v3 = gs * v3 + res[(size_t)(r0 + 8) * N + c0 + 1];
                }
                *(float2*)(C + (size_t)r0 * N + c0) = make_float2(v0, v1);
                *(float2*)(C + (size_t)(r0 + 8) * N + c0) = make_float2(v2, v3);
            } else if (EPI == 3) {
                const float b0 = bias[c0], b1 = bias[c0 + 1];
                const float v0 = acc[mf][nf][0] + b0;
                const float v1 = acc[mf][nf][1] + b1;
                const float v2 = acc[mf][nf][2] + b0;
                const float v3 = acc[mf][nf][3] + b1;
                *(__half2*)(Ch + (size_t)r0 * N + c0) = packh_hi(v0, v1);
                *(__half2*)(Cl + (size_t)r0 * N + c0) = packh_lo(v0, v1);
                *(__half2*)(Ch + (size_t)(r0 + 8) * N + c0) = packh_hi(v2, v3);
                *(__half2*)(Cl + (size_t)(r0 + 8) * N + c0) = packh_lo(v2, v3);
            } else {  // EPI == 4: GEGLU with interleaved W (even=val, odd=gate)
                const int jj = c0 >> 1;
                const int Nout = N >> 1;
                const float bv = bias[jj], bg = bias[FF_ + jj];
                const float va = acc[mf][nf][0] + bv;
                const float ga = acc[mf][nf][1] + bg;
                const float vb = acc[mf][nf][2] + bv;
                const float gb = acc[mf][nf][3] + bg;
                const float oa = va * gelu_exact(ga);
                const float ob = vb * gelu_exact(gb);
                const __half ha = __float2half_rn(oa);
                const __half hb = __float2half_rn(ob);
                Ch[(size_t)r0 * Nout + jj] = ha;
                Cl[(size_t)r0 * Nout + jj] = __float2half_rn(oa - __half2float(ha));
                Ch[(size_t)(r0 + 8) * Nout + jj] = hb;
                Cl[(size_t)(r0 + 8) * Nout + jj] = __float2half_rn(ob - __half2float(hb));
            }
        }
    }
}

// ----------------------------------------------------------------------------
// Tensor-core flash attention (fp16 2-term), HD=64, 64q x 64kv tiles.
// 128 threads (4 warps); warp w owns q rows [16w,16w+16).
// Q as hi/lo planes; K, V single (hi) planes. Output fp16 hi/lo, stride D_.
// ----------------------------------------------------------------------------
#define FRSB 144
#define FPLANE (64 * FRSB)            // 9216
#define FSTAGE (2 * FPLANE)           // 18432 (K, V)
#define FQOFF  (2 * FSTAGE)           // 36864 (QH, QL)
#define FLASH_SMEM (FQOFF + 2 * FPLANE)  // 55296

__global__ __launch_bounds__(128)
void flash_mma(const __half* __restrict__ Qh, const __half* __restrict__ Ql,
               int ldq,
               const __half* __restrict__ Kh, int ldk,
               const __half* __restrict__ Vh,
               const float* __restrict__ bias,
               __half* __restrict__ Oh, __half* __restrict__ Ol,
               int Lq, int Lkv) {
    extern __shared__ char smem[];
    const uint32_t sb = smem_u32(smem);
    const int t = threadIdx.x, lane = t & 31, w = t >> 5;
    const int bh = blockIdx.y, b = bh >> 4, h = bh & 15;
    const int q0 = blockIdx.x * 64;

    // Q tile -> smem
    #pragma unroll
    for (int j = 0; j < 4; j++) {
        const int id = t + 128 * j, r = id >> 3, ch = id & 7;
        const size_t g = ((size_t)(b * Lq + q0 + r)) * ldq + h * 64 + ch * 8;
        const uint32_t so = sb + FQOFF + (uint32_t)r * FRSB + ch * 16;
        cpa16(so, (const char*)Qh + g * 2);
        cpa16(so + FPLANE, (const char*)Ql + g * 2);
    }
    CP_COMMIT();

    auto load_kv = [&](int it, int s) {
        const uint32_t sd = sb + s * FSTAGE;
        const int k0 = it * 64;
        #pragma unroll
        for (int j = 0; j < 4; j++) {
            const int id = t + 128 * j, r = id >> 3, ch = id & 7;
            const size_t g = ((size_t)(b * Lkv + k0 + r)) * ldk + h * 64 + ch * 8;
            const uint32_t so = sd + (uint32_t)r * FRSB + ch * 16;
            cpa16(so,          (const char*)Kh + g * 2);
            cpa16(so + FPLANE, (const char*)Vh + g * 2);
        }
    };
    load_kv(0, 0); CP_COMMIT();

    uint32_t qfh[4][4], qfl[4][4];
    float o_[8][4];
    #pragma unroll
    for (int i = 0; i < 8; i++)
        #pragma unroll
        for (int j = 0; j < 4; j++) o_[i][j] = 0.f;
    float m0 = -1e30f, m1 = -1e30f, l0 = 0.f, l1 = 0.f;
    const float invs = 0.125f;

    const int nt = Lkv / 64;
    for (int it = 0; it < nt; it++) {
        if (it + 1 < nt) { load_kv(it + 1, (it + 1) & 1); CP_COMMIT(); CP_WAIT1(); }
        else { CP_WAIT0(); }
        __syncthreads();
        const uint32_t sd = sb + (it & 1) * FSTAGE;

        if (it == 0) {
            #pragma unroll
            for (int kf = 0; kf < 4; kf++) {
                const uint32_t qa = sb + FQOFF
                    + (uint32_t)(w * 16 + (lane & 15)) * FRSB
                    + ((lane >> 4) * 8 + kf * 16) * 2;
                ldm_x4(qfh[kf], qa);
                ldm_x4(qfl[kf], qa + FPLANE);
            }
        }

        // ---- S = Q K^T (2-term) ----
        float s_[8][4];
        #pragma unroll
        for (int i = 0; i < 8; i++)
            #pragma unroll
            for (int j = 0; j < 4; j++) s_[i][j] = 0.f;
        #pragma unroll
        for (int kf = 0; kf < 4; kf++) {
            #pragma unroll
            for (int g = 0; g < 4; g++) {
                const uint32_t ka = sd
                    + (uint32_t)(g * 16 + (lane & 7) + ((lane >> 4) & 1) * 8) * FRSB
                    + (((lane >> 3) & 1) * 8 + kf * 16) * 2;
                uint32_t rh[4];
                ldm_x4(rh, ka);
                mma_f16(s_[2 * g],     qfh[kf], rh);
                mma_f16(s_[2 * g],     qfl[kf], rh);
                mma_f16(s_[2 * g + 1], qfh[kf], rh + 2);
                mma_f16(s_[2 * g + 1], qfl[kf], rh + 2);
            }
        }

        // ---- scale + bias ----
        if (bias) {
            const int k0 = it * 64;
            const float* bp = bias
                + ((size_t)bh * Lq + (q0 + w * 16 + (lane >> 2))) * Lkv
                + k0 + (lane & 3) * 2;
            #pragma unroll
            for (int nf = 0; nf < 8; nf++) {
                const float2 b0 = *(const float2*)(bp + nf * 8);
                const float2 b1 = *(const float2*)(bp + (size_t)8 * Lkv + nf * 8);
                s_[nf][0] = fmaf(s_[nf][0], invs, b0.x);
                s_[nf][1] = fmaf(s_[nf][1], invs, b0.y);
                s_[nf][2] = fmaf(s_[nf][2], invs, b1.x);
                s_[nf][3] = fmaf(s_[nf][3], invs, b1.y);
            }
        } else {
            #pragma unroll
            for (int nf = 0; nf < 8; nf++)
                #pragma unroll
                for (int i = 0; i < 4; i++) s_[nf][i] *= invs;
        }

        // ---- online softmax ----
        float mx0 = s_[0][0], mx1 = s_[0][2];
        #pragma unroll
        for (int nf = 0; nf < 8; nf++) {
            mx0 = fmaxf(mx0, fmaxf(s_[nf][0], s_[nf][1]));
            mx1 = fmaxf(mx1, fmaxf(s_[nf][2], s_[nf][3]));
        }
        mx0 = fmaxf(mx0, __shfl_xor_sync(0xffffffffu, mx0, 1));
        mx0 = fmaxf(mx0, __shfl_xor_sync(0xffffffffu, mx0, 2));
        mx1 = fmaxf(mx1, __shfl_xor_sync(0xffffffffu, mx1, 1));
        mx1 = fmaxf(mx1, __shfl_xor_sync(0xffffffffu, mx1, 2));
        const float mn0 = fmaxf(m0, mx0), mn1 = fmaxf(m1, mx1);
        const float sc0 = fexp(m0 - mn0), sc1 = fexp(m1 - mn1);
        m0 = mn0; m1 = mn1;
        float sum0 = 0.f, sum1 = 0.f;
        #pragma unroll
        for (int nf = 0; nf < 8; nf++) {
            s_[nf][0] = fexp(s_[nf][0] - mn0);
            s_[nf][1] = fexp(s_[nf][1] - mn0);
            s_[nf][2] = fexp(s_[nf][2] - mn1);
            s_[nf][3] = fexp(s_[nf][3] - mn1);
            sum0 += s_[nf][0] + s_[nf][1];
            sum1 += s_[nf][2] + s_[nf][3];
        }
        sum0 += __shfl_xor_sync(0xffffffffu, sum0, 1);
        sum0 += __shfl_xor_sync(0xffffffffu, sum0, 2);
        sum1 += __shfl_xor_sync(0xffffffffu, sum1, 1);
        sum1 += __shfl_xor_sync(0xffffffffu, sum1, 2);
        l0 = l0 * sc0 + sum0;
        l1 = l1 * sc1 + sum1;
        #pragma unroll
        for (int nf = 0; nf < 8; nf++) {
            o_[nf][0] *= sc0; o_[nf][1] *= sc0;
            o_[nf][2] *= sc1; o_[nf][3] *= sc1;
        }

        // ---- O += P V (P hi/lo from regs, V single via ldmatrix.trans) ----
        #pragma unroll
        for (int kf = 0; kf < 4; kf++) {
            uint32_t pah[4], pal[4];
            pah[0] = packu_hi(s_[2 * kf][0], s_[2 * kf][1]);
            pah[1] = packu_hi(s_[2 * kf][2], s_[2 * kf][3]);
            pah[2] = packu_hi(s_[2 * kf + 1][0], s_[2 * kf + 1][1]);
            pah[3] = packu_hi(s_[2 * kf + 1][2], s_[2 * kf + 1][3]);
            pal[0] = packu_lo(s_[2 * kf][0], s_[2 * kf][1]);
            pal[1] = packu_lo(s_[2 * kf][2], s_[2 * kf][3]);
            pal[2] = packu_lo(s_[2 * kf + 1][0], s_[2 * kf + 1][1]);
            pal[3] = packu_lo(s_[2 * kf + 1][2], s_[2 * kf + 1][3]);
            #pragma unroll
            for (int g = 0; g < 4; g++) {
                const uint32_t va = sd + FPLANE
                    + (uint32_t)(kf * 16 + (lane & 15)) * FRSB
                    + ((lane >> 4) * 8 + g * 16) * 2;
                uint32_t rh[4];
                ldm_x4_t(rh, va);
                mma_f16(o_[2 * g],     pah, rh);
                mma_f16(o_[2 * g],     pal, rh);
                mma_f16(o_[2 * g + 1], pah, rh + 2);
                mma_f16(o_[2 * g + 1], pal, rh + 2);
            }
        }
        __syncthreads();
    }

    // ---- normalize + store fp16 hi/lo ----
    const float inv0 = 1.f / l0, inv1 = 1.f / l1;
    const int row0 = b * Lq + q0 + w * 16 + (lane >> 2);
    #pragma unroll
    for (int nf = 0; nf < 8; nf++) {
        const int col = h * 64 + nf * 8 + (lane & 3) * 2;
        const float a0 = o_[nf][0] * inv0, a1 = o_[nf][1] * inv0;
        const float a2 = o_[nf][2] * inv1, a3 = o_[nf][3] * inv1;
        *(__half2*)(Oh + (size_t)row0 * D_ + col) = packh_hi(a0, a1);
        *(__half2*)(Ol + (size_t)row0 * D_ + col) = packh_lo(a0, a1);
        *(__half2*)(Oh + (size_t)(row0 + 8) * D_ + col) = packh_hi(a2, a3);
        *(__half2*)(Ol + (size_t)(row0 + 8) * D_ + col) = packh_lo(a2, a3);
    }
}

// ----------------------------------------------------------------------------
// Host orchestration
// ----------------------------------------------------------------------------
extern "C" void kernel_launch(void* const* d_in, const int* in_sizes, int n_in,
                              void* d_out, int out_size) {
    const float* x          = (const float*)d_in[0];
    const float* alibi      = (const float*)d_in[1];
    const float* species    = (const float*)d_in[2];
    const float* norm1_g    = (const float*)d_in[3];
    const float* norm1_b    = (const float*)d_in[4];
    const float* sa_wqkv    = (const float*)d_in[5];
    const float* sa_bqkv    = (const float*)d_in[6];
    const float* sa_wo      = (const float*)d_in[7];
    const float* sa_bo      = (const float*)d_in[8];
    const float* ca_nq_g    = (const float*)d_in[9];
    const float* ca_nq_b    = (const float*)d_in[10];
    const float* ca_nkv_g   = (const float*)d_in[11];
    const float* ca_nkv_b   = (const float*)d_in[12];
    const float* ca_wqkv    = (const float*)d_in[13];
    const float* ca_bqkv    = (const float*)d_in[14];
    const float* ca_wo      = (const float*)d_in[15];
    const float* ca_bo      = (const float*)d_in[16];
    const float* gate_param = (const float*)d_in[17];
    const float* ffn_g      = (const float*)d_in[18];
    const float* ffn_b      = (const float*)d_in[19];
    const float* ffn_w1     = (const float*)d_in[20];
    const float* ffn_b1     = (const float*)d_in[21];
    const float* ffn_w2     = (const float*)d_in[22];
    const float* ffn_b2     = (const float*)d_in[23];
    float* out = (float*)d_out;

    char* S = nullptr;
    cudaGetSymbolAddress((void**)&S, g_scratch);
    #define HF(off) ((__half*)(S + (off)))
    #define F32(off) ((float*)(S + (off)))
    __half *wqkvs = HF(O_WQKVS), *wsao = HF(O_WSAO);
    __half *wqkvc = HF(O_WQKVC), *wcao = HF(O_WCAO);
    __half *wf1 = HF(O_WF1), *wf2 = HF(O_WF2);
    __half *ln_h = HF(O_LN_H), *ln_l = HF(O_LN_L);
    __half *at_h = HF(O_AT_H), *at_l = HF(O_AT_L);
    __half *kvn_h = HF(O_KVN_H), *kvn_l = HF(O_KVN_L);
    __half *gg_h = HF(O_GG_H), *gg_l = HF(O_GG_L);
    __half *qkv_h = HF(O_QKV_H), *qkv_l = HF(O_QKV_L);
    __half *cq_h = HF(O_CQ_H), *cq_l = HF(O_CQ_L);
    __half *ckv_h = HF(O_CKV_H), *ckv_l = HF(O_CKV_L);
    float *x1 = F32(O_X1), *x2 = F32(O_X2);

    cudaFuncSetAttribute(mma_gemm<1>, cudaFuncAttributeMaxDynamicSharedMemorySize, GEMM_SMEM);
    cudaFuncSetAttribute(mma_gemm<2>, cudaFuncAttributeMaxDynamicSharedMemorySize, GEMM_SMEM);
    cudaFuncSetAttribute(mma_gemm<3>, cudaFuncAttributeMaxDynamicSharedMemorySize, GEMM_SMEM);
    cudaFuncSetAttribute(mma_gemm<4>, cudaFuncAttributeMaxDynamicSharedMemorySize, GEMM_SMEM);
    cudaFuncSetAttribute(flash_mma, cudaFuncAttributeMaxDynamicSharedMemorySize, FLASH_SMEM);

    // ---- weight convert (single fp16 plane) ----
    auto cvt = [&](const float* w, __half* h, int n) {
        cvt_h_kernel<<<(n / 4 + 255) / 256, 256>>>(
            (const float4*)w, (__half2*)h, n / 4);
    };
    cvt(sa_wqkv, wqkvs, 3 * D_ * D_);
    cvt(sa_wo,   wsao,  D_ * D_);
    cvt(ca_wqkv, wqkvc, 3 * D_ * D_);
    cvt(ca_wo,   wcao,  D_ * D_);
    cvt(ffn_w2,  wf2,   D_ * FF_);
    cvt_h_ileave_kernel<<<(2 * FF_ * D_ / 4 + 255) / 256, 256>>>(
        ffn_w1, (__half2*)wf1, 2 * FF_ * D_ / 4);

    // ---- Self-attention ----
    ln_kernel<<<M_, 256>>>(x, norm1_g, norm1_b, ln_h, ln_l);
    mma_gemm<3><<<dim3(3 * D_ / TN, M_ / TM), 256, GEMM_SMEM>>>(
        ln_h, ln_l, wqkvs, sa_bqkv, nullptr, nullptr,
        nullptr, qkv_h, qkv_l, 3 * D_, D_, 0);
    flash_mma<<<dim3(L_ / 64, B_ * H_), 128, FLASH_SMEM>>>(
        qkv_h, qkv_l, 3 * D_,
        qkv_h + D_, 3 * D_,
        qkv_h + 2 * D_,
        alibi, at_h, at_l, L_, L_);
    mma_gemm<1><<<dim3(D_ / TN, M_ / TM), 256, GEMM_SMEM>>>(
        at_h, at_l, wsao, sa_bo, x, nullptr, x1, nullptr, nullptr, D_, D_, 0);

    // ---- Cross-attention ----
    ln_kernel<<<M_, 256>>>(x1, ca_nq_g, ca_nq_b, ln_h, ln_l);
    ln_kernel<<<B_ * NS_, 256>>>(species, ca_nkv_g, ca_nkv_b, kvn_h, kvn_l);
    mma_gemm<3><<<dim3(D_ / TN, M_ / TM), 256, GEMM_SMEM>>>(
        ln_h, ln_l, wqkvc, ca_bqkv, nullptr, nullptr,
        nullptr, cq_h, cq_l, D_, D_, 0);
    mma_gemm<3><<<dim3(2 * D_ / TN, (B_ * NS_) / TM), 256, GEMM_SMEM>>>(
        kvn_h, kvn_l, wqkvc, ca_bqkv + D_, nullptr, nullptr,
        nullptr, ckv_h, ckv_l, 2 * D_, D_, D_);
    flash_mma<<<dim3(L_ / 64, B_ * H_), 128, FLASH_SMEM>>>(
        cq_h, cq_l, D_,
        ckv_h, 2 * D_,
        ckv_h + D_,
        nullptr, at_h, at_l, L_, NS_);
    mma_gemm<2><<<dim3(D_ / TN, M_ / TM), 256, GEMM_SMEM>>>(
        at_h, at_l, wcao, ca_bo, x1, gate_param, x2, nullptr, nullptr, D_, D_, 0);

    // ---- FFN (GEGLU fused into FFN1 epilogue) ----
    ln_kernel<<<M_, 256>>>(x2, ffn_g, ffn_b, ln_h, ln_l);
    mma_gemm<4><<<dim3(2 * FF_ / TN, M_ / TM), 256, GEMM_SMEM>>>(
        ln_h, ln_l, wf1, ffn_b1, nullptr, nullptr,
        nullptr, gg_h, gg_l, 2 * FF_, D_, 0);
    mma_gemm<1><<<dim3(D_ / TN, M_ / TM), 256, GEMM_SMEM>>>(
        gg_h, gg_l, wf2, ffn_b2, x2, nullptr, out, nullptr, nullptr, D_, FF_, 0);
}

// round 10
// speedup vs baseline: 5.7601x; 1.5528x over previous
#include <cuda_runtime.h>
#include <cuda_fp16.h>
#include <math.h>
#include <stdint.h>

// ----------------------------------------------------------------------------
// Shapes (fixed)
// ----------------------------------------------------------------------------
#define B_   4
#define L_   1024
#define D_   1024
#define H_   16
#define HD_  64
#define FF_  4096
#define NS_  64
#define M_   (B_ * L_)          // 4096 rows

// ----------------------------------------------------------------------------
// Scratch (bytes) — single fp16 plane per tensor
// ----------------------------------------------------------------------------
#define SZ_WQKV   (3072ull*1024u*2u)
#define SZ_WO     (1024ull*1024u*2u)
#define SZ_WF1    (8192ull*1024u*2u)
#define SZ_WF2    (1024ull*4096u*2u)
#define SZ_ACT    (4096ull*1024u*2u)
#define SZ_KVN    (256ull*1024u*2u)
#define SZ_GG     (4096ull*4096u*2u)
#define SZ_QKV1   (4096ull*3072u*2u)
#define SZ_CKV1   (256ull*2048u*2u)
#define SZ_D32    (4096ull*1024u*4u)

#define O_WQKVS     0ull
#define O_WSAO      (O_WQKVS + SZ_WQKV)
#define O_WQKVC     (O_WSAO + SZ_WO)
#define O_WCAO      (O_WQKVC + SZ_WQKV)
#define O_WF1       (O_WCAO + SZ_WO)
#define O_WF2       (O_WF1 + SZ_WF1)
#define O_LN        (O_WF2 + SZ_WF2)
#define O_AT        (O_LN + SZ_ACT)
#define O_KVN       (O_AT + SZ_ACT)
#define O_GG        (O_KVN + SZ_KVN)
#define O_QKV       (O_GG + SZ_GG)
#define O_CQ        (O_QKV + SZ_QKV1)
#define O_CKV       (O_CQ + SZ_ACT)
#define O_X1        (O_CKV + SZ_CKV1)
#define O_X2        (O_X1 + SZ_D32)
#define SCRATCH_BYTES (O_X2 + SZ_D32)

__device__ __align__(1024) char g_scratch[SCRATCH_BYTES];

// ----------------------------------------------------------------------------
// PTX helpers (family-agnostic)
// ----------------------------------------------------------------------------
__device__ __forceinline__ uint32_t smem_u32(const void* p) {
    uint32_t a;
    asm("{ .reg .u64 t; cvta.to.shared.u64 t, %1; cvt.u32.u64 %0, t; }"
        : "=r"(a) : "l"(p));
    return a;
}
__device__ __forceinline__ void cpa16(uint32_t s, const void* g) {
    asm volatile("cp.async.cg.shared.global [%0], [%1], 16;" :: "r"(s), "l"(g));
}
#define CP_COMMIT() asm volatile("cp.async.commit_group;" ::: "memory")
#define CP_WAIT0() asm volatile("cp.async.wait_group 0;" ::: "memory")
#define CP_WAIT1() asm volatile("cp.async.wait_group 1;" ::: "memory")

__device__ __forceinline__ void ldm_x4(uint32_t* r, uint32_t addr) {
    asm volatile("ldmatrix.sync.aligned.m8n8.x4.shared.b16 {%0,%1,%2,%3}, [%4];"
        : "=r"(r[0]), "=r"(r[1]), "=r"(r[2]), "=r"(r[3]) : "r"(addr));
}
__device__ __forceinline__ void ldm_x4_t(uint32_t* r, uint32_t addr) {
    asm volatile("ldmatrix.sync.aligned.m8n8.x4.trans.shared.b16 {%0,%1,%2,%3}, [%4];"
        : "=r"(r[0]), "=r"(r[1]), "=r"(r[2]), "=r"(r[3]) : "r"(addr));
}
__device__ __forceinline__ void mma_f16(float* d, const uint32_t* a, const uint32_t* b) {
    asm volatile(
        "mma.sync.aligned.m16n8k16.row.col.f32.f16.f16.f32 "
        "{%0,%1,%2,%3}, {%4,%5,%6,%7}, {%8,%9}, {%0,%1,%2,%3};"
        : "+f"(d[0]), "+f"(d[1]), "+f"(d[2]), "+f"(d[3])
        : "r"(a[0]), "r"(a[1]), "r"(a[2]), "r"(a[3]), "r"(b[0]), "r"(b[1]));
}

__device__ __forceinline__ __half2 packh(float a, float b) {
    return __floats2half2_rn(a, b);
}
__device__ __forceinline__ uint32_t packu(float a, float b) {
    __half2 v = packh(a, b);
    return *(uint32_t*)&v;
}

// Fast exp on FFMA pipe (x <= 0 path), rel err ~2e-6
__device__ __forceinline__ float fexp(float x) {
    float z = x * 1.4426950408889634f;
    z = fmaxf(z, -120.0f);
    float zi = z + 12582912.0f;
    int i = __float_as_int(zi) - 0x4B400000;
    float f = z - (zi - 12582912.0f);
    float p = 1.3333558e-3f;
    p = fmaf(p, f, 9.6181291e-3f);
    p = fmaf(p, f, 5.5504109e-2f);
    p = fmaf(p, f, 2.4022651e-1f);
    p = fmaf(p, f, 6.9314718e-1f);
    p = fmaf(p, f, 1.0f);
    return p * __int_as_float((i + 127) << 23);
}

// ----------------------------------------------------------------------------
// Weight convert: fp32 -> fp16
// ----------------------------------------------------------------------------
__global__ __launch_bounds__(256)
void cvt_h_kernel(const float4* __restrict__ w, __half2* __restrict__ hi, int n4) {
    int i = blockIdx.x * 256 + threadIdx.x;
    if (i >= n4) return;
    const float4 v = w[i];
    hi[i * 2]     = packh(v.x, v.y);
    hi[i * 2 + 1] = packh(v.z, v.w);
}

// ffn_w1 interleave: dst row 2j = w1[j] (val), 2j+1 = w1[FF+j] (gate)
__global__ __launch_bounds__(256)
void cvt_h_ileave_kernel(const float* __restrict__ w, __half2* __restrict__ hi, int n4) {
    int i = blockIdx.x * 256 + threadIdx.x;
    if (i >= n4) return;
    const int row = i >> 8;
    const int col4 = (i & 255) * 4;
    const int srow = (row & 1) ? (FF_ + (row >> 1)) : (row >> 1);
    const float4 v = *(const float4*)(w + (size_t)srow * 1024 + col4);
    hi[i * 2]     = packh(v.x, v.y);
    hi[i * 2 + 1] = packh(v.z, v.w);
}

// ----------------------------------------------------------------------------
// LayerNorm -> fp16 plane
// ----------------------------------------------------------------------------
__global__ __launch_bounds__(256)
void ln_kernel(const float* __restrict__ x, const float* __restrict__ g,
               const float* __restrict__ b, __half* __restrict__ yh) {
    const int row = blockIdx.x;
    const int t = threadIdx.x;
    const float4 v = ((const float4*)(x + (size_t)row * D_))[t];

    __shared__ float red[8];
    __shared__ float stat[2];

    float s = v.x + v.y + v.z + v.w;
    #pragma unroll
    for (int o = 16; o; o >>= 1) s += __shfl_xor_sync(0xffffffffu, s, o);
    if ((t & 31) == 0) red[t >> 5] = s;
    __syncthreads();
    if (t == 0) {
        float s2 = 0.f;
        #pragma unroll
        for (int i = 0; i < 8; i++) s2 += red[i];
        stat[0] = s2 * (1.0f / D_);
    }
    __syncthreads();
    const float mu = stat[0];
    const float dx = v.x - mu, dy = v.y - mu, dz = v.z - mu, dw = v.w - mu;

    float q = dx * dx + dy * dy + dz * dz + dw * dw;
    #pragma unroll
    for (int o = 16; o; o >>= 1) q += __shfl_xor_sync(0xffffffffu, q, o);
    if ((t & 31) == 0) red[t >> 5] = q;
    __syncthreads();
    if (t == 0) {
        float s2 = 0.f;
        #pragma unroll
        for (int i = 0; i < 8; i++) s2 += red[i];
        stat[1] = rsqrtf(s2 * (1.0f / D_) + 1e-5f);
    }
    __syncthreads();
    const float rs = stat[1];

    const float4 gv = ((const float4*)g)[t];
    const float4 bv = ((const float4*)b)[t];
    const float o0 = dx * rs * gv.x + bv.x;
    const float o1 = dy * rs * gv.y + bv.y;
    const float o2 = dz * rs * gv.z + bv.z;
    const float o3 = dw * rs * gv.w + bv.w;
    const size_t base = (size_t)row * D_ + t * 4;
    *(__half2*)(yh + base)     = packh(o0, o1);
    *(__half2*)(yh + base + 2) = packh(o2, o3);
}

__device__ __forceinline__ float gelu_exact(float x) {
    return 0.5f * x * (1.0f + erff(x * 0.7071067811865476f));
}

// ----------------------------------------------------------------------------
// mma.sync 1-term fp16 GEMM: C[M,N] = A[M,K] @ W[N,K]^T (+epilogue)
// CTA tile 128x128, warp tile 64x32 (2x4 warps), K-chunk 64, double-buffered.
// EPI: 1 bias+res (fp32 out); 2 sigmoid(gate)*(..)+res (fp32 out);
//      3 bias only -> fp16 plane; 4 GEGLU (interleaved W) -> fp16 plane
// ----------------------------------------------------------------------------
#define TM 128
#define TN 128
#define KCH 64
#define RS 72
#define RSB (RS * 2)
#define PLANE_B (128 * RSB)         // 18432
#define SA_A 0
#define SW_W PLANE_B
#define STAGE_B (2 * PLANE_B)       // 36864
#define GEMM_SMEM (2 * STAGE_B)     // 73728

template <int EPI>
__global__ __launch_bounds__(256, 1)
void mma_gemm(const __half* __restrict__ A, const __half* __restrict__ W,
              const float* __restrict__ bias, const float* __restrict__ res,
              const float* __restrict__ gatep, float* __restrict__ C,
              __half* __restrict__ Ch,
              int N, int K, int wRowOff) {
    extern __shared__ char smem[];
    const uint32_t sb = smem_u32(smem);
    const int t = threadIdx.x;
    const int lane = t & 31;
    const int wid = t >> 5;
    const int wm = wid & 1;
    const int wn = wid >> 1;

    const int mBase = blockIdx.y * TM;
    const int nBase = blockIdx.x * TN;

    uint32_t sOff[4];
    size_t gOffA[4], gOffW[4];
    #pragma unroll
    for (int j = 0; j < 4; j++) {
        const int id = t + 256 * j;
        const int r = id >> 3;
        const int ch = id & 7;
        sOff[j] = (uint32_t)r * RSB + ch * 16;
        gOffA[j] = ((size_t)(mBase + r) * K + ch * 8) * 2;
        gOffW[j] = ((size_t)(nBase + wRowOff + r) * K + ch * 8) * 2;
    }
    const char* pA = (const char*)A;
    const char* pW = (const char*)W;

    auto load_stage = [&](int c, int s) {
        const uint32_t sd = sb + s * STAGE_B;
        const size_t kb = (size_t)c * 128;
        #pragma unroll
        for (int j = 0; j < 4; j++) {
            cpa16(sd + SA_A + sOff[j], pA + gOffA[j] + kb);
            cpa16(sd + SW_W + sOff[j], pW + gOffW[j] + kb);
        }
    };

    float acc[4][4][4];
    #pragma unroll
    for (int i = 0; i < 4; i++)
        #pragma unroll
        for (int j = 0; j < 4; j++)
            #pragma unroll
            for (int k = 0; k < 4; k++) acc[i][j][k] = 0.f;

    const int nch = K / KCH;
    load_stage(0, 0);
    CP_COMMIT();

    const uint32_t aRowOff = (uint32_t)(wm * 64 + (lane & 15)) * RSB
                           + ((lane >> 4) * 8) * 2;
    const uint32_t bRowOff = (uint32_t)(wn * 32 + (lane & 7) + ((lane >> 4) & 1) * 8) * RSB
                           + (((lane >> 3) & 1) * 8) * 2;

    for (int c = 0; c < nch; c++) {
        if (c + 1 < nch) { load_stage(c + 1, (c + 1) & 1); CP_COMMIT(); }
        if (c + 1 < nch) { CP_WAIT1(); } else { CP_WAIT0(); }
        __syncthreads();

        const uint32_t sd = sb + (c & 1) * STAGE_B;
        #pragma unroll
        for (int kk = 0; kk < KCH; kk += 16) {
            uint32_t ah[4][4];
            #pragma unroll
            for (int mf = 0; mf < 4; mf++) {
                const uint32_t ad = sd + SA_A + aRowOff + (uint32_t)(mf * 16) * RSB + kk * 2;
                ldm_x4(ah[mf], ad);
            }
            uint32_t bw[4][2];
            #pragma unroll
            for (int nf2 = 0; nf2 < 2; nf2++) {
                const uint32_t bd = sd + SW_W + bRowOff + (uint32_t)(nf2 * 16) * RSB + kk * 2;
                uint32_t r[4];
                ldm_x4(r, bd);
                bw[nf2 * 2][0] = r[0]; bw[nf2 * 2][1] = r[1];
                bw[nf2 * 2 + 1][0] = r[2]; bw[nf2 * 2 + 1][1] = r[3];
            }
            #pragma unroll
            for (int mf = 0; mf < 4; mf++)
                #pragma unroll
                for (int nf = 0; nf < 4; nf++)
                    mma_f16(acc[mf][nf], ah[mf], bw[nf]);
        }
        __syncthreads();
    }

    // ---- epilogue ----
    float gs = 1.f;
    if (EPI == 2) gs = 1.f / (1.f + __expf(-gatep[0]));

    const int mWarp = mBase + wm * 64;
    const int nWarp = nBase + wn * 32;
    #pragma unroll
    for (int mf = 0; mf < 4; mf++) {
        const int r0 = mWarp + mf * 16 + (lane >> 2);
        #pragma unroll
        for (int nf = 0; nf < 4; nf++) {
            const int c0 = nWarp + nf * 8 + 2 * (lane & 3);
            if (EPI == 1 || EPI == 2) {
                const float b0 = bias[c0], b1 = bias[c0 + 1];
                float v0 = acc[mf][nf][0] + b0;
                float v1 = acc[mf][nf][1] + b1;
                float v2 = acc[mf][nf][2] + b0;
                float v3 = acc[mf][nf][3] + b1;
                if (EPI == 1) {
                    v0 += res[(size_t)r0 * N + c0];
                    v1 += res[(size_t)r0 * N + c0 + 1];
                    v2 += res[(size_t)(r0 + 8) * N + c0];
                    v3 += res[(size_t)(r0 + 8) * N + c0 + 1];
                } else {
                    v0 = gs * v0 + res[(size_t)r0 * N + c0];
                    v1 = gs * v1 + res[(size_t)r0 * N + c0 + 1];
                    v2 = gs * v2 + res[(size_t)(r0 + 8) * N + c0];
                    v3 = gs * v3 + res[(size_t)(r0 + 8) * N + c0 + 1];
                }
                *(float2*)(C + (size_t)r0 * N + c0) = make_float2(v0, v1);
                *(float2*)(C + (size_t)(r0 + 8) * N + c0) = make_float2(v2, v3);
            } else if (EPI == 3) {
                const float b0 = bias[c0], b1 = bias[c0 + 1];
                *(__half2*)(Ch + (size_t)r0 * N + c0) =
                    packh(acc[mf][nf][0] + b0, acc[mf][nf][1] + b1);
                *(__half2*)(Ch + (size_t)(r0 + 8) * N + c0) =
                    packh(acc[mf][nf][2] + b0, acc[mf][nf][3] + b1);
            } else {  // EPI == 4: GEGLU with interleaved W (even=val, odd=gate)
                const int jj = c0 >> 1;
                const int Nout = N >> 1;
                const float bv = bias[jj], bg = bias[FF_ + jj];
                const float va = acc[mf][nf][0] + bv;
                const float ga = acc[mf][nf][1] + bg;
                const float vb = acc[mf][nf][2] + bv;
                const float gb = acc[mf][nf][3] + bg;
                Ch[(size_t)r0 * Nout + jj] = __float2half_rn(va * gelu_exact(ga));
                Ch[(size_t)(r0 + 8) * Nout + jj] = __float2half_rn(vb * gelu_exact(gb));
            }
        }
    }
}

// ----------------------------------------------------------------------------
// Tensor-core flash attention (1-term fp16), HD=64, 64q x 64kv tiles.
// 128 threads (4 warps); warp w owns q rows [16w,16w+16).
// Output fp16 plane with row stride D_.
// ----------------------------------------------------------------------------
#define FRSB 144
#define FPLANE (64 * FRSB)            // 9216
#define FSTAGE (2 * FPLANE)           // 18432 (K, V)
#define FQOFF  (2 * FSTAGE)           // 36864 (Q)
#define FLASH_SMEM (FQOFF + FPLANE)   // 46080

__global__ __launch_bounds__(128)
void flash_mma(const __half* __restrict__ Qh, int ldq,
               const __half* __restrict__ Kh, int ldk,
               const __half* __restrict__ Vh,
               const float* __restrict__ bias,
               __half* __restrict__ Oh,
               int Lq, int Lkv) {
    extern __shared__ char smem[];
    const uint32_t sb = smem_u32(smem);
    const int t = threadIdx.x, lane = t & 31, w = t >> 5;
    const int bh = blockIdx.y, b = bh >> 4, h = bh & 15;
    const int q0 = blockIdx.x * 64;

    // Q tile -> smem
    #pragma unroll
    for (int j = 0; j < 4; j++) {
        const int id = t + 128 * j, r = id >> 3, ch = id & 7;
        const size_t g = ((size_t)(b * Lq + q0 + r)) * ldq + h * 64 + ch * 8;
        cpa16(sb + FQOFF + (uint32_t)r * FRSB + ch * 16, (const char*)Qh + g * 2);
    }
    CP_COMMIT();

    auto load_kv = [&](int it, int s) {
        const uint32_t sd = sb + s * FSTAGE;
        const int k0 = it * 64;
        #pragma unroll
        for (int j = 0; j < 4; j++) {
            const int id = t + 128 * j, r = id >> 3, ch = id & 7;
            const size_t g = ((size_t)(b * Lkv + k0 + r)) * ldk + h * 64 + ch * 8;
            const uint32_t so = sd + (uint32_t)r * FRSB + ch * 16;
            cpa16(so,          (const char*)Kh + g * 2);
            cpa16(so + FPLANE, (const char*)Vh + g * 2);
        }
    };
    load_kv(0, 0); CP_COMMIT();

    uint32_t qf[4][4];
    float o_[8][4];
    #pragma unroll
    for (int i = 0; i < 8; i++)
        #pragma unroll
        for (int j = 0; j < 4; j++) o_[i][j] = 0.f;
    float m0 = -1e30f, m1 = -1e30f, l0 = 0.f, l1 = 0.f;
    const float invs = 0.125f;

    const int nt = Lkv / 64;
    for (int it = 0; it < nt; it++) {
        if (it + 1 < nt) { load_kv(it + 1, (it + 1) & 1); CP_COMMIT(); CP_WAIT1(); }
        else { CP_WAIT0(); }
        __syncthreads();
        const uint32_t sd = sb + (it & 1) * FSTAGE;

        if (it == 0) {
            #pragma unroll
            for (int kf = 0; kf < 4; kf++) {
                const uint32_t qa = sb + FQOFF
                    + (uint32_t)(w * 16 + (lane & 15)) * FRSB
                    + ((lane >> 4) * 8 + kf * 16) * 2;
                ldm_x4(qf[kf], qa);
            }
        }

        // ---- S = Q K^T ----
        float s_[8][4];
        #pragma unroll
        for (int i = 0; i < 8; i++)
            #pragma unroll
            for (int j = 0; j < 4; j++) s_[i][j] = 0.f;
        #pragma unroll
        for (int kf = 0; kf < 4; kf++) {
            #pragma unroll
            for (int g = 0; g < 4; g++) {
                const uint32_t ka = sd
                    + (uint32_t)(g * 16 + (lane & 7) + ((lane >> 4) & 1) * 8) * FRSB
                    + (((lane >> 3) & 1) * 8 + kf * 16) * 2;
                uint32_t rh[4];
                ldm_x4(rh, ka);
                mma_f16(s_[2 * g],     qf[kf], rh);
                mma_f16(s_[2 * g + 1], qf[kf], rh + 2);
            }
        }

        // ---- scale + bias ----
        if (bias) {
            const int k0 = it * 64;
            const float* bp = bias
                + ((size_t)bh * Lq + (q0 + w * 16 + (lane >> 2))) * Lkv
                + k0 + (lane & 3) * 2;
            #pragma unroll
            for (int nf = 0; nf < 8; nf++) {
                const float2 b0 = *(const float2*)(bp + nf * 8);
                const float2 b1 = *(const float2*)(bp + (size_t)8 * Lkv + nf * 8);
                s_[nf][0] = fmaf(s_[nf][0], invs, b0.x);
                s_[nf][1] = fmaf(s_[nf][1], invs, b0.y);
                s_[nf][2] = fmaf(s_[nf][2], invs, b1.x);
                s_[nf][3] = fmaf(s_[nf][3], invs, b1.y);
            }
        } else {
            #pragma unroll
            for (int nf = 0; nf < 8; nf++)
                #pragma unroll
                for (int i = 0; i < 4; i++) s_[nf][i] *= invs;
        }

        // ---- online softmax ----
        float mx0 = s_[0][0], mx1 = s_[0][2];
        #pragma unroll
        for (int nf = 0; nf < 8; nf++) {
            mx0 = fmaxf(mx0, fmaxf(s_[nf][0], s_[nf][1]));
            mx1 = fmaxf(mx1, fmaxf(s_[nf][2], s_[nf][3]));
        }
        mx0 = fmaxf(mx0, __shfl_xor_sync(0xffffffffu, mx0, 1));
        mx0 = fmaxf(mx0, __shfl_xor_sync(0xffffffffu, mx0, 2));
        mx1 = fmaxf(mx1, __shfl_xor_sync(0xffffffffu, mx1, 1));
        mx1 = fmaxf(mx1, __shfl_xor_sync(0xffffffffu, mx1, 2));
        const float mn0 = fmaxf(m0, mx0), mn1 = fmaxf(m1, mx1);
        const float sc0 = fexp(m0 - mn0), sc1 = fexp(m1 - mn1);
        m0 = mn0; m1 = mn1;
        float sum0 = 0.f, sum1 = 0.f;
        #pragma unroll
        for (int nf = 0; nf < 8; nf++) {
            s_[nf][0] = fexp(s_[nf][0] - mn0);
            s_[nf][1] = fexp(s_[nf][1] - mn0);
            s_[nf][2] = fexp(s_[nf][2] - mn1);
            s_[nf][3] = fexp(s_[nf][3] - mn1);
            sum0 += s_[nf][0] + s_[nf][1];
            sum1 += s_[nf][2] + s_[nf][3];
        }
        sum0 += __shfl_xor_sync(0xffffffffu, sum0, 1);
        sum0 += __shfl_xor_sync(0xffffffffu, sum0, 2);
        sum1 += __shfl_xor_sync(0xffffffffu, sum1, 1);
        sum1 += __shfl_xor_sync(0xffffffffu, sum1, 2);
        l0 = l0 * sc0 + sum0;
        l1 = l1 * sc1 + sum1;
        #pragma unroll
        for (int nf = 0; nf < 8; nf++) {
            o_[nf][0] *= sc0; o_[nf][1] *= sc0;
            o_[nf][2] *= sc1; o_[nf][3] *= sc1;
        }

        // ---- O += P V (P from regs, V via ldmatrix.trans) ----
        #pragma unroll
        for (int kf = 0; kf < 4; kf++) {
            uint32_t pa[4];
            pa[0] = packu(s_[2 * kf][0], s_[2 * kf][1]);
            pa[1] = packu(s_[2 * kf][2], s_[2 * kf][3]);
            pa[2] = packu(s_[2 * kf + 1][0], s_[2 * kf + 1][1]);
            pa[3] = packu(s_[2 * kf + 1][2], s_[2 * kf + 1][3]);
            #pragma unroll
            for (int g = 0; g < 4; g++) {
                const uint32_t va = sd + FPLANE
                    + (uint32_t)(kf * 16 + (lane & 15)) * FRSB
                    + ((lane >> 4) * 8 + g * 16) * 2;
                uint32_t rh[4];
                ldm_x4_t(rh, va);
                mma_f16(o_[2 * g],     pa, rh);
                mma_f16(o_[2 * g + 1], pa, rh + 2);
            }
        }
        __syncthreads();
    }

    // ---- normalize + store fp16 ----
    const float inv0 = 1.f / l0, inv1 = 1.f / l1;
    const int row0 = b * Lq + q0 + w * 16 + (lane >> 2);
    #pragma unroll
    for (int nf = 0; nf < 8; nf++) {
        const int col = h * 64 + nf * 8 + (lane & 3) * 2;
        *(__half2*)(Oh + (size_t)row0 * D_ + col) =
            packh(o_[nf][0] * inv0, o_[nf][1] * inv0);
        *(__half2*)(Oh + (size_t)(row0 + 8) * D_ + col) =
            packh(o_[nf][2] * inv1, o_[nf][3] * inv1);
    }
}

// ----------------------------------------------------------------------------
// Host orchestration
// ----------------------------------------------------------------------------
extern "C" void kernel_launch(void* const* d_in, const int* in_sizes, int n_in,
                              void* d_out, int out_size) {
    const float* x          = (const float*)d_in[0];
    const float* alibi      = (const float*)d_in[1];
    const float* species    = (const float*)d_in[2];
    const float* norm1_g    = (const float*)d_in[3];
    const float* norm1_b    = (const float*)d_in[4];
    const float* sa_wqkv    = (const float*)d_in[5];
    const float* sa_bqkv    = (const float*)d_in[6];
    const float* sa_wo      = (const float*)d_in[7];
    const float* sa_bo      = (const float*)d_in[8];
    const float* ca_nq_g    = (const float*)d_in[9];
    const float* ca_nq_b    = (const float*)d_in[10];
    const float* ca_nkv_g   = (const float*)d_in[11];
    const float* ca_nkv_b   = (const float*)d_in[12];
    const float* ca_wqkv    = (const float*)d_in[13];
    const float* ca_bqkv    = (const float*)d_in[14];
    const float* ca_wo      = (const float*)d_in[15];
    const float* ca_bo      = (const float*)d_in[16];
    const float* gate_param = (const float*)d_in[17];
    const float* ffn_g      = (const float*)d_in[18];
    const float* ffn_b      = (const float*)d_in[19];
    const float* ffn_w1     = (const float*)d_in[20];
    const float* ffn_b1     = (const float*)d_in[21];
    const float* ffn_w2     = (const float*)d_in[22];
    const float* ffn_b2     = (const float*)d_in[23];
    float* out = (float*)d_out;

    char* S = nullptr;
    cudaGetSymbolAddress((void**)&S, g_scratch);
    #define HF(off) ((__half*)(S + (off)))
    #define F32(off) ((float*)(S + (off)))
    __half *wqkvs = HF(O_WQKVS), *wsao = HF(O_WSAO);
    __half *wqkvc = HF(O_WQKVC), *wcao = HF(O_WCAO);
    __half *wf1 = HF(O_WF1), *wf2 = HF(O_WF2);
    __half *lnb = HF(O_LN), *atb = HF(O_AT), *kvnb = HF(O_KVN);
    __half *ggb = HF(O_GG), *qkvb = HF(O_QKV);
    __half *cqb = HF(O_CQ), *ckvb = HF(O_CKV);
    float *x1 = F32(O_X1), *x2 = F32(O_X2);

    cudaFuncSetAttribute(mma_gemm<1>, cudaFuncAttributeMaxDynamicSharedMemorySize, GEMM_SMEM);
    cudaFuncSetAttribute(mma_gemm<2>, cudaFuncAttributeMaxDynamicSharedMemorySize, GEMM_SMEM);
    cudaFuncSetAttribute(mma_gemm<3>, cudaFuncAttributeMaxDynamicSharedMemorySize, GEMM_SMEM);
    cudaFuncSetAttribute(mma_gemm<4>, cudaFuncAttributeMaxDynamicSharedMemorySize, GEMM_SMEM);
    cudaFuncSetAttribute(flash_mma, cudaFuncAttributeMaxDynamicSharedMemorySize, FLASH_SMEM);

    // ---- weight convert ----
    auto cvt = [&](const float* w, __half* h, int n) {
        cvt_h_kernel<<<(n / 4 + 255) / 256, 256>>>(
            (const float4*)w, (__half2*)h, n / 4);
    };
    cvt(sa_wqkv, wqkvs, 3 * D_ * D_);
    cvt(sa_wo,   wsao,  D_ * D_);
    cvt(ca_wqkv, wqkvc, 3 * D_ * D_);
    cvt(ca_wo,   wcao,  D_ * D_);
    cvt(ffn_w2,  wf2,   D_ * FF_);
    cvt_h_ileave_kernel<<<(2 * FF_ * D_ / 4 + 255) / 256, 256>>>(
        ffn_w1, (__half2*)wf1, 2 * FF_ * D_ / 4);

    // ---- Self-attention ----
    ln_kernel<<<M_, 256>>>(x, norm1_g, norm1_b, lnb);
    mma_gemm<3><<<dim3(3 * D_ / TN, M_ / TM), 256, GEMM_SMEM>>>(
        lnb, wqkvs, sa_bqkv, nullptr, nullptr, nullptr, qkvb, 3 * D_, D_, 0);
    flash_mma<<<dim3(L_ / 64, B_ * H_), 128, FLASH_SMEM>>>(
        qkvb, 3 * D_,
        qkvb + D_, 3 * D_,
        qkvb + 2 * D_,
        alibi, atb, L_, L_);
    mma_gemm<1><<<dim3(D_ / TN, M_ / TM), 256, GEMM_SMEM>>>(
        atb, wsao, sa_bo, x, nullptr, x1, nullptr, D_, D_, 0);

    // ---- Cross-attention ----
    ln_kernel<<<M_, 256>>>(x1, ca_nq_g, ca_nq_b, lnb);
    ln_kernel<<<B_ * NS_, 256>>>(species, ca_nkv_g, ca_nkv_b, kvnb);
    mma_gemm<3><<<dim3(D_ / TN, M_ / TM), 256, GEMM_SMEM>>>(
        lnb, wqkvc, ca_bqkv, nullptr, nullptr, nullptr, cqb, D_, D_, 0);
    mma_gemm<3><<<dim3(2 * D_ / TN, (B_ * NS_) / TM), 256, GEMM_SMEM>>>(
        kvnb, wqkvc, ca_bqkv + D_, nullptr, nullptr, nullptr, ckvb, 2 * D_, D_, D_);
    flash_mma<<<dim3(L_ / 64, B_ * H_), 128, FLASH_SMEM>>>(
        cqb, D_,
        ckvb, 2 * D_,
        ckvb + D_,
        nullptr, atb, L_, NS_);
    mma_gemm<2><<<dim3(D_ / TN, M_ / TM), 256, GEMM_SMEM>>>(
        atb, wcao, ca_bo, x1, gate_param, x2, nullptr, D_, D_, 0);

    // ---- FFN (GEGLU fused into FFN1 epilogue) ----
    ln_kernel<<<M_, 256>>>(x2, ffn_g, ffn_b, lnb);
    mma_gemm<4><<<dim3(2 * FF_ / TN, M_ / TM), 256, GEMM_SMEM>>>(
        lnb, wf1, ffn_b1, nullptr, nullptr, nullptr, ggb, 2 * FF_, D_, 0);
    mma_gemm<1><<<dim3(D_ / TN, M_ / TM), 256, GEMM_SMEM>>>(
        ggb, wf2, ffn_b2, x2, nullptr, out, nullptr, D_, FF_, 0);
}

// round 11
// speedup vs baseline: 6.3365x; 1.1001x over previous
#include <cuda_runtime.h>
#include <cuda_fp16.h>
#include <math.h>
#include <stdint.h>

// ----------------------------------------------------------------------------
// Shapes (fixed)
// ----------------------------------------------------------------------------
#define B_   4
#define L_   1024
#define D_   1024
#define H_   16
#define HD_  64
#define FF_  4096
#define NS_  64
#define M_   (B_ * L_)          // 4096 rows

// ----------------------------------------------------------------------------
// Scratch (bytes) — single fp16 plane per tensor
// ----------------------------------------------------------------------------
#define SZ_WQKV   (3072ull*1024u*2u)
#define SZ_WO     (1024ull*1024u*2u)
#define SZ_WF1    (8192ull*1024u*2u)
#define SZ_WF2    (1024ull*4096u*2u)
#define SZ_ACT    (4096ull*1024u*2u)
#define SZ_KVN    (256ull*1024u*2u)
#define SZ_GG     (4096ull*4096u*2u)
#define SZ_QKV1   (4096ull*3072u*2u)
#define SZ_CKV1   (256ull*2048u*2u)
#define SZ_D32    (4096ull*1024u*4u)

#define O_WQKVS     0ull
#define O_WSAO      (O_WQKVS + SZ_WQKV)
#define O_WQKVC     (O_WSAO + SZ_WO)
#define O_WCAO      (O_WQKVC + SZ_WQKV)
#define O_WF1       (O_WCAO + SZ_WO)
#define O_WF2       (O_WF1 + SZ_WF1)
#define O_LN        (O_WF2 + SZ_WF2)
#define O_AT        (O_LN + SZ_ACT)
#define O_KVN       (O_AT + SZ_ACT)
#define O_GG        (O_KVN + SZ_KVN)
#define O_QKV       (O_GG + SZ_GG)
#define O_CQ        (O_QKV + SZ_QKV1)
#define O_CKV       (O_CQ + SZ_ACT)
#define O_X1        (O_CKV + SZ_CKV1)
#define O_X2        (O_X1 + SZ_D32)
#define SCRATCH_BYTES (O_X2 + SZ_D32)

__device__ __align__(1024) char g_scratch[SCRATCH_BYTES];

// ----------------------------------------------------------------------------
// PTX helpers (family-agnostic)
// ----------------------------------------------------------------------------
__device__ __forceinline__ uint32_t smem_u32(const void* p) {
    uint32_t a;
    asm("{ .reg .u64 t; cvta.to.shared.u64 t, %1; cvt.u32.u64 %0, t; }"
        : "=r"(a) : "l"(p));
    return a;
}
__device__ __forceinline__ void cpa16(uint32_t s, const void* g) {
    asm volatile("cp.async.cg.shared.global [%0], [%1], 16;" :: "r"(s), "l"(g));
}
#define CP_COMMIT() asm volatile("cp.async.commit_group;" ::: "memory")
#define CP_WAIT0() asm volatile("cp.async.wait_group 0;" ::: "memory")
#define CP_WAIT1() asm volatile("cp.async.wait_group 1;" ::: "memory")
#define CP_WAIT2() asm volatile("cp.async.wait_group 2;" ::: "memory")

__device__ __forceinline__ void ldm_x4(uint32_t* r, uint32_t addr) {
    asm volatile("ldmatrix.sync.aligned.m8n8.x4.shared.b16 {%0,%1,%2,%3}, [%4];"
        : "=r"(r[0]), "=r"(r[1]), "=r"(r[2]), "=r"(r[3]) : "r"(addr));
}
__device__ __forceinline__ void ldm_x4_t(uint32_t* r, uint32_t addr) {
    asm volatile("ldmatrix.sync.aligned.m8n8.x4.trans.shared.b16 {%0,%1,%2,%3}, [%4];"
        : "=r"(r[0]), "=r"(r[1]), "=r"(r[2]), "=r"(r[3]) : "r"(addr));
}
__device__ __forceinline__ void mma_f16(float* d, const uint32_t* a, const uint32_t* b) {
    asm volatile(
        "mma.sync.aligned.m16n8k16.row.col.f32.f16.f16.f32 "
        "{%0,%1,%2,%3}, {%4,%5,%6,%7}, {%8,%9}, {%0,%1,%2,%3};"
        : "+f"(d[0]), "+f"(d[1]), "+f"(d[2]), "+f"(d[3])
        : "r"(a[0]), "r"(a[1]), "r"(a[2]), "r"(a[3]), "r"(b[0]), "r"(b[1]));
}

__device__ __forceinline__ __half2 packh(float a, float b) {
    return __floats2half2_rn(a, b);
}
__device__ __forceinline__ uint32_t packu(float a, float b) {
    __half2 v = packh(a, b);
    return *(uint32_t*)&v;
}

// Fast exp on FFMA pipe (x <= 0 path), rel err ~2e-6
__device__ __forceinline__ float fexp(float x) {
    float z = x * 1.4426950408889634f;
    z = fmaxf(z, -120.0f);
    float zi = z + 12582912.0f;
    int i = __float_as_int(zi) - 0x4B400000;
    float f = z - (zi - 12582912.0f);
    float p = 1.3333558e-3f;
    p = fmaf(p, f, 9.6181291e-3f);
    p = fmaf(p, f, 5.5504109e-2f);
    p = fmaf(p, f, 2.4022651e-1f);
    p = fmaf(p, f, 6.9314718e-1f);
    p = fmaf(p, f, 1.0f);
    return p * __int_as_float((i + 127) << 23);
}

// ----------------------------------------------------------------------------
// Weight convert: fp32 -> fp16
// ----------------------------------------------------------------------------
__global__ __launch_bounds__(256)
void cvt_h_kernel(const float4* __restrict__ w, __half2* __restrict__ hi, int n4) {
    int i = blockIdx.x * 256 + threadIdx.x;
    if (i >= n4) return;
    const float4 v = w[i];
    hi[i * 2]     = packh(v.x, v.y);
    hi[i * 2 + 1] = packh(v.z, v.w);
}

// ffn_w1 interleave: dst row 2j = w1[j] (val), 2j+1 = w1[FF+j] (gate)
__global__ __launch_bounds__(256)
void cvt_h_ileave_kernel(const float* __restrict__ w, __half2* __restrict__ hi, int n4) {
    int i = blockIdx.x * 256 + threadIdx.x;
    if (i >= n4) return;
    const int row = i >> 8;
    const int col4 = (i & 255) * 4;
    const int srow = (row & 1) ? (FF_ + (row >> 1)) : (row >> 1);
    const float4 v = *(const float4*)(w + (size_t)srow * 1024 + col4);
    hi[i * 2]     = packh(v.x, v.y);
    hi[i * 2 + 1] = packh(v.z, v.w);
}

// ----------------------------------------------------------------------------
// LayerNorm -> fp16 plane
// ----------------------------------------------------------------------------
__global__ __launch_bounds__(256)
void ln_kernel(const float* __restrict__ x, const float* __restrict__ g,
               const float* __restrict__ b, __half* __restrict__ yh) {
    const int row = blockIdx.x;
    const int t = threadIdx.x;
    const float4 v = ((const float4*)(x + (size_t)row * D_))[t];

    __shared__ float red[8];
    __shared__ float stat[2];

    float s = v.x + v.y + v.z + v.w;
    #pragma unroll
    for (int o = 16; o; o >>= 1) s += __shfl_xor_sync(0xffffffffu, s, o);
    if ((t & 31) == 0) red[t >> 5] = s;
    __syncthreads();
    if (t == 0) {
        float s2 = 0.f;
        #pragma unroll
        for (int i = 0; i < 8; i++) s2 += red[i];
        stat[0] = s2 * (1.0f / D_);
    }
    __syncthreads();
    const float mu = stat[0];
    const float dx = v.x - mu, dy = v.y - mu, dz = v.z - mu, dw = v.w - mu;

    float q = dx * dx + dy * dy + dz * dz + dw * dw;
    #pragma unroll
    for (int o = 16; o; o >>= 1) q += __shfl_xor_sync(0xffffffffu, q, o);
    if ((t & 31) == 0) red[t >> 5] = q;
    __syncthreads();
    if (t == 0) {
        float s2 = 0.f;
        #pragma unroll
        for (int i = 0; i < 8; i++) s2 += red[i];
        stat[1] = rsqrtf(s2 * (1.0f / D_) + 1e-5f);
    }
    __syncthreads();
    const float rs = stat[1];

    const float4 gv = ((const float4*)g)[t];
    const float4 bv = ((const float4*)b)[t];
    const float o0 = dx * rs * gv.x + bv.x;
    const float o1 = dy * rs * gv.y + bv.y;
    const float o2 = dz * rs * gv.z + bv.z;
    const float o3 = dw * rs * gv.w + bv.w;
    const size_t base = (size_t)row * D_ + t * 4;
    *(__half2*)(yh + base)     = packh(o0, o1);
    *(__half2*)(yh + base + 2) = packh(o2, o3);
}

__device__ __forceinline__ float gelu_exact(float x) {
    return 0.5f * x * (1.0f + erff(x * 0.7071067811865476f));
}

// ----------------------------------------------------------------------------
// mma.sync 1-term fp16 GEMM: C[M,N] = A[M,K] @ W[N,K]^T (+epilogue)
// CTA tile 128x256, warp tile 64x64 (2x4 warps), K-chunk 64, 3-stage cp.async.
// EPI: 1 bias+res (fp32 out); 2 sigmoid(gate)*(..)+res (fp32 out);
//      3 bias only -> fp16 plane; 4 GEGLU (interleaved W) -> fp16 plane
// ----------------------------------------------------------------------------
#define TM 128
#define TN 256
#define KCH 64
#define RS 72
#define RSB (RS * 2)
#define APLANE_B (128 * RSB)        // 18432
#define WPLANE_B (256 * RSB)        // 36864
#define SA_A 0
#define SW_W APLANE_B
#define STAGE_B (APLANE_B + WPLANE_B)  // 55296
#define GEMM_SMEM (3 * STAGE_B)        // 165888

template <int EPI>
__global__ __launch_bounds__(256, 1)
void mma_gemm(const __half* __restrict__ A, const __half* __restrict__ W,
              const float* __restrict__ bias, const float* __restrict__ res,
              const float* __restrict__ gatep, float* __restrict__ C,
              __half* __restrict__ Ch,
              int N, int K, int wRowOff) {
    extern __shared__ char smem[];
    const uint32_t sb = smem_u32(smem);
    const int t = threadIdx.x;
    const int lane = t & 31;
    const int wid = t >> 5;
    const int wm = wid & 1;         // m half (64)
    const int wn = wid >> 1;        // n quarter (64)

    const int mBase = blockIdx.y * TM;
    const int nBase = blockIdx.x * TN;

    // A: 128x64 -> 4 chunks/thread; W: 256x64 -> 8 chunks/thread
    uint32_t sOffA[4], sOffW[8];
    size_t gOffA[4], gOffW[8];
    #pragma unroll
    for (int j = 0; j < 4; j++) {
        const int id = t + 256 * j;
        const int r = id >> 3;
        const int ch = id & 7;
        sOffA[j] = (uint32_t)r * RSB + ch * 16;
        gOffA[j] = ((size_t)(mBase + r) * K + ch * 8) * 2;
    }
    #pragma unroll
    for (int j = 0; j < 8; j++) {
        const int id = t + 256 * j;
        const int r = id >> 3;
        const int ch = id & 7;
        sOffW[j] = (uint32_t)r * RSB + ch * 16;
        gOffW[j] = ((size_t)(nBase + wRowOff + r) * K + ch * 8) * 2;
    }
    const char* pA = (const char*)A;
    const char* pW = (const char*)W;

    auto load_stage = [&](int c, int s) {
        const uint32_t sd = sb + s * STAGE_B;
        const size_t kb = (size_t)c * 128;
        #pragma unroll
        for (int j = 0; j < 4; j++)
            cpa16(sd + SA_A + sOffA[j], pA + gOffA[j] + kb);
        #pragma unroll
        for (int j = 0; j < 8; j++)
            cpa16(sd + SW_W + sOffW[j], pW + gOffW[j] + kb);
    };

    float acc[4][8][4];
    #pragma unroll
    for (int i = 0; i < 4; i++)
        #pragma unroll
        for (int j = 0; j < 8; j++)
            #pragma unroll
            for (int k = 0; k < 4; k++) acc[i][j][k] = 0.f;

    const int nch = K / KCH;
    load_stage(0, 0); CP_COMMIT();
    if (nch > 1) { load_stage(1, 1); CP_COMMIT(); }

    const uint32_t aRowOff = (uint32_t)(wm * 64 + (lane & 15)) * RSB
                           + ((lane >> 4) * 8) * 2;
    const uint32_t bRowOff = (uint32_t)(wn * 64 + (lane & 7) + ((lane >> 4) & 1) * 8) * RSB
                           + (((lane >> 3) & 1) * 8) * 2;

    int sidx = 0;
    for (int c = 0; c < nch; c++) {
        if (c + 2 < nch) {
            load_stage(c + 2, (sidx + 2) % 3);
            CP_COMMIT();
            CP_WAIT2();
        } else if (c + 1 < nch) {
            CP_WAIT1();
        } else {
            CP_WAIT0();
        }
        __syncthreads();

        const uint32_t sd = sb + sidx * STAGE_B;
        #pragma unroll
        for (int kk = 0; kk < KCH; kk += 16) {
            uint32_t ah[4][4];
            #pragma unroll
            for (int mf = 0; mf < 4; mf++) {
                const uint32_t ad = sd + SA_A + aRowOff + (uint32_t)(mf * 16) * RSB + kk * 2;
                ldm_x4(ah[mf], ad);
            }
            uint32_t bw[8][2];
            #pragma unroll
            for (int nf2 = 0; nf2 < 4; nf2++) {
                const uint32_t bd = sd + SW_W + bRowOff + (uint32_t)(nf2 * 16) * RSB + kk * 2;
                uint32_t r[4];
                ldm_x4(r, bd);
                bw[nf2 * 2][0] = r[0]; bw[nf2 * 2][1] = r[1];
                bw[nf2 * 2 + 1][0] = r[2]; bw[nf2 * 2 + 1][1] = r[3];
            }
            #pragma unroll
            for (int mf = 0; mf < 4; mf++)
                #pragma unroll
                for (int nf = 0; nf < 8; nf++)
                    mma_f16(acc[mf][nf], ah[mf], bw[nf]);
        }
        __syncthreads();
        sidx = (sidx + 1) % 3;
    }

    // ---- epilogue ----
    float gs = 1.f;
    if (EPI == 2) gs = 1.f / (1.f + __expf(-gatep[0]));

    const int mWarp = mBase + wm * 64;
    const int nWarp = nBase + wn * 64;
    #pragma unroll
    for (int mf = 0; mf < 4; mf++) {
        const int r0 = mWarp + mf * 16 + (lane >> 2);
        #pragma unroll
        for (int nf = 0; nf < 8; nf++) {
            const int c0 = nWarp + nf * 8 + 2 * (lane & 3);
            if (EPI == 1 || EPI == 2) {
                const float b0 = bias[c0], b1 = bias[c0 + 1];
                float v0 = acc[mf][nf][0] + b0;
                float v1 = acc[mf][nf][1] + b1;
                float v2 = acc[mf][nf][2] + b0;
                float v3 = acc[mf][nf][3] + b1;
                if (EPI == 1) {
                    v0 += res[(size_t)r0 * N + c0];
                    v1 += res[(size_t)r0 * N + c0 + 1];
                    v2 += res[(size_t)(r0 + 8) * N + c0];
                    v3 += res[(size_t)(r0 + 8) * N + c0 + 1];
                } else {
                    v0 = gs * v0 + res[(size_t)r0 * N + c0];
                    v1 = gs * v1 + res[(size_t)r0 * N + c0 + 1];
                    v2 = gs * v2 + res[(size_t)(r0 + 8) * N + c0];
                    v3 = gs * v3 + res[(size_t)(r0 + 8) * N + c0 + 1];
                }
                *(float2*)(C + (size_t)r0 * N + c0) = make_float2(v0, v1);
                *(float2*)(C + (size_t)(r0 + 8) * N + c0) = make_float2(v2, v3);
            } else if (EPI == 3) {
                const float b0 = bias[c0], b1 = bias[c0 + 1];
                *(__half2*)(Ch + (size_t)r0 * N + c0) =
                    packh(acc[mf][nf][0] + b0, acc[mf][nf][1] + b1);
                *(__half2*)(Ch + (size_t)(r0 + 8) * N + c0) =
                    packh(acc[mf][nf][2] + b0, acc[mf][nf][3] + b1);
            } else {  // EPI == 4: GEGLU with interleaved W (even=val, odd=gate)
                const int jj = c0 >> 1;
                const int Nout = N >> 1;
                const float bv = bias[jj], bg = bias[FF_ + jj];
                const float va = acc[mf][nf][0] + bv;
                const float ga = acc[mf][nf][1] + bg;
                const float vb = acc[mf][nf][2] + bv;
                const float gb = acc[mf][nf][3] + bg;
                Ch[(size_t)r0 * Nout + jj] = __float2half_rn(va * gelu_exact(ga));
                Ch[(size_t)(r0 + 8) * Nout + jj] = __float2half_rn(vb * gelu_exact(gb));
            }
        }
    }
}

// ----------------------------------------------------------------------------
// Tensor-core flash attention (1-term fp16), HD=64, 64q x 64kv tiles.
// 128 threads (4 warps); warp w owns q rows [16w,16w+16).
// Output fp16 plane with row stride D_.
// ----------------------------------------------------------------------------
#define FRSB 144
#define FPLANE (64 * FRSB)            // 9216
#define FSTAGE (2 * FPLANE)           // 18432 (K, V)
#define FQOFF  (2 * FSTAGE)           // 36864 (Q)
#define FLASH_SMEM (FQOFF + FPLANE)   // 46080

__global__ __launch_bounds__(128)
void flash_mma(const __half* __restrict__ Qh, int ldq,
               const __half* __restrict__ Kh, int ldk,
               const __half* __restrict__ Vh,
               const float* __restrict__ bias,
               __half* __restrict__ Oh,
               int Lq, int Lkv) {
    extern __shared__ char smem[];
    const uint32_t sb = smem_u32(smem);
    const int t = threadIdx.x, lane = t & 31, w = t >> 5;
    const int bh = blockIdx.y, b = bh >> 4, h = bh & 15;
    const int q0 = blockIdx.x * 64;

    // Q tile -> smem
    #pragma unroll
    for (int j = 0; j < 4; j++) {
        const int id = t + 128 * j, r = id >> 3, ch = id & 7;
        const size_t g = ((size_t)(b * Lq + q0 + r)) * ldq + h * 64 + ch * 8;
        cpa16(sb + FQOFF + (uint32_t)r * FRSB + ch * 16, (const char*)Qh + g * 2);
    }
    CP_COMMIT();

    auto load_kv = [&](int it, int s) {
        const uint32_t sd = sb + s * FSTAGE;
        const int k0 = it * 64;
        #pragma unroll
        for (int j = 0; j < 4; j++) {
            const int id = t + 128 * j, r = id >> 3, ch = id & 7;
            const size_t g = ((size_t)(b * Lkv + k0 + r)) * ldk + h * 64 + ch * 8;
            const uint32_t so = sd + (uint32_t)r * FRSB + ch * 16;
            cpa16(so,          (const char*)Kh + g * 2);
            cpa16(so + FPLANE, (const char*)Vh + g * 2);
        }
    };
    load_kv(0, 0); CP_COMMIT();

    uint32_t qf[4][4];
    float o_[8][4];
    #pragma unroll
    for (int i = 0; i < 8; i++)
        #pragma unroll
        for (int j = 0; j < 4; j++) o_[i][j] = 0.f;
    float m0 = -1e30f, m1 = -1e30f, l0 = 0.f, l1 = 0.f;
    const float invs = 0.125f;

    const int nt = Lkv / 64;
    for (int it = 0; it < nt; it++) {
        if (it + 1 < nt) { load_kv(it + 1, (it + 1) & 1); CP_COMMIT(); CP_WAIT1(); }
        else { CP_WAIT0(); }
        __syncthreads();
        const uint32_t sd = sb + (it & 1) * FSTAGE;

        if (it == 0) {
            #pragma unroll
            for (int kf = 0; kf < 4; kf++) {
                const uint32_t qa = sb + FQOFF
                    + (uint32_t)(w * 16 + (lane & 15)) * FRSB
                    + ((lane >> 4) * 8 + kf * 16) * 2;
                ldm_x4(qf[kf], qa);
            }
        }

        // ---- S = Q K^T ----
        float s_[8][4];
        #pragma unroll
        for (int i = 0; i < 8; i++)
            #pragma unroll
            for (int j = 0; j < 4; j++) s_[i][j] = 0.f;
        #pragma unroll
        for (int kf = 0; kf < 4; kf++) {
            #pragma unroll
            for (int g = 0; g < 4; g++) {
                const uint32_t ka = sd
                    + (uint32_t)(g * 16 + (lane & 7) + ((lane >> 4) & 1) * 8) * FRSB
                    + (((lane >> 3) & 1) * 8 + kf * 16) * 2;
                uint32_t rh[4];
                ldm_x4(rh, ka);
                mma_f16(s_[2 * g],     qf[kf], rh);
                mma_f16(s_[2 * g + 1], qf[kf], rh + 2);
            }
        }

        // ---- scale + bias ----
        if (bias) {
            const int k0 = it * 64;
            const float* bp = bias
                + ((size_t)bh * Lq + (q0 + w * 16 + (lane >> 2))) * Lkv
                + k0 + (lane & 3) * 2;
            #pragma unroll
            for (int nf = 0; nf < 8; nf++) {
                const float2 b0 = *(const float2*)(bp + nf * 8);
                const float2 b1 = *(const float2*)(bp + (size_t)8 * Lkv + nf * 8);
                s_[nf][0] = fmaf(s_[nf][0], invs, b0.x);
                s_[nf][1] = fmaf(s_[nf][1], invs, b0.y);
                s_[nf][2] = fmaf(s_[nf][2], invs, b1.x);
                s_[nf][3] = fmaf(s_[nf][3], invs, b1.y);
            }
        } else {
            #pragma unroll
            for (int nf = 0; nf < 8; nf++)
                #pragma unroll
                for (int i = 0; i < 4; i++) s_[nf][i] *= invs;
        }

        // ---- online softmax ----
        float mx0 = s_[0][0], mx1 = s_[0][2];
        #pragma unroll
        for (int nf = 0; nf < 8; nf++) {
            mx0 = fmaxf(mx0, fmaxf(s_[nf][0], s_[nf][1]));
            mx1 = fmaxf(mx1, fmaxf(s_[nf][2], s_[nf][3]));
        }
        mx0 = fmaxf(mx0, __shfl_xor_sync(0xffffffffu, mx0, 1));
        mx0 = fmaxf(mx0, __shfl_xor_sync(0xffffffffu, mx0, 2));
        mx1 = fmaxf(mx1, __shfl_xor_sync(0xffffffffu, mx1, 1));
        mx1 = fmaxf(mx1, __shfl_xor_sync(0xffffffffu, mx1, 2));
        const float mn0 = fmaxf(m0, mx0), mn1 = fmaxf(m1, mx1);
        const float sc0 = fexp(m0 - mn0), sc1 = fexp(m1 - mn1);
        m0 = mn0; m1 = mn1;
        float sum0 = 0.f, sum1 = 0.f;
        #pragma unroll
        for (int nf = 0; nf < 8; nf++) {
            s_[nf][0] = fexp(s_[nf][0] - mn0);
            s_[nf][1] = fexp(s_[nf][1] - mn0);
            s_[nf][2] = fexp(s_[nf][2] - mn1);
            s_[nf][3] = fexp(s_[nf][3] - mn1);
            sum0 += s_[nf][0] + s_[nf][1];
            sum1 += s_[nf][2] + s_[nf][3];
        }
        sum0 += __shfl_xor_sync(0xffffffffu, sum0, 1);
        sum0 += __shfl_xor_sync(0xffffffffu, sum0, 2);
        sum1 += __shfl_xor_sync(0xffffffffu, sum1, 1);
        sum1 += __shfl_xor_sync(0xffffffffu, sum1, 2);
        l0 = l0 * sc0 + sum0;
        l1 = l1 * sc1 + sum1;
        #pragma unroll
        for (int nf = 0; nf < 8; nf++) {
            o_[nf][0] *= sc0; o_[nf][1] *= sc0;
            o_[nf][2] *= sc1; o_[nf][3] *= sc1;
        }

        // ---- O += P V (P from regs, V via ldmatrix.trans) ----
        #pragma unroll
        for (int kf = 0; kf < 4; kf++) {
            uint32_t pa[4];
            pa[0] = packu(s_[2 * kf][0], s_[2 * kf][1]);
            pa[1] = packu(s_[2 * kf][2], s_[2 * kf][3]);
            pa[2] = packu(s_[2 * kf + 1][0], s_[2 * kf + 1][1]);
            pa[3] = packu(s_[2 * kf + 1][2], s_[2 * kf + 1][3]);
            #pragma unroll
            for (int g = 0; g < 4; g++) {
                const uint32_t va = sd + FPLANE
                    + (uint32_t)(kf * 16 + (lane & 15)) * FRSB
                    + ((lane >> 4) * 8 + g * 16) * 2;
                uint32_t rh[4];
                ldm_x4_t(rh, va);
                mma_f16(o_[2 * g],     pa, rh);
                mma_f16(o_[2 * g + 1], pa, rh + 2);
            }
        }
        __syncthreads();
    }

    // ---- normalize + store fp16 ----
    const float inv0 = 1.f / l0, inv1 = 1.f / l1;
    const int row0 = b * Lq + q0 + w * 16 + (lane >> 2);
    #pragma unroll
    for (int nf = 0; nf < 8; nf++) {
        const int col = h * 64 + nf * 8 + (lane & 3) * 2;
        *(__half2*)(Oh + (size_t)row0 * D_ + col) =
            packh(o_[nf][0] * inv0, o_[nf][1] * inv0);
        *(__half2*)(Oh + (size_t)(row0 + 8) * D_ + col) =
            packh(o_[nf][2] * inv1, o_[nf][3] * inv1);
    }
}

// ----------------------------------------------------------------------------
// Host orchestration
// ----------------------------------------------------------------------------
extern "C" void kernel_launch(void* const* d_in, const int* in_sizes, int n_in,
                              void* d_out, int out_size) {
    const float* x          = (const float*)d_in[0];
    const float* alibi      = (const float*)d_in[1];
    const float* species    = (const float*)d_in[2];
    const float* norm1_g    = (const float*)d_in[3];
    const float* norm1_b    = (const float*)d_in[4];
    const float* sa_wqkv    = (const float*)d_in[5];
    const float* sa_bqkv    = (const float*)d_in[6];
    const float* sa_wo      = (const float*)d_in[7];
    const float* sa_bo      = (const float*)d_in[8];
    const float* ca_nq_g    = (const float*)d_in[9];
    const float* ca_nq_b    = (const float*)d_in[10];
    const float* ca_nkv_g   = (const float*)d_in[11];
    const float* ca_nkv_b   = (const float*)d_in[12];
    const float* ca_wqkv    = (const float*)d_in[13];
    const float* ca_bqkv    = (const float*)d_in[14];
    const float* ca_wo      = (const float*)d_in[15];
    const float* ca_bo      = (const float*)d_in[16];
    const float* gate_param = (const float*)d_in[17];
    const float* ffn_g      = (const float*)d_in[18];
    const float* ffn_b      = (const float*)d_in[19];
    const float* ffn_w1     = (const float*)d_in[20];
    const float* ffn_b1     = (const float*)d_in[21];
    const float* ffn_w2     = (const float*)d_in[22];
    const float* ffn_b2     = (const float*)d_in[23];
    float* out = (float*)d_out;

    char* S = nullptr;
    cudaGetSymbolAddress((void**)&S, g_scratch);
    #define HF(off) ((__half*)(S + (off)))
    #define F32(off) ((float*)(S + (off)))
    __half *wqkvs = HF(O_WQKVS), *wsao = HF(O_WSAO);
    __half *wqkvc = HF(O_WQKVC), *wcao = HF(O_WCAO);
    __half *wf1 = HF(O_WF1), *wf2 = HF(O_WF2);
    __half *lnb = HF(O_LN), *atb = HF(O_AT), *kvnb = HF(O_KVN);
    __half *ggb = HF(O_GG), *qkvb = HF(O_QKV);
    __half *cqb = HF(O_CQ), *ckvb = HF(O_CKV);
    float *x1 = F32(O_X1), *x2 = F32(O_X2);

    cudaFuncSetAttribute(mma_gemm<1>, cudaFuncAttributeMaxDynamicSharedMemorySize, GEMM_SMEM);
    cudaFuncSetAttribute(mma_gemm<2>, cudaFuncAttributeMaxDynamicSharedMemorySize, GEMM_SMEM);
    cudaFuncSetAttribute(mma_gemm<3>, cudaFuncAttributeMaxDynamicSharedMemorySize, GEMM_SMEM);
    cudaFuncSetAttribute(mma_gemm<4>, cudaFuncAttributeMaxDynamicSharedMemorySize, GEMM_SMEM);
    cudaFuncSetAttribute(flash_mma, cudaFuncAttributeMaxDynamicSharedMemorySize, FLASH_SMEM);

    // ---- weight convert ----
    auto cvt = [&](const float* w, __half* h, int n) {
        cvt_h_kernel<<<(n / 4 + 255) / 256, 256>>>(
            (const float4*)w, (__half2*)h, n / 4);
    };
    cvt(sa_wqkv, wqkvs, 3 * D_ * D_);
    cvt(sa_wo,   wsao,  D_ * D_);
    cvt(ca_wqkv, wqkvc, 3 * D_ * D_);
    cvt(ca_wo,   wcao,  D_ * D_);
    cvt(ffn_w2,  wf2,   D_ * FF_);
    cvt_h_ileave_kernel<<<(2 * FF_ * D_ / 4 + 255) / 256, 256>>>(
        ffn_w1, (__half2*)wf1, 2 * FF_ * D_ / 4);

    // ---- Self-attention ----
    ln_kernel<<<M_, 256>>>(x, norm1_g, norm1_b, lnb);
    mma_gemm<3><<<dim3(3 * D_ / TN, M_ / TM), 256, GEMM_SMEM>>>(
        lnb, wqkvs, sa_bqkv, nullptr, nullptr, nullptr, qkvb, 3 * D_, D_, 0);
    flash_mma<<<dim3(L_ / 64, B_ * H_), 128, FLASH_SMEM>>>(
        qkvb, 3 * D_,
        qkvb + D_, 3 * D_,
        qkvb + 2 * D_,
        alibi, atb, L_, L_);
    mma_gemm<1><<<dim3(D_ / TN, M_ / TM), 256, GEMM_SMEM>>>(
        atb, wsao, sa_bo, x, nullptr, x1, nullptr, D_, D_, 0);

    // ---- Cross-attention ----
    ln_kernel<<<M_, 256>>>(x1, ca_nq_g, ca_nq_b, lnb);
    ln_kernel<<<B_ * NS_, 256>>>(species, ca_nkv_g, ca_nkv_b, kvnb);
    mma_gemm<3><<<dim3(D_ / TN, M_ / TM), 256, GEMM_SMEM>>>(
        lnb, wqkvc, ca_bqkv, nullptr, nullptr, nullptr, cqb, D_, D_, 0);
    mma_gemm<3><<<dim3(2 * D_ / TN, (B_ * NS_) / TM), 256, GEMM_SMEM>>>(
        kvnb, wqkvc, ca_bqkv + D_, nullptr, nullptr, nullptr, ckvb, 2 * D_, D_, D_);
    flash_mma<<<dim3(L_ / 64, B_ * H_), 128, FLASH_SMEM>>>(
        cqb, D_,
        ckvb, 2 * D_,
        ckvb + D_,
        nullptr, atb, L_, NS_);
    mma_gemm<2><<<dim3(D_ / TN, M_ / TM), 256, GEMM_SMEM>>>(
        atb, wcao, ca_bo, x1, gate_param, x2, nullptr, D_, D_, 0);

    // ---- FFN (GEGLU fused into FFN1 epilogue) ----
    ln_kernel<<<M_, 256>>>(x2, ffn_g, ffn_b, lnb);
    mma_gemm<4><<<dim3(2 * FF_ / TN, M_ / TM), 256, GEMM_SMEM>>>(
        lnb, wf1, ffn_b1, nullptr, nullptr, nullptr, ggb, 2 * FF_, D_, 0);
    mma_gemm<1><<<dim3(D_ / TN, M_ / TM), 256, GEMM_SMEM>>>(
        ggb, wf2, ffn_b2, x2, nullptr, out, nullptr, D_, FF_, 0);
}